// round 4
// baseline (speedup 1.0000x reference)
#include <cuda_runtime.h>
#include <mma.h>
#include <math.h>

using namespace nvcuda;

#define NN 50000
#define NE 150000
#define NG 2000
#define DD 75
#define TW 5
#define FO 15
#define NL 4
#define AVGLOG 1.1308269950720914f

// ---------------- scratch (device globals; no allocs) ----------------
__device__ float g_H[NN * DD];
__device__ float g_CAB[NN * 825];       // [A(dst 375) | B(src 375) | H@W0 (75)]
__device__ float g_AGG[NN * 1500];      // [T,4,D]
__device__ float g_G[NN * 225];
__device__ float g_Z[NN * DD];
__device__ float g_Y[NN * DD];
__device__ float g_amp[NN];
__device__ float g_invamp[NN];
__device__ int   g_deg[NN];
__device__ int   g_rowptr[NN + 1];
__device__ int   g_cursor[NN];
__device__ int   g_csr[NE];
__device__ int   g_bsum[256];
__device__ int   g_boffs[256];
__device__ float g_Wcat[NL * 75 * 825];
__device__ float g_Etab[NL * 4 * 375];
__device__ float g_WG[NL * TW * 300 * 45];
__device__ float g_Wxcat[NL * 75 * 75];
__device__ double g_bnS[DD];
__device__ double g_bnQ[DD];
__device__ float g_pool[NG * DD];
__device__ float g_z1[NG * 50];
__device__ float g_z2[NG * 25];

// ---------------- 3xTF32 tensor-core GEMM (128x64 tile, batched over z) ----------------
// dynamic smem layout (floats): sA[128*20] | sB[16*72] | sC[128*72]
#define SMEM_FLOATS (128 * 20 + 16 * 72 + 128 * 72)
#define SMEM_BYTES (SMEM_FLOATS * 4)

__global__ void tgemm_kernel(const float* __restrict__ A, int lda, long sAb,
                             const float* __restrict__ B, int ldb, long sBb,
                             float* __restrict__ C, int ldc, long sCb,
                             int M, int N, int K,
                             const float* __restrict__ bias,
                             const float* __restrict__ addC, int ldadd,
                             int act) {
    extern __shared__ float smem[];
    float* sA = smem;                       // 128*20
    float* sB = smem + 128 * 20;            // 16*72
    float* sC = smem + 128 * 20 + 16 * 72;  // 128*72
    const float* Ab = A + (long)blockIdx.z * sAb;
    const float* Bb = B + (long)blockIdx.z * sBb;
    float* Cb = C + (long)blockIdx.z * sCb;
    int m0 = blockIdx.y * 128, n0 = blockIdx.x * 64;
    int tid = threadIdx.x;
    int warp = tid >> 5;
    int wm = (warp & 3) * 32;
    int wn = (warp >> 2) * 32;

    wmma::fragment<wmma::accumulator, 16, 16, 8, float> acc[2][2];
#pragma unroll
    for (int i = 0; i < 2; i++)
#pragma unroll
        for (int j = 0; j < 2; j++) wmma::fill_fragment(acc[i][j], 0.f);

    for (int k0 = 0; k0 < K; k0 += 16) {
        for (int i = tid; i < 128 * 16; i += 256) {
            int r = i >> 4, c = i & 15;
            int gm = m0 + r, gk = k0 + c;
            sA[r * 20 + c] = (gm < M && gk < K) ? Ab[(long)gm * lda + gk] : 0.f;
        }
        for (int i = tid; i < 16 * 64; i += 256) {
            int r = i >> 6, c = i & 63;
            int gk = k0 + r, gn = n0 + c;
            sB[r * 72 + c] = (gk < K && gn < N) ? Bb[(long)gk * ldb + gn] : 0.f;
        }
        __syncthreads();
#pragma unroll
        for (int kk = 0; kk < 16; kk += 8) {
            wmma::fragment<wmma::matrix_a, 16, 16, 8, wmma::precision::tf32, wmma::row_major> ah[2], al[2];
            wmma::fragment<wmma::matrix_b, 16, 16, 8, wmma::precision::tf32, wmma::row_major> bh[2], bl[2];
#pragma unroll
            for (int i = 0; i < 2; i++) {
                wmma::load_matrix_sync(ah[i], &sA[(wm + 16 * i) * 20 + kk], 20);
#pragma unroll
                for (int e = 0; e < ah[i].num_elements; e++) {
                    float v = ah[i].x[e];
                    float hi = wmma::__float_to_tf32(v);
                    ah[i].x[e] = hi;
                    al[i].x[e] = wmma::__float_to_tf32(v - hi);
                }
            }
#pragma unroll
            for (int j = 0; j < 2; j++) {
                wmma::load_matrix_sync(bh[j], &sB[kk * 72 + wn + 16 * j], 72);
#pragma unroll
                for (int e = 0; e < bh[j].num_elements; e++) {
                    float v = bh[j].x[e];
                    float hi = wmma::__float_to_tf32(v);
                    bh[j].x[e] = hi;
                    bl[j].x[e] = wmma::__float_to_tf32(v - hi);
                }
            }
#pragma unroll
            for (int i = 0; i < 2; i++)
#pragma unroll
                for (int j = 0; j < 2; j++) {
                    wmma::mma_sync(acc[i][j], al[i], bh[j], acc[i][j]);
                    wmma::mma_sync(acc[i][j], ah[i], bl[j], acc[i][j]);
                    wmma::mma_sync(acc[i][j], ah[i], bh[j], acc[i][j]);
                }
        }
        __syncthreads();
    }
#pragma unroll
    for (int i = 0; i < 2; i++)
#pragma unroll
        for (int j = 0; j < 2; j++)
            wmma::store_matrix_sync(&sC[(wm + 16 * i) * 72 + wn + 16 * j], acc[i][j], 72,
                                    wmma::mem_row_major);
    __syncthreads();
    for (int i = tid; i < 128 * 64; i += 256) {
        int r = i >> 6, c = i & 63;
        int gm = m0 + r, gn = n0 + c;
        if (gm < M && gn < N) {
            float v = sC[r * 72 + c];
            if (bias) v += bias[gn];
            if (addC) v += addC[(long)gm * ldadd + gn];
            if (act) v = fmaxf(v, 0.f);
            Cb[(long)gm * ldc + gn] = v;
        }
    }
}

// ---------------- small utility kernels ----------------
__global__ void zero_i(int* p, int n) {
    int i = blockIdx.x * blockDim.x + threadIdx.x;
    if (i < n) p[i] = 0;
}
__global__ void zero_f(float* p, int n) {
    int i = blockIdx.x * blockDim.x + threadIdx.x;
    if (i < n) p[i] = 0.f;
}
__global__ void zero_d75(double* a, double* b) {
    int i = threadIdx.x;
    if (i < DD) { a[i] = 0.0; b[i] = 0.0; }
}

__global__ void hist_k(const int* __restrict__ ei, int* __restrict__ deg) {
    int e = blockIdx.x * blockDim.x + threadIdx.x;
    if (e < NE) atomicAdd(&deg[ei[NE + e]], 1);
}

__global__ void scan_chunks(const int* __restrict__ in, int* __restrict__ out,
                            int* __restrict__ bsum, int n) {
    __shared__ int s[512];
    int b = blockIdx.x, t = threadIdx.x;
    int idx = b * 512 + t;
    int v = (idx < n) ? in[idx] : 0;
    s[t] = v;
    __syncthreads();
    for (int off = 1; off < 512; off <<= 1) {
        int x = (t >= off) ? s[t - off] : 0;
        __syncthreads();
        s[t] += x;
        __syncthreads();
    }
    if (idx < n) out[idx] = s[t] - v;
    if (t == 511) bsum[b] = s[511];
}
__global__ void scan_sums(const int* __restrict__ sums, int* __restrict__ offs, int nb) {
    __shared__ int s[128];
    int t = threadIdx.x;
    int v = (t < nb) ? sums[t] : 0;
    s[t] = v;
    __syncthreads();
    for (int off = 1; off < 128; off <<= 1) {
        int x = (t >= off) ? s[t - off] : 0;
        __syncthreads();
        s[t] += x;
        __syncthreads();
    }
    if (t < nb) offs[t] = s[t] - v;
}
__global__ void scan_add(int* __restrict__ rowptr, const int* __restrict__ offs) {
    int i = blockIdx.x * blockDim.x + threadIdx.x;
    if (i < NN) rowptr[i] += offs[i >> 9];
    if (i == 0) rowptr[NN] = NE;
}

__global__ void fill_csr(const int* __restrict__ ei, const int* __restrict__ ea,
                         const int* __restrict__ rowptr, int* __restrict__ cursor,
                         int* __restrict__ csr) {
    int e = blockIdx.x * blockDim.x + threadIdx.x;
    if (e >= NE) return;
    int d = ei[NE + e];
    int pos = rowptr[d] + atomicAdd(&cursor[d], 1);
    csr[pos] = ei[e] | (ea[e] << 20);
}

__global__ void amp_k(const int* __restrict__ rowptr, float* __restrict__ amp,
                      float* __restrict__ invamp) {
    int i = blockIdx.x * blockDim.x + threadIdx.x;
    if (i >= NN) return;
    int dg = rowptr[i + 1] - rowptr[i];
    float a = logf((float)max(dg, 1) + 1.f) / AVGLOG;
    amp[i] = a;
    invamp[i] = 1.f / a;
}

__global__ void embed_k(const int* __restrict__ x, const float* __restrict__ emb,
                        float* __restrict__ H) {
    int i = blockIdx.x * blockDim.x + threadIdx.x;
    if (i >= NN * DD) return;
    H[i] = emb[x[i / DD] * DD + i % DD];
}

// ---------------- weight prep ----------------
__global__ void prep_wcat(const float* __restrict__ Wpre, float* __restrict__ Wcat) {
    int i = blockIdx.x * blockDim.x + threadIdx.x;
    if (i >= NL * 75 * 750) return;
    int l = i / (75 * 750), r = i % (75 * 750);
    int k = r / 750, j = r % 750;
    int part = j / 375, j2 = j % 375;
    int t = j2 / 75, f = j2 % 75;
    int c = part * 75 + k;
    Wcat[(l * 75 + k) * 825 + j] = Wpre[((l * TW + t) * 225 + c) * 75 + f];
}

__global__ void prep_etab(const float* __restrict__ edge_emb, const float* __restrict__ We,
                          const float* __restrict__ be, const float* __restrict__ Wpre,
                          const float* __restrict__ bpre, float* __restrict__ Etab) {
    int a = blockIdx.x, l = blockIdx.y;
    __shared__ float ev[75];
    int t0 = threadIdx.x;
    if (t0 < 75) {
        float s = be[l * 75 + t0];
        for (int c = 0; c < 50; c++) s += edge_emb[a * 50 + c] * We[(l * 50 + c) * 75 + t0];
        ev[t0] = s;
    }
    __syncthreads();
    for (int j = t0; j < 375; j += blockDim.x) {
        int t = j / 75, f = j % 75;
        float s = bpre[(l * TW + t) * 75 + f];
        for (int d = 0; d < 75; d++)
            s += ev[d] * Wpre[((l * TW + t) * 225 + 150 + d) * 75 + f];
        Etab[(l * 4 + a) * 375 + j] = s;
    }
}

__global__ void prep_wg(const float* __restrict__ Wpost, float* __restrict__ WG) {
    int i = blockIdx.x * blockDim.x + threadIdx.x;
    if (i >= NL * TW * 300 * 45) return;
    int lt = i / (300 * 45), r = i % (300 * 45);
    int c = r / 45, col = r % 45;
    int g = col / 15, f = col % 15;
    WG[i] = Wpost[(lt * 975 + 75 + g * 300 + c) * 15 + f];
}

__global__ void prep_wxcat(const float* __restrict__ Wpost, float* __restrict__ Wx) {
    int i = blockIdx.x * blockDim.x + threadIdx.x;
    if (i >= NL * 75 * 75) return;
    int l = i / (75 * 75), r = i % (75 * 75);
    int c = r / 75, j = r % 75;
    int t = j / 15, f = j % 15;
    Wx[i] = Wpost[((l * TW + t) * 975 + c) * 15 + f];
}

// W0 = Wxcat @ Wlin, stored into columns [750, 825) of Wcat
__global__ void prep_w0(const float* __restrict__ Wx, const float* __restrict__ Wlin,
                        float* __restrict__ Wcat) {
    int i = blockIdx.x * blockDim.x + threadIdx.x;
    if (i >= NL * 75 * 75) return;
    int l = i / (75 * 75), r = i % (75 * 75);
    int k = r / 75, c = r % 75;
    float s = 0.f;
    for (int d = 0; d < 75; d++)
        s += Wx[l * 5625 + k * 75 + d] * Wlin[l * 5625 + d * 75 + c];
    Wcat[(l * 75 + k) * 825 + 750 + c] = s;
}

// ---------------- PNA aggregation (mean/min/max/std over CSR) ----------------
__global__ void pna_agg(const float* __restrict__ CAB, const float* __restrict__ Etab,
                        const int* __restrict__ rowptr, const int* __restrict__ csr,
                        float* __restrict__ AGG) {
    int n = blockIdx.x;
    int j = threadIdx.x;
    if (j >= 375) return;
    float adst = CAB[(long)n * 825 + j];
    int beg = rowptr[n], end = rowptr[n + 1];
    float s = 0.f, sq = 0.f, mn = 3.4e38f, mx = -3.4e38f;
    for (int e = beg; e < end; e++) {
        int p = csr[e];
        int src = p & 0xFFFFF;
        int attr = p >> 20;
        float v = adst + CAB[(long)src * 825 + 375 + j] + Etab[attr * 375 + j];
        s += v;
        sq += v * v;
        mn = fminf(mn, v);
        mx = fmaxf(mx, v);
    }
    int dg = end - beg;
    float denom = fmaxf((float)dg, 1.f);
    float mean = s / denom, msq = sq / denom;
    float sd = sqrtf(fmaxf(msq - mean * mean, 0.f) + 1e-5f);
    if (dg == 0) { mn = 0.f; mx = 0.f; }
    int t = j / 75, f = j % 75;
    float* o = AGG + (long)n * 1500 + t * 300;
    o[f] = mean;
    o[75 + f] = mn;
    o[150 + f] = mx;
    o[225 + f] = sd;
}

// ---------------- combine towers + scalers (includes bpost; no HWX) ----------------
__global__ void combine_k(const float* __restrict__ G, const float* __restrict__ amp,
                          const float* __restrict__ invamp, const float* __restrict__ bpost,
                          float* __restrict__ Z) {
    int i = blockIdx.x * blockDim.x + threadIdx.x;
    if (i >= NN * DD) return;
    int n = i / DD, j = i % DD;
    int t = j / 15, f = j % 15;
    const float* g = G + (long)n * 225 + t * 45;
    Z[i] = g[f] + amp[n] * g[15 + f] + invamp[n] * g[30 + f] + bpost[t * 15 + f];
}

// ---------------- batchnorm ----------------
__global__ void bn_stats(const float* __restrict__ Y, double* __restrict__ S,
                         double* __restrict__ Q) {
    __shared__ float ss[4][75], sq[4][75];
    int f = threadIdx.x, w = threadIdx.y;
    int base = blockIdx.x * 64;
    float s = 0.f, q = 0.f;
    for (int r = w; r < 64; r += 4) {
        int n = base + r;
        if (n < NN) {
            float v = Y[(long)n * DD + f];
            s += v;
            q += v * v;
        }
    }
    ss[w][f] = s;
    sq[w][f] = q;
    __syncthreads();
    if (w == 0) {
        float st = ss[0][f] + ss[1][f] + ss[2][f] + ss[3][f];
        float qt = sq[0][f] + sq[1][f] + sq[2][f] + sq[3][f];
        atomicAdd(&S[f], (double)st);
        atomicAdd(&Q[f], (double)qt);
    }
}

__global__ void bn_apply(const float* __restrict__ Y, const double* __restrict__ S,
                         const double* __restrict__ Q, const float* __restrict__ gamma,
                         const float* __restrict__ beta, float* __restrict__ H) {
    int i = blockIdx.x * blockDim.x + threadIdx.x;
    if (i >= NN * DD) return;
    int f = i % DD;
    double mu = S[f] / (double)NN;
    double var = Q[f] / (double)NN - mu * mu;
    float inv = rsqrtf((float)var + 1e-5f);
    float v = gamma[f] * ((Y[i] - (float)mu) * inv) + beta[f];
    H[i] = fmaxf(v, 0.f);
}

// ---------------- pooling ----------------
__global__ void pool_k(const int* __restrict__ batch, const float* __restrict__ H,
                       float* __restrict__ pool) {
    int i = blockIdx.x * blockDim.x + threadIdx.x;
    if (i >= NN * DD) return;
    int n = i / DD, f = i % DD;
    atomicAdd(&pool[batch[n] * DD + f], H[i]);
}

// ---------------- launch ----------------
static inline void tgemm(const float* A, int lda, long sA, const float* B, int ldb, long sB,
                         float* C, int ldc, long sC, int M, int N, int K, const float* bias,
                         const float* addC, int ldadd, int act, int nz) {
    dim3 grid((N + 63) / 64, (M + 127) / 128, nz);
    tgemm_kernel<<<grid, 256, SMEM_BYTES>>>(A, lda, sA, B, ldb, sB, C, ldc, sC, M, N, K, bias,
                                            addC, ldadd, act);
}

extern "C" void kernel_launch(void* const* d_in, const int* in_sizes, int n_in,
                              void* d_out, int out_size) {
    const int* x = (const int*)d_in[0];
    const int* ei = (const int*)d_in[1];
    const int* ea = (const int*)d_in[2];
    const int* batch = (const int*)d_in[3];
    const float* node_emb = (const float*)d_in[4];
    const float* edge_emb = (const float*)d_in[5];
    const float* We = (const float*)d_in[6];
    const float* be = (const float*)d_in[7];
    const float* Wpre = (const float*)d_in[8];
    const float* bpre = (const float*)d_in[9];
    const float* Wpost = (const float*)d_in[10];
    const float* bpost = (const float*)d_in[11];
    const float* Wlin = (const float*)d_in[12];
    const float* blin = (const float*)d_in[13];
    const float* gamma = (const float*)d_in[14];
    const float* beta = (const float*)d_in[15];
    const float* W1 = (const float*)d_in[16];
    const float* b1 = (const float*)d_in[17];
    const float* W2 = (const float*)d_in[18];
    const float* b2 = (const float*)d_in[19];
    const float* W3 = (const float*)d_in[20];
    const float* b3 = (const float*)d_in[21];
    float* out = (float*)d_out;

    cudaFuncSetAttribute(tgemm_kernel, cudaFuncAttributeMaxDynamicSharedMemorySize, SMEM_BYTES);

    float *H, *CAB, *AGG, *G, *Z, *Y, *amp, *invamp, *Wcat, *Etab, *WG, *Wx, *pool, *z1, *z2;
    int *deg, *rowptr, *cursor, *csr, *bsum, *boffs;
    double *bnS, *bnQ;
    cudaGetSymbolAddress((void**)&H, g_H);
    cudaGetSymbolAddress((void**)&CAB, g_CAB);
    cudaGetSymbolAddress((void**)&AGG, g_AGG);
    cudaGetSymbolAddress((void**)&G, g_G);
    cudaGetSymbolAddress((void**)&Z, g_Z);
    cudaGetSymbolAddress((void**)&Y, g_Y);
    cudaGetSymbolAddress((void**)&amp, g_amp);
    cudaGetSymbolAddress((void**)&invamp, g_invamp);
    cudaGetSymbolAddress((void**)&deg, g_deg);
    cudaGetSymbolAddress((void**)&rowptr, g_rowptr);
    cudaGetSymbolAddress((void**)&cursor, g_cursor);
    cudaGetSymbolAddress((void**)&csr, g_csr);
    cudaGetSymbolAddress((void**)&bsum, g_bsum);
    cudaGetSymbolAddress((void**)&boffs, g_boffs);
    cudaGetSymbolAddress((void**)&Wcat, g_Wcat);
    cudaGetSymbolAddress((void**)&Etab, g_Etab);
    cudaGetSymbolAddress((void**)&WG, g_WG);
    cudaGetSymbolAddress((void**)&Wx, g_Wxcat);
    cudaGetSymbolAddress((void**)&bnS, g_bnS);
    cudaGetSymbolAddress((void**)&bnQ, g_bnQ);
    cudaGetSymbolAddress((void**)&pool, g_pool);
    cudaGetSymbolAddress((void**)&z1, g_z1);
    cudaGetSymbolAddress((void**)&z2, g_z2);

    // ---- graph structure prep ----
    zero_i<<<(NN + 255) / 256, 256>>>(deg, NN);
    zero_i<<<(NN + 255) / 256, 256>>>(cursor, NN);
    hist_k<<<(NE + 255) / 256, 256>>>(ei, deg);
    int nchunks = (NN + 511) / 512;
    scan_chunks<<<nchunks, 512>>>(deg, rowptr, bsum, NN);
    scan_sums<<<1, 128>>>(bsum, boffs, nchunks);
    scan_add<<<(NN + 255) / 256, 256>>>(rowptr, boffs);
    fill_csr<<<(NE + 255) / 256, 256>>>(ei, ea, rowptr, cursor, csr);
    amp_k<<<(NN + 255) / 256, 256>>>(rowptr, amp, invamp);
    embed_k<<<(NN * DD + 255) / 256, 256>>>(x, node_emb, H);

    // ---- weight prep ----
    prep_wcat<<<(NL * 75 * 750 + 255) / 256, 256>>>(Wpre, Wcat);
    prep_etab<<<dim3(4, NL), 384>>>(edge_emb, We, be, Wpre, bpre, Etab);
    prep_wg<<<(NL * TW * 300 * 45 + 255) / 256, 256>>>(Wpost, WG);
    prep_wxcat<<<(NL * 75 * 75 + 255) / 256, 256>>>(Wpost, Wx);
    prep_w0<<<(NL * 75 * 75 + 255) / 256, 256>>>(Wx, Wlin, Wcat);

    // ---- layers ----
    for (int l = 0; l < NL; l++) {
        // CAB = H @ Wcat_l  [NN,75] x [75,825]  (cols 750.. hold H@W0)
        tgemm(H, 75, 0, Wcat + l * 75 * 825, 825, 0, CAB, 825, 0, NN, 825, 75,
              nullptr, nullptr, 0, 0, 1);
        pna_agg<<<NN, 384>>>(CAB, Etab + l * 4 * 375, rowptr, csr, AGG);
        // G[t] = AGG[:, t*300:(t+1)*300] @ WG[l][t]  (batched over 5 towers)
        tgemm(AGG, 1500, 300, WG + l * TW * 300 * 45, 45, (long)300 * 45, G, 225, 45,
              NN, 45, 300, nullptr, nullptr, 0, 0, TW);
        combine_k<<<(NN * DD + 255) / 256, 256>>>(G, amp, invamp, bpost + l * TW * FO, Z);
        // Y = Z @ Wlin_l + (H@W0 from CAB[:,750:]) + blin
        tgemm(Z, 75, 0, Wlin + l * 5625, 75, 0, Y, 75, 0, NN, 75, 75,
              blin + l * 75, CAB + 750, 825, 0, 1);
        zero_d75<<<1, 128>>>(bnS, bnQ);
        bn_stats<<<(NN + 63) / 64, dim3(75, 4)>>>(Y, bnS, bnQ);
        bn_apply<<<(NN * DD + 255) / 256, 256>>>(Y, bnS, bnQ, gamma + l * DD, beta + l * DD, H);
    }

    // ---- pooling + MLP ----
    zero_f<<<(NG * DD + 255) / 256, 256>>>(pool, NG * DD);
    pool_k<<<(NN * DD + 255) / 256, 256>>>(batch, H, pool);
    tgemm(pool, 75, 0, W1, 50, 0, z1, 50, 0, NG, 50, 75, b1, nullptr, 0, 1, 1);
    tgemm(z1, 50, 0, W2, 25, 0, z2, 25, 0, NG, 25, 50, b2, nullptr, 0, 1, 1);
    tgemm(z2, 25, 0, W3, 1, 0, out, 1, 0, NG, 1, 25, b3, nullptr, 0, 0, 1);
}

// round 6
// speedup vs baseline: 1.0966x; 1.0966x over previous
#include <cuda_runtime.h>
#include <mma.h>
#include <math.h>
#include <cstdint>

using namespace nvcuda;

#define NN 50000
#define NE 150000
#define NG 2000
#define DD 75
#define TW 5
#define FO 15
#define NL 4
#define AVGLOG 1.1308269950720914f

// ---------------- scratch (device globals; no allocs) ----------------
__device__ float g_H[NN * DD];
__device__ float g_CAB[NN * 825];       // [A(dst 375) | B(src 375) | H@W0 (75)]
__device__ float g_AGG[NN * 1500];      // [T,4,D]
__device__ float g_G[NN * 225];
__device__ float g_Z[NN * DD];
__device__ float g_Y[NN * DD];
__device__ float g_amp[NN];
__device__ float g_invamp[NN];
__device__ int   g_deg[NN * 2];         // deg | cursor
__device__ int   g_rowptr[NN + 1];
__device__ int   g_csr[NE];
__device__ int   g_bsum[256];
__device__ int   g_boffs[256];
__device__ float g_Wcat[NL * 75 * 825];
__device__ float g_Etab[NL * 4 * 375];
__device__ float g_WG[NL * TW * 300 * 45];
__device__ float g_Wxcat[NL * 75 * 75];
__device__ double g_bnS[DD];
__device__ double g_bnQ[DD];
__device__ float g_pool[NG * DD];
__device__ float g_z1[NG * 50];
__device__ float g_z2[NG * 25];

// ---------------- cp.async helpers ----------------
__device__ __forceinline__ void cp4(float* dst_smem, const float* src, bool pred) {
    unsigned d = (unsigned)__cvta_generic_to_shared(dst_smem);
    int sz = pred ? 4 : 0;
    asm volatile("cp.async.ca.shared.global [%0], [%1], 4, %2;\n" ::"r"(d), "l"(src), "r"(sz));
}
#define CP_COMMIT() asm volatile("cp.async.commit_group;\n" ::: "memory")
#define CP_WAIT1() asm volatile("cp.async.wait_group 1;\n" ::: "memory")
#define CP_WAIT0() asm volatile("cp.async.wait_group 0;\n" ::: "memory")

// ---------------- 3xTF32 tensor-core GEMM, 2-stage cp.async pipeline ----------------
// tile 128x64, 256 threads (8 warps of 32x32)
// smem floats: sA[2][128*20] | sB[2][16*72] | sC[128*72]
#define SA_STRIDE 20
#define SB_STRIDE 72
#define SA_SZ (128 * SA_STRIDE)
#define SB_SZ (16 * SB_STRIDE)
#define SMEM_FLOATS (2 * SA_SZ + 2 * SB_SZ + 128 * 72)
#define SMEM_BYTES (SMEM_FLOATS * 4)

__global__ void tgemm_kernel(const float* __restrict__ A, int lda, long sAb,
                             const float* __restrict__ B, int ldb, long sBb,
                             float* __restrict__ C, int ldc, long sCb,
                             int M, int N, int K,
                             const float* __restrict__ bias,
                             const float* __restrict__ addC, int ldadd,
                             int act) {
    extern __shared__ float smem[];
    float* sA[2] = {smem, smem + SA_SZ};
    float* sB[2] = {smem + 2 * SA_SZ, smem + 2 * SA_SZ + SB_SZ};
    float* sC = smem + 2 * SA_SZ + 2 * SB_SZ;
    const float* Ab = A + (long)blockIdx.z * sAb;
    const float* Bb = B + (long)blockIdx.z * sBb;
    float* Cb = C + (long)blockIdx.z * sCb;
    int m0 = blockIdx.y * 128, n0 = blockIdx.x * 64;
    int tid = threadIdx.x;
    int warp = tid >> 5;
    int wm = (warp & 3) * 32;
    int wn = (warp >> 2) * 32;
    int numK = (K + 15) / 16;

    wmma::fragment<wmma::accumulator, 16, 16, 8, float> acc[2][2];
#pragma unroll
    for (int i = 0; i < 2; i++)
#pragma unroll
        for (int j = 0; j < 2; j++) wmma::fill_fragment(acc[i][j], 0.f);

    // stage loader
    auto load_stage = [&](int st, int k0) {
#pragma unroll 4
        for (int i = tid; i < 128 * 16; i += 256) {
            int r = i >> 4, c = i & 15;
            int gm = m0 + r, gk = k0 + c;
            bool p = (gm < M) && (gk < K);
            const float* src = p ? (Ab + (long)gm * lda + gk) : Ab;
            cp4(&sA[st][r * SA_STRIDE + c], src, p);
        }
#pragma unroll 2
        for (int i = tid; i < 16 * 64; i += 256) {
            int r = i >> 6, c = i & 63;
            int gk = k0 + r, gn = n0 + c;
            bool p = (gk < K) && (gn < N);
            const float* src = p ? (Bb + (long)gk * ldb + gn) : Bb;
            cp4(&sB[st][r * SB_STRIDE + c], src, p);
        }
    };

    load_stage(0, 0);
    CP_COMMIT();

    for (int kt = 0; kt < numK; kt++) {
        int st = kt & 1;
        if (kt + 1 < numK) {
            load_stage(st ^ 1, (kt + 1) * 16);
            CP_COMMIT();
            CP_WAIT1();
        } else {
            CP_WAIT0();
        }
        __syncthreads();
#pragma unroll
        for (int kk = 0; kk < 16; kk += 8) {
            wmma::fragment<wmma::matrix_a, 16, 16, 8, wmma::precision::tf32, wmma::row_major> ah[2], al[2];
            wmma::fragment<wmma::matrix_b, 16, 16, 8, wmma::precision::tf32, wmma::row_major> bh[2], bl[2];
#pragma unroll
            for (int i = 0; i < 2; i++) {
                wmma::load_matrix_sync(ah[i], &sA[st][(wm + 16 * i) * SA_STRIDE + kk], SA_STRIDE);
#pragma unroll
                for (int e = 0; e < ah[i].num_elements; e++) {
                    float v = ah[i].x[e];
                    float hi = wmma::__float_to_tf32(v);
                    ah[i].x[e] = hi;
                    al[i].x[e] = wmma::__float_to_tf32(v - hi);
                }
            }
#pragma unroll
            for (int j = 0; j < 2; j++) {
                wmma::load_matrix_sync(bh[j], &sB[st][kk * SB_STRIDE + wn + 16 * j], SB_STRIDE);
#pragma unroll
                for (int e = 0; e < bh[j].num_elements; e++) {
                    float v = bh[j].x[e];
                    float hi = wmma::__float_to_tf32(v);
                    bh[j].x[e] = hi;
                    bl[j].x[e] = wmma::__float_to_tf32(v - hi);
                }
            }
#pragma unroll
            for (int i = 0; i < 2; i++)
#pragma unroll
                for (int j = 0; j < 2; j++) {
                    wmma::mma_sync(acc[i][j], al[i], bh[j], acc[i][j]);
                    wmma::mma_sync(acc[i][j], ah[i], bl[j], acc[i][j]);
                    wmma::mma_sync(acc[i][j], ah[i], bh[j], acc[i][j]);
                }
        }
        __syncthreads();
    }
#pragma unroll
    for (int i = 0; i < 2; i++)
#pragma unroll
        for (int j = 0; j < 2; j++)
            wmma::store_matrix_sync(&sC[(wm + 16 * i) * 72 + wn + 16 * j], acc[i][j], 72,
                                    wmma::mem_row_major);
    __syncthreads();
    for (int i = tid; i < 128 * 64; i += 256) {
        int r = i >> 6, c = i & 63;
        int gm = m0 + r, gn = n0 + c;
        if (gm < M && gn < N) {
            float v = sC[r * 72 + c];
            if (bias) v += bias[gn];
            if (addC) v += addC[(long)gm * ldadd + gn];
            if (act) v = fmaxf(v, 0.f);
            Cb[(long)gm * ldc + gn] = v;
        }
    }
}

// ---------------- small utility kernels ----------------
__global__ void zero_i(int* p, int n) {
    int i = blockIdx.x * blockDim.x + threadIdx.x;
    if (i < n) p[i] = 0;
}
__global__ void zero_f(float* p, int n) {
    int i = blockIdx.x * blockDim.x + threadIdx.x;
    if (i < n) p[i] = 0.f;
}
__global__ void zero_d75(double* a, double* b) {
    int i = threadIdx.x;
    if (i < DD) { a[i] = 0.0; b[i] = 0.0; }
}

__global__ void hist_k(const int* __restrict__ ei, int* __restrict__ deg) {
    int e = blockIdx.x * blockDim.x + threadIdx.x;
    if (e < NE) atomicAdd(&deg[ei[NE + e]], 1);
}

__global__ void scan_chunks(const int* __restrict__ in, int* __restrict__ out,
                            int* __restrict__ bsum, int n) {
    __shared__ int s[512];
    int b = blockIdx.x, t = threadIdx.x;
    int idx = b * 512 + t;
    int v = (idx < n) ? in[idx] : 0;
    s[t] = v;
    __syncthreads();
    for (int off = 1; off < 512; off <<= 1) {
        int x = (t >= off) ? s[t - off] : 0;
        __syncthreads();
        s[t] += x;
        __syncthreads();
    }
    if (idx < n) out[idx] = s[t] - v;
    if (t == 511) bsum[b] = s[511];
}
__global__ void scan_sums(const int* __restrict__ sums, int* __restrict__ offs, int nb) {
    __shared__ int s[128];
    int t = threadIdx.x;
    int v = (t < nb) ? sums[t] : 0;
    s[t] = v;
    __syncthreads();
    for (int off = 1; off < 128; off <<= 1) {
        int x = (t >= off) ? s[t - off] : 0;
        __syncthreads();
        s[t] += x;
        __syncthreads();
    }
    if (t < nb) offs[t] = s[t] - v;
}
__global__ void scan_add(int* __restrict__ rowptr, const int* __restrict__ offs) {
    int i = blockIdx.x * blockDim.x + threadIdx.x;
    if (i < NN) rowptr[i] += offs[i >> 9];
    if (i == 0) rowptr[NN] = NE;
}

__global__ void fill_csr(const int* __restrict__ ei, const int* __restrict__ ea,
                         const int* __restrict__ rowptr, int* __restrict__ cursor,
                         int* __restrict__ csr) {
    int e = blockIdx.x * blockDim.x + threadIdx.x;
    if (e >= NE) return;
    int d = ei[NE + e];
    int pos = rowptr[d] + atomicAdd(&cursor[d], 1);
    csr[pos] = ei[e] | (ea[e] << 20);
}

__global__ void amp_k(const int* __restrict__ rowptr, float* __restrict__ amp,
                      float* __restrict__ invamp) {
    int i = blockIdx.x * blockDim.x + threadIdx.x;
    if (i >= NN) return;
    int dg = rowptr[i + 1] - rowptr[i];
    float a = logf((float)max(dg, 1) + 1.f) / AVGLOG;
    amp[i] = a;
    invamp[i] = 1.f / a;
}

__global__ void embed_k(const int* __restrict__ x, const float* __restrict__ emb,
                        float* __restrict__ H) {
    int i = blockIdx.x * blockDim.x + threadIdx.x;
    if (i >= NN * DD) return;
    H[i] = emb[x[i / DD] * DD + i % DD];
}

// ---------------- weight prep ----------------
__global__ void prep_wcat(const float* __restrict__ Wpre, float* __restrict__ Wcat) {
    int i = blockIdx.x * blockDim.x + threadIdx.x;
    if (i >= NL * 75 * 750) return;
    int l = i / (75 * 750), r = i % (75 * 750);
    int k = r / 750, j = r % 750;
    int part = j / 375, j2 = j % 375;
    int t = j2 / 75, f = j2 % 75;
    int c = part * 75 + k;
    Wcat[(l * 75 + k) * 825 + j] = Wpre[((l * TW + t) * 225 + c) * 75 + f];
}

__global__ void prep_etab(const float* __restrict__ edge_emb, const float* __restrict__ We,
                          const float* __restrict__ be, const float* __restrict__ Wpre,
                          const float* __restrict__ bpre, float* __restrict__ Etab) {
    int a = blockIdx.x, l = blockIdx.y;
    __shared__ float ev[75];
    int t0 = threadIdx.x;
    if (t0 < 75) {
        float s = be[l * 75 + t0];
        for (int c = 0; c < 50; c++) s += edge_emb[a * 50 + c] * We[(l * 50 + c) * 75 + t0];
        ev[t0] = s;
    }
    __syncthreads();
    for (int j = t0; j < 375; j += blockDim.x) {
        int t = j / 75, f = j % 75;
        float s = bpre[(l * TW + t) * 75 + f];
        for (int d = 0; d < 75; d++)
            s += ev[d] * Wpre[((l * TW + t) * 225 + 150 + d) * 75 + f];
        Etab[(l * 4 + a) * 375 + j] = s;
    }
}

__global__ void prep_wg(const float* __restrict__ Wpost, float* __restrict__ WG) {
    int i = blockIdx.x * blockDim.x + threadIdx.x;
    if (i >= NL * TW * 300 * 45) return;
    int lt = i / (300 * 45), r = i % (300 * 45);
    int c = r / 45, col = r % 45;
    int g = col / 15, f = col % 15;
    WG[i] = Wpost[(lt * 975 + 75 + g * 300 + c) * 15 + f];
}

__global__ void prep_wxcat(const float* __restrict__ Wpost, float* __restrict__ Wx) {
    int i = blockIdx.x * blockDim.x + threadIdx.x;
    if (i >= NL * 75 * 75) return;
    int l = i / (75 * 75), r = i % (75 * 75);
    int c = r / 75, j = r % 75;
    int t = j / 15, f = j % 15;
    Wx[i] = Wpost[((l * TW + t) * 975 + c) * 15 + f];
}

// W0 = Wxcat @ Wlin, stored into columns [750, 825) of Wcat
__global__ void prep_w0(const float* __restrict__ Wx, const float* __restrict__ Wlin,
                        float* __restrict__ Wcat) {
    int i = blockIdx.x * blockDim.x + threadIdx.x;
    if (i >= NL * 75 * 75) return;
    int l = i / (75 * 75), r = i % (75 * 75);
    int k = r / 75, c = r % 75;
    float s = 0.f;
    for (int d = 0; d < 75; d++)
        s += Wx[l * 5625 + k * 75 + d] * Wlin[l * 5625 + d * 75 + c];
    Wcat[(l * 75 + k) * 825 + 750 + c] = s;
}

// ---------------- PNA aggregation (mean/min/max/std over CSR) ----------------
__global__ void pna_agg(const float* __restrict__ CAB, const float* __restrict__ Etab,
                        const int* __restrict__ rowptr, const int* __restrict__ csr,
                        float* __restrict__ AGG) {
    int n = blockIdx.x;
    int j = threadIdx.x;
    if (j >= 375) return;
    float adst = CAB[(long)n * 825 + j];
    int beg = rowptr[n], end = rowptr[n + 1];
    float s = 0.f, sq = 0.f, mn = 3.4e38f, mx = -3.4e38f;
    for (int e = beg; e < end; e++) {
        int p = csr[e];
        int src = p & 0xFFFFF;
        int attr = p >> 20;
        float v = adst + CAB[(long)src * 825 + 375 + j] + Etab[attr * 375 + j];
        s += v;
        sq += v * v;
        mn = fminf(mn, v);
        mx = fmaxf(mx, v);
    }
    int dg = end - beg;
    float denom = fmaxf((float)dg, 1.f);
    float mean = s / denom, msq = sq / denom;
    float sd = sqrtf(fmaxf(msq - mean * mean, 0.f) + 1e-5f);
    if (dg == 0) { mn = 0.f; mx = 0.f; }
    int t = j / 75, f = j % 75;
    float* o = AGG + (long)n * 1500 + t * 300;
    o[f] = mean;
    o[75 + f] = mn;
    o[150 + f] = mx;
    o[225 + f] = sd;
}

// ---------------- combine towers + scalers ----------------
__global__ void combine_k(const float* __restrict__ G, const float* __restrict__ amp,
                          const float* __restrict__ invamp, const float* __restrict__ bpost,
                          float* __restrict__ Z) {
    int i = blockIdx.x * blockDim.x + threadIdx.x;
    if (i >= NN * DD) return;
    int n = i / DD, j = i % DD;
    int t = j / 15, f = j % 15;
    const float* g = G + (long)n * 225 + t * 45;
    Z[i] = g[f] + amp[n] * g[15 + f] + invamp[n] * g[30 + f] + bpost[t * 15 + f];
}

// ---------------- batchnorm ----------------
__global__ void bn_stats(const float* __restrict__ Y, double* __restrict__ S,
                         double* __restrict__ Q) {
    __shared__ float ss[4][75], sq[4][75];
    int f = threadIdx.x, w = threadIdx.y;
    int base = blockIdx.x * 64;
    float s = 0.f, q = 0.f;
    for (int r = w; r < 64; r += 4) {
        int n = base + r;
        if (n < NN) {
            float v = Y[(long)n * DD + f];
            s += v;
            q += v * v;
        }
    }
    ss[w][f] = s;
    sq[w][f] = q;
    __syncthreads();
    if (w == 0) {
        float st = ss[0][f] + ss[1][f] + ss[2][f] + ss[3][f];
        float qt = sq[0][f] + sq[1][f] + sq[2][f] + sq[3][f];
        atomicAdd(&S[f], (double)st);
        atomicAdd(&Q[f], (double)qt);
    }
}

__global__ void bn_apply(const float* __restrict__ Y, const double* __restrict__ S,
                         const double* __restrict__ Q, const float* __restrict__ gamma,
                         const float* __restrict__ beta, float* __restrict__ H) {
    int i = blockIdx.x * blockDim.x + threadIdx.x;
    if (i >= NN * DD) return;
    int f = i % DD;
    double mu = S[f] / (double)NN;
    double var = Q[f] / (double)NN - mu * mu;
    float inv = rsqrtf((float)var + 1e-5f);
    float v = gamma[f] * ((Y[i] - (float)mu) * inv) + beta[f];
    H[i] = fmaxf(v, 0.f);
}

// ---------------- pooling ----------------
__global__ void pool_k(const int* __restrict__ batch, const float* __restrict__ H,
                       float* __restrict__ pool) {
    int i = blockIdx.x * blockDim.x + threadIdx.x;
    if (i >= NN * DD) return;
    int n = i / DD, f = i % DD;
    atomicAdd(&pool[batch[n] * DD + f], H[i]);
}

// ---------------- launch ----------------
static inline void tgemm(const float* A, int lda, long sA, const float* B, int ldb, long sB,
                         float* C, int ldc, long sC, int M, int N, int K, const float* bias,
                         const float* addC, int ldadd, int act, int nz) {
    dim3 grid((N + 63) / 64, (M + 127) / 128, nz);
    tgemm_kernel<<<grid, 256, SMEM_BYTES>>>(A, lda, sA, B, ldb, sB, C, ldc, sC, M, N, K, bias,
                                            addC, ldadd, act);
}

extern "C" void kernel_launch(void* const* d_in, const int* in_sizes, int n_in,
                              void* d_out, int out_size) {
    const int* x = (const int*)d_in[0];
    const int* ei = (const int*)d_in[1];
    const int* ea = (const int*)d_in[2];
    const int* batch = (const int*)d_in[3];
    const float* node_emb = (const float*)d_in[4];
    const float* edge_emb = (const float*)d_in[5];
    const float* We = (const float*)d_in[6];
    const float* be = (const float*)d_in[7];
    const float* Wpre = (const float*)d_in[8];
    const float* bpre = (const float*)d_in[9];
    const float* Wpost = (const float*)d_in[10];
    const float* bpost = (const float*)d_in[11];
    const float* Wlin = (const float*)d_in[12];
    const float* blin = (const float*)d_in[13];
    const float* gamma = (const float*)d_in[14];
    const float* beta = (const float*)d_in[15];
    const float* W1 = (const float*)d_in[16];
    const float* b1 = (const float*)d_in[17];
    const float* W2 = (const float*)d_in[18];
    const float* b2 = (const float*)d_in[19];
    const float* W3 = (const float*)d_in[20];
    const float* b3 = (const float*)d_in[21];
    float* out = (float*)d_out;

    cudaFuncSetAttribute(tgemm_kernel, cudaFuncAttributeMaxDynamicSharedMemorySize, SMEM_BYTES);

    float *H, *CAB, *AGG, *G, *Z, *Y, *amp, *invamp, *Wcat, *Etab, *WG, *Wx, *pool, *z1, *z2;
    int *deg, *rowptr, *csr, *bsum, *boffs;
    double *bnS, *bnQ;
    cudaGetSymbolAddress((void**)&H, g_H);
    cudaGetSymbolAddress((void**)&CAB, g_CAB);
    cudaGetSymbolAddress((void**)&AGG, g_AGG);
    cudaGetSymbolAddress((void**)&G, g_G);
    cudaGetSymbolAddress((void**)&Z, g_Z);
    cudaGetSymbolAddress((void**)&Y, g_Y);
    cudaGetSymbolAddress((void**)&amp, g_amp);
    cudaGetSymbolAddress((void**)&invamp, g_invamp);
    cudaGetSymbolAddress((void**)&deg, g_deg);
    cudaGetSymbolAddress((void**)&rowptr, g_rowptr);
    cudaGetSymbolAddress((void**)&csr, g_csr);
    cudaGetSymbolAddress((void**)&bsum, g_bsum);
    cudaGetSymbolAddress((void**)&boffs, g_boffs);
    cudaGetSymbolAddress((void**)&Wcat, g_Wcat);
    cudaGetSymbolAddress((void**)&Etab, g_Etab);
    cudaGetSymbolAddress((void**)&WG, g_WG);
    cudaGetSymbolAddress((void**)&Wx, g_Wxcat);
    cudaGetSymbolAddress((void**)&bnS, g_bnS);
    cudaGetSymbolAddress((void**)&bnQ, g_bnQ);
    cudaGetSymbolAddress((void**)&pool, g_pool);
    cudaGetSymbolAddress((void**)&z1, g_z1);
    cudaGetSymbolAddress((void**)&z2, g_z2);
    int* cursor = deg + NN;

    // ---- ordered so launch index 5 is the first big GEMM (ncu -s 5 -c 1) ----
    embed_k<<<(NN * DD + 255) / 256, 256>>>(x, node_emb, H);             // 0
    prep_wcat<<<(NL * 75 * 750 + 255) / 256, 256>>>(Wpre, Wcat);         // 1
    prep_wg<<<(NL * TW * 300 * 45 + 255) / 256, 256>>>(Wpost, WG);       // 2
    prep_wxcat<<<(NL * 75 * 75 + 255) / 256, 256>>>(Wpost, Wx);          // 3
    prep_w0<<<(NL * 75 * 75 + 255) / 256, 256>>>(Wx, Wlin, Wcat);        // 4
    // 5: layer-0 CAB GEMM  (ncu capture target)
    tgemm(H, 75, 0, Wcat, 825, 0, CAB, 825, 0, NN, 825, 75, nullptr, nullptr, 0, 0, 1);

    // ---- graph structure prep (all before pna_agg) ----
    zero_i<<<(2 * NN + 255) / 256, 256>>>(deg, 2 * NN);
    hist_k<<<(NE + 255) / 256, 256>>>(ei, deg);
    int nchunks = (NN + 511) / 512;
    scan_chunks<<<nchunks, 512>>>(deg, rowptr, bsum, NN);
    scan_sums<<<1, 128>>>(bsum, boffs, nchunks);
    scan_add<<<(NN + 255) / 256, 256>>>(rowptr, boffs);
    fill_csr<<<(NE + 255) / 256, 256>>>(ei, ea, rowptr, cursor, csr);
    amp_k<<<(NN + 255) / 256, 256>>>(rowptr, amp, invamp);
    prep_etab<<<dim3(4, NL), 384>>>(edge_emb, We, be, Wpre, bpre, Etab);

    // ---- layers ----
    for (int l = 0; l < NL; l++) {
        if (l > 0) {
            // CAB = H @ Wcat_l  [NN,75] x [75,825]  (cols 750.. hold H@W0)
            tgemm(H, 75, 0, Wcat + l * 75 * 825, 825, 0, CAB, 825, 0, NN, 825, 75,
                  nullptr, nullptr, 0, 0, 1);
        }
        pna_agg<<<NN, 384>>>(CAB, Etab + l * 4 * 375, rowptr, csr, AGG);
        // G[t] = AGG[:, t*300:(t+1)*300] @ WG[l][t]  (batched over 5 towers)
        tgemm(AGG, 1500, 300, WG + l * TW * 300 * 45, 45, (long)300 * 45, G, 225, 45,
              NN, 45, 300, nullptr, nullptr, 0, 0, TW);
        combine_k<<<(NN * DD + 255) / 256, 256>>>(G, amp, invamp, bpost + l * TW * FO, Z);
        // Y = Z @ Wlin_l + (H@W0 from CAB[:,750:]) + blin
        tgemm(Z, 75, 0, Wlin + l * 5625, 75, 0, Y, 75, 0, NN, 75, 75,
              blin + l * 75, CAB + 750, 825, 0, 1);
        zero_d75<<<1, 128>>>(bnS, bnQ);
        bn_stats<<<(NN + 63) / 64, dim3(75, 4)>>>(Y, bnS, bnQ);
        bn_apply<<<(NN * DD + 255) / 256, 256>>>(Y, bnS, bnQ, gamma + l * DD, beta + l * DD, H);
    }

    // ---- pooling + MLP ----
    zero_f<<<(NG * DD + 255) / 256, 256>>>(pool, NG * DD);
    pool_k<<<(NN * DD + 255) / 256, 256>>>(batch, H, pool);
    tgemm(pool, 75, 0, W1, 50, 0, z1, 50, 0, NG, 50, 75, b1, nullptr, 0, 1, 1);
    tgemm(z1, 50, 0, W2, 25, 0, z2, 25, 0, NG, 25, 50, b2, nullptr, 0, 1, 1);
    tgemm(z2, 25, 0, W3, 1, 0, out, 1, 0, NG, 1, 25, b3, nullptr, 0, 0, 1);
}

// round 8
// speedup vs baseline: 1.4660x; 1.3368x over previous
#include <cuda_runtime.h>
#include <mma.h>
#include <math.h>
#include <cstdint>
#include <cuda_bf16.h>

using namespace nvcuda;

#define NN 50000
#define NE 150000
#define NG 2000
#define DD 75
#define TW 5
#define FO 15
#define NL 4
#define AVGLOG 1.1308269950720914f

// ---------------- scratch (device globals; no allocs) ----------------
__device__ float g_H[NN * DD];
__device__ float g_CAB[NN * 825];       // [A(dst 375) | B(src 375) | H@W0 (75)]
__device__ float g_AGG[NN * 1500];      // [T,4,D]
__device__ float g_G[NN * 225];
__device__ float g_Z[NN * DD];
__device__ float g_Y[NN * DD];
__device__ float g_amp[NN];
__device__ float g_invamp[NN];
__device__ int   g_deg[NN * 2];         // deg | cursor
__device__ int   g_rowptr[NN + 1];
__device__ int   g_csr[NE];
__device__ int   g_bsum[256];
__device__ int   g_boffs[256];
__device__ float g_Wcat[NL * 75 * 825];
__device__ float g_Etab[NL * 4 * 375];
__device__ float g_WG[NL * TW * 300 * 45];
__device__ double g_bnS[DD];
__device__ double g_bnQ[DD];
__device__ float g_pool[NG * DD];
__device__ float g_z1[NG * 50];
__device__ float g_z2[NG * 25];

// ---------------- split-bf16 tensor-core GEMM (128x64 tile, batched over z) ----------
// A,B fp32 in global; converted to bf16 hi/lo in smem; acc fp32.
// smem (bf16 elems): sAh/sAl [2][128*24], sBh/sBl [2][16*72]; sC fp32 unioned at base.
#define SAS 24
#define SBS 72
#define SA_ELE (128 * SAS)
#define SB_ELE (16 * SBS)
#define STAGE_BYTES (2 * (2 * SA_ELE + 2 * SB_ELE))          // bytes of all bf16 buffers
#define SC_BYTES (128 * 72 * 4)
#define SMEM_BYTES (STAGE_BYTES > SC_BYTES ? STAGE_BYTES : SC_BYTES)

__global__ __launch_bounds__(256) void tgemm_kernel(
    const float* __restrict__ A, int lda, long sAb,
    const float* __restrict__ B, int ldb, long sBb,
    float* __restrict__ C, int ldc, long sCb,
    int M, int N, int K,
    const float* __restrict__ bias,
    const float* __restrict__ addC, int ldadd,
    int act) {
    extern __shared__ char smem_raw[];
    __nv_bfloat16* bb = (__nv_bfloat16*)smem_raw;
    __nv_bfloat16* sAh[2] = {bb, bb + SA_ELE};
    __nv_bfloat16* sAl[2] = {bb + 2 * SA_ELE, bb + 3 * SA_ELE};
    __nv_bfloat16* sBh[2] = {bb + 4 * SA_ELE, bb + 4 * SA_ELE + SB_ELE};
    __nv_bfloat16* sBl[2] = {bb + 4 * SA_ELE + 2 * SB_ELE, bb + 4 * SA_ELE + 3 * SB_ELE};
    float* sC = (float*)smem_raw;   // union: used after mainloop only

    const float* Ab = A + (long)blockIdx.z * sAb;
    const float* Bb = B + (long)blockIdx.z * sBb;
    float* Cb = C + (long)blockIdx.z * sCb;
    int m0 = blockIdx.y * 128, n0 = blockIdx.x * 64;
    int tid = threadIdx.x;
    int warp = tid >> 5;
    int wm = (warp & 3) * 32;
    int wn = (warp >> 2) * 32;
    int numK = (K + 15) / 16;

    wmma::fragment<wmma::accumulator, 16, 16, 16, float> acc[2][2];
#pragma unroll
    for (int i = 0; i < 2; i++)
#pragma unroll
        for (int j = 0; j < 2; j++) wmma::fill_fragment(acc[i][j], 0.f);

    float ra[8], rb[4];
    auto gload = [&](int k0) {
#pragma unroll
        for (int u = 0; u < 8; u++) {
            int i = tid + u * 256;
            int r = i >> 4, c = i & 15;
            int gm = m0 + r, gk = k0 + c;
            ra[u] = (gm < M && gk < K) ? __ldg(Ab + (long)gm * lda + gk) : 0.f;
        }
#pragma unroll
        for (int u = 0; u < 4; u++) {
            int i = tid + u * 256;
            int r = i >> 6, c = i & 63;
            int gk = k0 + r, gn = n0 + c;
            rb[u] = (gk < K && gn < N) ? __ldg(Bb + (long)gk * ldb + gn) : 0.f;
        }
    };
    auto sstore = [&](int st) {
#pragma unroll
        for (int u = 0; u < 8; u++) {
            int i = tid + u * 256;
            int r = i >> 4, c = i & 15;
            __nv_bfloat16 h = __float2bfloat16(ra[u]);
            sAh[st][r * SAS + c] = h;
            sAl[st][r * SAS + c] = __float2bfloat16(ra[u] - __bfloat162float(h));
        }
#pragma unroll
        for (int u = 0; u < 4; u++) {
            int i = tid + u * 256;
            int r = i >> 6, c = i & 63;
            __nv_bfloat16 h = __float2bfloat16(rb[u]);
            sBh[st][r * SBS + c] = h;
            sBl[st][r * SBS + c] = __float2bfloat16(rb[u] - __bfloat162float(h));
        }
    };

    gload(0);
    sstore(0);
    __syncthreads();

    for (int kt = 0; kt < numK; kt++) {
        int st = kt & 1;
        if (kt + 1 < numK) gload((kt + 1) * 16);   // global loads in flight during compute

        wmma::fragment<wmma::matrix_a, 16, 16, 16, __nv_bfloat16, wmma::row_major> ah[2], al[2];
        wmma::fragment<wmma::matrix_b, 16, 16, 16, __nv_bfloat16, wmma::row_major> bh[2], bl[2];
#pragma unroll
        for (int i = 0; i < 2; i++) {
            wmma::load_matrix_sync(ah[i], &sAh[st][(wm + 16 * i) * SAS], SAS);
            wmma::load_matrix_sync(al[i], &sAl[st][(wm + 16 * i) * SAS], SAS);
        }
#pragma unroll
        for (int j = 0; j < 2; j++) {
            wmma::load_matrix_sync(bh[j], &sBh[st][wn + 16 * j], SBS);
            wmma::load_matrix_sync(bl[j], &sBl[st][wn + 16 * j], SBS);
        }
#pragma unroll
        for (int i = 0; i < 2; i++)
#pragma unroll
            for (int j = 0; j < 2; j++) {
                wmma::mma_sync(acc[i][j], al[i], bh[j], acc[i][j]);
                wmma::mma_sync(acc[i][j], ah[i], bl[j], acc[i][j]);
                wmma::mma_sync(acc[i][j], ah[i], bh[j], acc[i][j]);
            }
        __syncthreads();
        if (kt + 1 < numK) {
            sstore(st ^ 1);
            __syncthreads();
        }
    }

    // epilogue via smem (unioned with stage buffers; all reads done)
#pragma unroll
    for (int i = 0; i < 2; i++)
#pragma unroll
        for (int j = 0; j < 2; j++)
            wmma::store_matrix_sync(&sC[(wm + 16 * i) * 72 + wn + 16 * j], acc[i][j], 72,
                                    wmma::mem_row_major);
    __syncthreads();
    for (int i = tid; i < 128 * 64; i += 256) {
        int r = i >> 6, c = i & 63;
        int gm = m0 + r, gn = n0 + c;
        if (gm < M && gn < N) {
            float v = sC[r * 72 + c];
            if (bias) v += bias[gn];
            if (addC) v += addC[(long)gm * ldadd + gn];
            if (act) v = fmaxf(v, 0.f);
            Cb[(long)gm * ldc + gn] = v;
        }
    }
}

// ---------------- small utility kernels ----------------
__global__ void zero_i(int* p, int n) {
    int i = blockIdx.x * blockDim.x + threadIdx.x;
    if (i < n) p[i] = 0;
}
__global__ void zero_f(float* p, int n) {
    int i = blockIdx.x * blockDim.x + threadIdx.x;
    if (i < n) p[i] = 0.f;
}
__global__ void zero_d75(double* a, double* b) {
    int i = threadIdx.x;
    if (i < DD) { a[i] = 0.0; b[i] = 0.0; }
}

__global__ void hist_k(const int* __restrict__ ei, int* __restrict__ deg) {
    int e = blockIdx.x * blockDim.x + threadIdx.x;
    if (e < NE) atomicAdd(&deg[ei[NE + e]], 1);
}

__global__ void scan_chunks(const int* __restrict__ in, int* __restrict__ out,
                            int* __restrict__ bsum, int n) {
    __shared__ int s[512];
    int b = blockIdx.x, t = threadIdx.x;
    int idx = b * 512 + t;
    int v = (idx < n) ? in[idx] : 0;
    s[t] = v;
    __syncthreads();
    for (int off = 1; off < 512; off <<= 1) {
        int x = (t >= off) ? s[t - off] : 0;
        __syncthreads();
        s[t] += x;
        __syncthreads();
    }
    if (idx < n) out[idx] = s[t] - v;
    if (t == 511) bsum[b] = s[511];
}
__global__ void scan_sums(const int* __restrict__ sums, int* __restrict__ offs, int nb) {
    __shared__ int s[128];
    int t = threadIdx.x;
    int v = (t < nb) ? sums[t] : 0;
    s[t] = v;
    __syncthreads();
    for (int off = 1; off < 128; off <<= 1) {
        int x = (t >= off) ? s[t - off] : 0;
        __syncthreads();
        s[t] += x;
        __syncthreads();
    }
    if (t < nb) offs[t] = s[t] - v;
}
__global__ void scan_add(int* __restrict__ rowptr, const int* __restrict__ offs) {
    int i = blockIdx.x * blockDim.x + threadIdx.x;
    if (i < NN) rowptr[i] += offs[i >> 9];
    if (i == 0) rowptr[NN] = NE;
}

__global__ void fill_csr(const int* __restrict__ ei, const int* __restrict__ ea,
                         const int* __restrict__ rowptr, int* __restrict__ cursor,
                         int* __restrict__ csr) {
    int e = blockIdx.x * blockDim.x + threadIdx.x;
    if (e >= NE) return;
    int d = ei[NE + e];
    int pos = rowptr[d] + atomicAdd(&cursor[d], 1);
    csr[pos] = ei[e] | (ea[e] << 20);
}

__global__ void amp_k(const int* __restrict__ rowptr, float* __restrict__ amp,
                      float* __restrict__ invamp) {
    int i = blockIdx.x * blockDim.x + threadIdx.x;
    if (i >= NN) return;
    int dg = rowptr[i + 1] - rowptr[i];
    float a = logf((float)max(dg, 1) + 1.f) / AVGLOG;
    amp[i] = a;
    invamp[i] = 1.f / a;
}

__global__ void embed_k(const int* __restrict__ x, const float* __restrict__ emb,
                        float* __restrict__ H) {
    int i = blockIdx.x * blockDim.x + threadIdx.x;
    if (i >= NN * DD) return;
    H[i] = emb[x[i / DD] * DD + i % DD];
}

// ---------------- weight prep ----------------
__global__ void prep_wcat(const float* __restrict__ Wpre, float* __restrict__ Wcat) {
    int i = blockIdx.x * blockDim.x + threadIdx.x;
    if (i >= NL * 75 * 750) return;
    int l = i / (75 * 750), r = i % (75 * 750);
    int k = r / 750, j = r % 750;
    int part = j / 375, j2 = j % 375;
    int t = j2 / 75, f = j2 % 75;
    int c = part * 75 + k;
    Wcat[(l * 75 + k) * 825 + j] = Wpre[((l * TW + t) * 225 + c) * 75 + f];
}

// W0 = Wx @ Wlin (Wx built on the fly from Wpost), into Wcat cols [750,825)
__global__ void prep_w0(const float* __restrict__ Wpost, const float* __restrict__ Wlin,
                        float* __restrict__ Wcat) {
    int i = blockIdx.x * blockDim.x + threadIdx.x;
    if (i >= NL * 75 * 75) return;
    int l = i / 5625, r = i % 5625;
    int k = r / 75, c = r % 75;
    float s = 0.f;
    for (int d = 0; d < 75; d++) {
        int t = d / 15, f = d % 15;
        float wx = Wpost[((l * TW + t) * 975 + k) * 15 + f];
        s += wx * Wlin[l * 5625 + d * 75 + c];
    }
    Wcat[(l * 75 + k) * 825 + 750 + c] = s;
}

__global__ void prep_etab(const float* __restrict__ edge_emb, const float* __restrict__ We,
                          const float* __restrict__ be, const float* __restrict__ Wpre,
                          const float* __restrict__ bpre, float* __restrict__ Etab) {
    int a = blockIdx.x, l = blockIdx.y;
    __shared__ float ev[75];
    int t0 = threadIdx.x;
    if (t0 < 75) {
        float s = be[l * 75 + t0];
        for (int c = 0; c < 50; c++) s += edge_emb[a * 50 + c] * We[(l * 50 + c) * 75 + t0];
        ev[t0] = s;
    }
    __syncthreads();
    for (int j = t0; j < 375; j += blockDim.x) {
        int t = j / 75, f = j % 75;
        float s = bpre[(l * TW + t) * 75 + f];
        for (int d = 0; d < 75; d++)
            s += ev[d] * Wpre[((l * TW + t) * 225 + 150 + d) * 75 + f];
        Etab[(l * 4 + a) * 375 + j] = s;
    }
}

__global__ void prep_wg(const float* __restrict__ Wpost, float* __restrict__ WG) {
    int i = blockIdx.x * blockDim.x + threadIdx.x;
    if (i >= NL * TW * 300 * 45) return;
    int lt = i / (300 * 45), r = i % (300 * 45);
    int c = r / 45, col = r % 45;
    int g = col / 15, f = col % 15;
    WG[i] = Wpost[(lt * 975 + 75 + g * 300 + c) * 15 + f];
}

// ---------------- PNA aggregation (mean/min/max/std over CSR), 2-way unroll ---------
__global__ __launch_bounds__(384) void pna_agg(const float* __restrict__ CAB,
                                               const float* __restrict__ Etab,
                                               const int* __restrict__ rowptr,
                                               const int* __restrict__ csr,
                                               float* __restrict__ AGG) {
    int n = blockIdx.x;
    int j = threadIdx.x;
    if (j >= 375) return;
    float adst = CAB[(long)n * 825 + j];
    int beg = rowptr[n], end = rowptr[n + 1];
    float s = 0.f, sq = 0.f, mn = 3.4e38f, mx = -3.4e38f;
    int e = beg;
    for (; e + 1 < end; e += 2) {
        int p0 = csr[e], p1 = csr[e + 1];
        float b0 = CAB[(long)(p0 & 0xFFFFF) * 825 + 375 + j];
        float b1 = CAB[(long)(p1 & 0xFFFFF) * 825 + 375 + j];
        float v0 = adst + b0 + Etab[(p0 >> 20) * 375 + j];
        float v1 = adst + b1 + Etab[(p1 >> 20) * 375 + j];
        s += v0 + v1;
        sq += v0 * v0 + v1 * v1;
        mn = fminf(mn, fminf(v0, v1));
        mx = fmaxf(mx, fmaxf(v0, v1));
    }
    if (e < end) {
        int p0 = csr[e];
        float v0 = adst + CAB[(long)(p0 & 0xFFFFF) * 825 + 375 + j] + Etab[(p0 >> 20) * 375 + j];
        s += v0;
        sq += v0 * v0;
        mn = fminf(mn, v0);
        mx = fmaxf(mx, v0);
    }
    int dg = end - beg;
    float denom = fmaxf((float)dg, 1.f);
    float mean = s / denom, msq = sq / denom;
    float sd = sqrtf(fmaxf(msq - mean * mean, 0.f) + 1e-5f);
    if (dg == 0) { mn = 0.f; mx = 0.f; }
    int t = j / 75, f = j % 75;
    float* o = AGG + (long)n * 1500 + t * 300;
    o[f] = mean;
    o[75 + f] = mn;
    o[150 + f] = mx;
    o[225 + f] = sd;
}

// ---------------- combine towers + scalers ----------------
__global__ void combine_k(const float* __restrict__ G, const float* __restrict__ amp,
                          const float* __restrict__ invamp, const float* __restrict__ bpost,
                          float* __restrict__ Z) {
    int i = blockIdx.x * blockDim.x + threadIdx.x;
    if (i >= NN * DD) return;
    int n = i / DD, j = i % DD;
    int t = j / 15, f = j % 15;
    const float* g = G + (long)n * 225 + t * 45;
    Z[i] = g[f] + amp[n] * g[15 + f] + invamp[n] * g[30 + f] + bpost[t * 15 + f];
}

// ---------------- batchnorm ----------------
__global__ void bn_stats(const float* __restrict__ Y, double* __restrict__ S,
                         double* __restrict__ Q) {
    __shared__ float ss[4][75], sq[4][75];
    int f = threadIdx.x, w = threadIdx.y;
    int base = blockIdx.x * 64;
    float s = 0.f, q = 0.f;
    for (int r = w; r < 64; r += 4) {
        int n = base + r;
        if (n < NN) {
            float v = Y[(long)n * DD + f];
            s += v;
            q += v * v;
        }
    }
    ss[w][f] = s;
    sq[w][f] = q;
    __syncthreads();
    if (w == 0) {
        float st = ss[0][f] + ss[1][f] + ss[2][f] + ss[3][f];
        float qt = sq[0][f] + sq[1][f] + sq[2][f] + sq[3][f];
        atomicAdd(&S[f], (double)st);
        atomicAdd(&Q[f], (double)qt);
    }
}

__global__ void bn_apply(const float* __restrict__ Y, const double* __restrict__ S,
                         const double* __restrict__ Q, const float* __restrict__ gamma,
                         const float* __restrict__ beta, float* __restrict__ H) {
    int i = blockIdx.x * blockDim.x + threadIdx.x;
    if (i >= NN * DD) return;
    int f = i % DD;
    double mu = S[f] / (double)NN;
    double var = Q[f] / (double)NN - mu * mu;
    float inv = rsqrtf((float)var + 1e-5f);
    float v = gamma[f] * ((Y[i] - (float)mu) * inv) + beta[f];
    H[i] = fmaxf(v, 0.f);
}

// ---------------- pooling ----------------
__global__ void pool_k(const int* __restrict__ batch, const float* __restrict__ H,
                       float* __restrict__ pool) {
    int i = blockIdx.x * blockDim.x + threadIdx.x;
    if (i >= NN * DD) return;
    int n = i / DD, f = i % DD;
    atomicAdd(&pool[batch[n] * DD + f], H[i]);
}

// ---------------- launch ----------------
static inline void tgemm(const float* A, int lda, long sA, const float* B, int ldb, long sB,
                         float* C, int ldc, long sC, int M, int N, int K, const float* bias,
                         const float* addC, int ldadd, int act, int nz) {
    dim3 grid((N + 63) / 64, (M + 127) / 128, nz);
    tgemm_kernel<<<grid, 256, SMEM_BYTES>>>(A, lda, sA, B, ldb, sB, C, ldc, sC, M, N, K, bias,
                                            addC, ldadd, act);
}

extern "C" void kernel_launch(void* const* d_in, const int* in_sizes, int n_in,
                              void* d_out, int out_size) {
    const int* x = (const int*)d_in[0];
    const int* ei = (const int*)d_in[1];
    const int* ea = (const int*)d_in[2];
    const int* batch = (const int*)d_in[3];
    const float* node_emb = (const float*)d_in[4];
    const float* edge_emb = (const float*)d_in[5];
    const float* We = (const float*)d_in[6];
    const float* be = (const float*)d_in[7];
    const float* Wpre = (const float*)d_in[8];
    const float* bpre = (const float*)d_in[9];
    const float* Wpost = (const float*)d_in[10];
    const float* bpost = (const float*)d_in[11];
    const float* Wlin = (const float*)d_in[12];
    const float* blin = (const float*)d_in[13];
    const float* gamma = (const float*)d_in[14];
    const float* beta = (const float*)d_in[15];
    const float* W1 = (const float*)d_in[16];
    const float* b1 = (const float*)d_in[17];
    const float* W2 = (const float*)d_in[18];
    const float* b2 = (const float*)d_in[19];
    const float* W3 = (const float*)d_in[20];
    const float* b3 = (const float*)d_in[21];
    float* out = (float*)d_out;

    cudaFuncSetAttribute(tgemm_kernel, cudaFuncAttributeMaxDynamicSharedMemorySize, SMEM_BYTES);

    float *H, *CAB, *AGG, *G, *Z, *Y, *amp, *invamp, *Wcat, *Etab, *WG, *pool, *z1, *z2;
    int *deg, *rowptr, *csr, *bsum, *boffs;
    double *bnS, *bnQ;
    cudaGetSymbolAddress((void**)&H, g_H);
    cudaGetSymbolAddress((void**)&CAB, g_CAB);
    cudaGetSymbolAddress((void**)&AGG, g_AGG);
    cudaGetSymbolAddress((void**)&G, g_G);
    cudaGetSymbolAddress((void**)&Z, g_Z);
    cudaGetSymbolAddress((void**)&Y, g_Y);
    cudaGetSymbolAddress((void**)&amp, g_amp);
    cudaGetSymbolAddress((void**)&invamp, g_invamp);
    cudaGetSymbolAddress((void**)&deg, g_deg);
    cudaGetSymbolAddress((void**)&rowptr, g_rowptr);
    cudaGetSymbolAddress((void**)&csr, g_csr);
    cudaGetSymbolAddress((void**)&bsum, g_bsum);
    cudaGetSymbolAddress((void**)&boffs, g_boffs);
    cudaGetSymbolAddress((void**)&Wcat, g_Wcat);
    cudaGetSymbolAddress((void**)&Etab, g_Etab);
    cudaGetSymbolAddress((void**)&WG, g_WG);
    cudaGetSymbolAddress((void**)&bnS, g_bnS);
    cudaGetSymbolAddress((void**)&bnQ, g_bnQ);
    cudaGetSymbolAddress((void**)&pool, g_pool);
    cudaGetSymbolAddress((void**)&z1, g_z1);
    cudaGetSymbolAddress((void**)&z2, g_z2);
    int* cursor = deg + NN;

    // ---- launch index 3 must be the CAB GEMM (ncu capture slot) ----
    embed_k<<<(NN * DD + 255) / 256, 256>>>(x, node_emb, H);              // 0
    prep_wcat<<<(NL * 75 * 750 + 255) / 256, 256>>>(Wpre, Wcat);          // 1
    prep_w0<<<(NL * 75 * 75 + 255) / 256, 256>>>(Wpost, Wlin, Wcat);      // 2
    // 3: layer-0 CAB GEMM  [NN,75]x[75,825]
    tgemm(H, 75, 0, Wcat, 825, 0, CAB, 825, 0, NN, 825, 75, nullptr, nullptr, 0, 0, 1);
    prep_wg<<<(NL * TW * 300 * 45 + 255) / 256, 256>>>(Wpost, WG);        // 4

    // ---- graph structure prep (all before pna_agg) ----
    zero_i<<<(2 * NN + 255) / 256, 256>>>(deg, 2 * NN);
    hist_k<<<(NE + 255) / 256, 256>>>(ei, deg);
    int nchunks = (NN + 511) / 512;
    scan_chunks<<<nchunks, 512>>>(deg, rowptr, bsum, NN);
    scan_sums<<<1, 128>>>(bsum, boffs, nchunks);
    scan_add<<<(NN + 255) / 256, 256>>>(rowptr, boffs);
    fill_csr<<<(NE + 255) / 256, 256>>>(ei, ea, rowptr, cursor, csr);
    amp_k<<<(NN + 255) / 256, 256>>>(rowptr, amp, invamp);
    prep_etab<<<dim3(4, NL), 384>>>(edge_emb, We, be, Wpre, bpre, Etab);

    // ---- layers ----
    for (int l = 0; l < NL; l++) {
        if (l > 0) {
            tgemm(H, 75, 0, Wcat + l * 75 * 825, 825, 0, CAB, 825, 0, NN, 825, 75,
                  nullptr, nullptr, 0, 0, 1);
        }
        pna_agg<<<NN, 384>>>(CAB, Etab + l * 4 * 375, rowptr, csr, AGG);
        tgemm(AGG, 1500, 300, WG + l * TW * 300 * 45, 45, (long)300 * 45, G, 225, 45,
              NN, 45, 300, nullptr, nullptr, 0, 0, TW);
        combine_k<<<(NN * DD + 255) / 256, 256>>>(G, amp, invamp, bpost + l * TW * FO, Z);
        tgemm(Z, 75, 0, Wlin + l * 5625, 75, 0, Y, 75, 0, NN, 75, 75,
              blin + l * 75, CAB + 750, 825, 0, 1);
        zero_d75<<<1, 128>>>(bnS, bnQ);
        bn_stats<<<(NN + 63) / 64, dim3(75, 4)>>>(Y, bnS, bnQ);
        bn_apply<<<(NN * DD + 255) / 256, 256>>>(Y, bnS, bnQ, gamma + l * DD, beta + l * DD, H);
    }

    // ---- pooling + MLP ----
    zero_f<<<(NG * DD + 255) / 256, 256>>>(pool, NG * DD);
    pool_k<<<(NN * DD + 255) / 256, 256>>>(batch, H, pool);
    tgemm(pool, 75, 0, W1, 50, 0, z1, 50, 0, NG, 50, 75, b1, nullptr, 0, 1, 1);
    tgemm(z1, 50, 0, W2, 25, 0, z2, 25, 0, NG, 25, 50, b2, nullptr, 0, 1, 1);
    tgemm(z2, 25, 0, W3, 1, 0, out, 1, 0, NG, 1, 25, b3, nullptr, 0, 0, 1);
}

// round 9
// speedup vs baseline: 1.7496x; 1.1935x over previous
#include <cuda_runtime.h>
#include <mma.h>
#include <math.h>
#include <cstdint>
#include <cuda_bf16.h>

using namespace nvcuda;

#define NN 50000
#define NE 150000
#define NG 2000
#define DD 75
#define TW 5
#define FO 15
#define NL 4
#define AVGLOG 1.1308269950720914f

typedef __nv_bfloat16 bf16;

// ---------------- scratch (device globals; no allocs) ----------------
__device__ bf16  g_Hh[NN * 80];
__device__ bf16  g_Hl[NN * 80];
__device__ float g_CAB[NN * 825];        // fp32: [A(375) | B(375) | H@W0(75)]
__device__ bf16  g_AGGh[NN * 1520];      // [N][T][304] padded towers
__device__ bf16  g_AGGl[NN * 1520];
__device__ float g_G[NN * 225];
__device__ bf16  g_Zh[NN * 80];
__device__ bf16  g_Zl[NN * 80];
__device__ float g_Y[NN * DD];
__device__ float g_amp[NN];
__device__ float g_invamp[NN];
__device__ int   g_deg[NN * 2];
__device__ int   g_rowptr[NN + 1];
__device__ int   g_csr[NE];
__device__ int   g_bsum[256];
__device__ int   g_boffs[256];
__device__ bf16  g_Wcath[NL * 75 * 826];
__device__ bf16  g_Wcatl[NL * 75 * 826];
__device__ float g_Etab[NL * 4 * 375];
__device__ bf16  g_WGh[NL * TW * 300 * 46];
__device__ bf16  g_WGl[NL * TW * 300 * 46];
__device__ bf16  g_Wlinh[NL * 75 * 76];
__device__ bf16  g_Wlinl[NL * 75 * 76];
__device__ double g_bnS[DD];
__device__ double g_bnQ[DD];
__device__ float g_pool[NG * DD];
__device__ float g_z1[NG * 50];
__device__ float g_z2[NG * 25];

__device__ __forceinline__ void bsplit(float v, bf16* h, bf16* l) {
    bf16 hi = __float2bfloat16(v);
    *h = hi;
    *l = __float2bfloat16(v - __bfloat162float(hi));
}

// ---------------- cp.async helpers ----------------
__device__ __forceinline__ void cp4(void* dst_smem, const void* src, bool pred) {
    unsigned d = (unsigned)__cvta_generic_to_shared(dst_smem);
    int sz = pred ? 4 : 0;
    asm volatile("cp.async.ca.shared.global [%0], [%1], 4, %2;\n" ::"r"(d), "l"(src), "r"(sz));
}
#define CP_COMMIT() asm volatile("cp.async.commit_group;\n" ::: "memory")
#define CP_WAIT1() asm volatile("cp.async.wait_group 1;\n" ::: "memory")
#define CP_WAIT0() asm volatile("cp.async.wait_group 0;\n" ::: "memory")

// ---------------- split-bf16 GEMM; operands pre-split into hi/lo planes -------------
// tile 128x64, 256 threads. smem: hi/lo A [2 stages][128*24], hi/lo B [2][16*72]; sC fp32 union.
#define SAS 24
#define SBS 72
#define SA_PLANE (128 * SAS)
#define SB_PLANE (16 * SBS)
#define SMEM_BYTES (128 * 72 * 4)   // sC (36864) > stage buffers (33792)

__global__ __launch_bounds__(256) void tgemm_kernel(
    const bf16* __restrict__ Ah, const bf16* __restrict__ Al, int lda, long sAb,
    const bf16* __restrict__ Bh, const bf16* __restrict__ Bl, int ldb, long sBb,
    float* __restrict__ C, int ldc, long sCb,
    int M, int N, int K,
    const float* __restrict__ bias,
    const float* __restrict__ addC, int ldadd,
    int act) {
    extern __shared__ char smem_raw[];
    bf16* bb = (bf16*)smem_raw;
    bf16* sAh[2] = {bb, bb + SA_PLANE};
    bf16* sAl[2] = {bb + 2 * SA_PLANE, bb + 3 * SA_PLANE};
    bf16* sBh[2] = {bb + 4 * SA_PLANE, bb + 4 * SA_PLANE + SB_PLANE};
    bf16* sBl[2] = {bb + 4 * SA_PLANE + 2 * SB_PLANE, bb + 4 * SA_PLANE + 3 * SB_PLANE};
    float* sC = (float*)smem_raw;

    const bf16* Abh = Ah + (long)blockIdx.z * sAb;
    const bf16* Abl = Al + (long)blockIdx.z * sAb;
    const bf16* Bbh = Bh + (long)blockIdx.z * sBb;
    const bf16* Bbl = Bl + (long)blockIdx.z * sBb;
    float* Cb = C + (long)blockIdx.z * sCb;
    int m0 = blockIdx.y * 128, n0 = blockIdx.x * 64;
    int tid = threadIdx.x;
    int warp = tid >> 5;
    int wm = (warp & 3) * 32;
    int wn = (warp >> 2) * 32;
    int numK = (K + 15) / 16;

    wmma::fragment<wmma::accumulator, 16, 16, 16, float> acc[2][2];
#pragma unroll
    for (int i = 0; i < 2; i++)
#pragma unroll
        for (int j = 0; j < 2; j++) wmma::fill_fragment(acc[i][j], 0.f);

    auto load_stage = [&](int st, int k0) {
        // A: 128x16 per plane; pairs (u32). k-overreads land in zeroed pad (lda padded).
#pragma unroll
        for (int u = 0; u < 8; u++) {
            int i = tid + u * 256;           // 0..2047
            int pl = i >> 10, idx = i & 1023;
            int r = idx >> 3, c2 = idx & 7;
            int gm = m0 + r;
            bool p = gm < M;
            const bf16* base = pl ? Abl : Abh;
            const bf16* src = base + (long)gm * lda + k0 + c2 * 2;
            bf16* dst = (pl ? sAl[st] : sAh[st]) + r * SAS + c2 * 2;
            cp4(dst, p ? src : base, p);
        }
        // B: 16x64 per plane; pairs along n (ldb even, pads zeroed).
#pragma unroll
        for (int u = 0; u < 4; u++) {
            int i = tid + u * 256;           // 0..1023
            int pl = i >> 9, idx = i & 511;
            int r = idx >> 5, c2 = idx & 31;
            int gk = k0 + r, gn = n0 + c2 * 2;
            bool p = (gk < K) && (gn < N);
            const bf16* base = pl ? Bbl : Bbh;
            const bf16* src = base + (long)gk * ldb + gn;
            bf16* dst = (pl ? sBl[st] : sBh[st]) + r * SBS + c2 * 2;
            cp4(dst, p ? src : base, p);
        }
    };

    load_stage(0, 0);
    CP_COMMIT();

    for (int kt = 0; kt < numK; kt++) {
        int st = kt & 1;
        if (kt + 1 < numK) {
            load_stage(st ^ 1, (kt + 1) * 16);
            CP_COMMIT();
            CP_WAIT1();
        } else {
            CP_WAIT0();
        }
        __syncthreads();

        wmma::fragment<wmma::matrix_a, 16, 16, 16, bf16, wmma::row_major> ah[2], al[2];
        wmma::fragment<wmma::matrix_b, 16, 16, 16, bf16, wmma::row_major> bh[2], bl[2];
#pragma unroll
        for (int i = 0; i < 2; i++) {
            wmma::load_matrix_sync(ah[i], &sAh[st][(wm + 16 * i) * SAS], SAS);
            wmma::load_matrix_sync(al[i], &sAl[st][(wm + 16 * i) * SAS], SAS);
        }
#pragma unroll
        for (int j = 0; j < 2; j++) {
            wmma::load_matrix_sync(bh[j], &sBh[st][wn + 16 * j], SBS);
            wmma::load_matrix_sync(bl[j], &sBl[st][wn + 16 * j], SBS);
        }
#pragma unroll
        for (int i = 0; i < 2; i++)
#pragma unroll
            for (int j = 0; j < 2; j++) {
                wmma::mma_sync(acc[i][j], al[i], bh[j], acc[i][j]);
                wmma::mma_sync(acc[i][j], ah[i], bl[j], acc[i][j]);
                wmma::mma_sync(acc[i][j], ah[i], bh[j], acc[i][j]);
            }
        __syncthreads();
    }

#pragma unroll
    for (int i = 0; i < 2; i++)
#pragma unroll
        for (int j = 0; j < 2; j++)
            wmma::store_matrix_sync(&sC[(wm + 16 * i) * 72 + wn + 16 * j], acc[i][j], 72,
                                    wmma::mem_row_major);
    __syncthreads();
    for (int i = tid; i < 128 * 64; i += 256) {
        int r = i >> 6, c = i & 63;
        int gm = m0 + r, gn = n0 + c;
        if (gm < M && gn < N) {
            float v = sC[r * 72 + c];
            if (bias) v += bias[gn];
            if (addC) v += addC[(long)gm * ldadd + gn];
            if (act) v = fmaxf(v, 0.f);
            Cb[(long)gm * ldc + gn] = v;
        }
    }
}

// ---------------- tiny fp32 GEMM for the final MLP ----------------
__global__ void sgemm_s(const float* __restrict__ A, int lda, const float* __restrict__ B,
                        int ldb, float* __restrict__ C, int ldc, int M, int N, int K,
                        const float* __restrict__ bias, int act) {
    int i = blockIdx.x * blockDim.x + threadIdx.x;
    if (i >= M * N) return;
    int m = i / N, n = i % N;
    float s = bias ? bias[n] : 0.f;
    for (int k = 0; k < K; k++) s += A[m * lda + k] * B[k * ldb + n];
    if (act) s = fmaxf(s, 0.f);
    C[m * ldc + n] = s;
}

// ---------------- small utility kernels ----------------
__global__ void zero_i(int* p, int n) {
    int i = blockIdx.x * blockDim.x + threadIdx.x;
    if (i < n) p[i] = 0;
}
__global__ void zero_f(float* p, int n) {
    int i = blockIdx.x * blockDim.x + threadIdx.x;
    if (i < n) p[i] = 0.f;
}
__global__ void zero_d75(double* a, double* b) {
    int i = threadIdx.x;
    if (i < DD) { a[i] = 0.0; b[i] = 0.0; }
}

__global__ void hist_k(const int* __restrict__ ei, int* __restrict__ deg) {
    int e = blockIdx.x * blockDim.x + threadIdx.x;
    if (e < NE) atomicAdd(&deg[ei[NE + e]], 1);
}

__global__ void scan_chunks(const int* __restrict__ in, int* __restrict__ out,
                            int* __restrict__ bsum, int n) {
    __shared__ int s[512];
    int b = blockIdx.x, t = threadIdx.x;
    int idx = b * 512 + t;
    int v = (idx < n) ? in[idx] : 0;
    s[t] = v;
    __syncthreads();
    for (int off = 1; off < 512; off <<= 1) {
        int x = (t >= off) ? s[t - off] : 0;
        __syncthreads();
        s[t] += x;
        __syncthreads();
    }
    if (idx < n) out[idx] = s[t] - v;
    if (t == 511) bsum[b] = s[511];
}
__global__ void scan_sums(const int* __restrict__ sums, int* __restrict__ offs, int nb) {
    __shared__ int s[128];
    int t = threadIdx.x;
    int v = (t < nb) ? sums[t] : 0;
    s[t] = v;
    __syncthreads();
    for (int off = 1; off < 128; off <<= 1) {
        int x = (t >= off) ? s[t - off] : 0;
        __syncthreads();
        s[t] += x;
        __syncthreads();
    }
    if (t < nb) offs[t] = s[t] - v;
}
__global__ void scan_add(int* __restrict__ rowptr, const int* __restrict__ offs) {
    int i = blockIdx.x * blockDim.x + threadIdx.x;
    if (i < NN) rowptr[i] += offs[i >> 9];
    if (i == 0) rowptr[NN] = NE;
}

__global__ void fill_csr(const int* __restrict__ ei, const int* __restrict__ ea,
                         const int* __restrict__ rowptr, int* __restrict__ cursor,
                         int* __restrict__ csr) {
    int e = blockIdx.x * blockDim.x + threadIdx.x;
    if (e >= NE) return;
    int d = ei[NE + e];
    int pos = rowptr[d] + atomicAdd(&cursor[d], 1);
    csr[pos] = ei[e] | (ea[e] << 20);
}

__global__ void amp_k(const int* __restrict__ rowptr, float* __restrict__ amp,
                      float* __restrict__ invamp) {
    int i = blockIdx.x * blockDim.x + threadIdx.x;
    if (i >= NN) return;
    int dg = rowptr[i + 1] - rowptr[i];
    float a = logf((float)max(dg, 1) + 1.f) / AVGLOG;
    amp[i] = a;
    invamp[i] = 1.f / a;
}

// writes H hi/lo planes (ld 80, cols 75..79 zero)
__global__ void embed_k(const int* __restrict__ x, const float* __restrict__ emb,
                        bf16* __restrict__ Hh, bf16* __restrict__ Hl) {
    int i = blockIdx.x * blockDim.x + threadIdx.x;
    if (i >= NN * 80) return;
    int n = i / 80, f = i % 80;
    float v = (f < 75) ? emb[x[n] * 75 + f] : 0.f;
    bsplit(v, &Hh[i], &Hl[i]);
}

// ---------------- weight prep (bf16 planes) ----------------
__global__ void prep_wcat(const float* __restrict__ Wpre, bf16* __restrict__ Wh,
                          bf16* __restrict__ Wl) {
    int i = blockIdx.x * blockDim.x + threadIdx.x;
    if (i >= NL * 75 * 826) return;
    int l = i / (75 * 826), r = i % (75 * 826);
    int k = r / 826, j = r % 826;
    if (j >= 750 && j < 825) return;  // W0 region written by prep_w0
    float v = 0.f;
    if (j < 750) {
        int part = j / 375, j2 = j % 375;
        int t = j2 / 75, f = j2 % 75;
        int c = part * 75 + k;
        v = Wpre[((l * TW + t) * 225 + c) * 75 + f];
    }
    bsplit(v, &Wh[(l * 75 + k) * 826 + j], &Wl[(l * 75 + k) * 826 + j]);
}

__global__ void prep_w0(const float* __restrict__ Wpost, const float* __restrict__ Wlin,
                        bf16* __restrict__ Wh, bf16* __restrict__ Wl) {
    int i = blockIdx.x * blockDim.x + threadIdx.x;
    if (i >= NL * 75 * 75) return;
    int l = i / 5625, r = i % 5625;
    int k = r / 75, c = r % 75;
    float s = 0.f;
    for (int d = 0; d < 75; d++) {
        int t = d / 15, f = d % 15;
        s += Wpost[((l * TW + t) * 975 + k) * 15 + f] * Wlin[l * 5625 + d * 75 + c];
    }
    int o = (l * 75 + k) * 826 + 750 + c;
    bsplit(s, &Wh[o], &Wl[o]);
}

__global__ void prep_etab(const float* __restrict__ edge_emb, const float* __restrict__ We,
                          const float* __restrict__ be, const float* __restrict__ Wpre,
                          const float* __restrict__ bpre, float* __restrict__ Etab) {
    int a = blockIdx.x, l = blockIdx.y;
    __shared__ float ev[75];
    int t0 = threadIdx.x;
    if (t0 < 75) {
        float s = be[l * 75 + t0];
        for (int c = 0; c < 50; c++) s += edge_emb[a * 50 + c] * We[(l * 50 + c) * 75 + t0];
        ev[t0] = s;
    }
    __syncthreads();
    for (int j = t0; j < 375; j += blockDim.x) {
        int t = j / 75, f = j % 75;
        float s = bpre[(l * TW + t) * 75 + f];
        for (int d = 0; d < 75; d++)
            s += ev[d] * Wpre[((l * TW + t) * 225 + 150 + d) * 75 + f];
        Etab[(l * 4 + a) * 375 + j] = s;
    }
}

__global__ void prep_wg(const float* __restrict__ Wpost, bf16* __restrict__ Wh,
                        bf16* __restrict__ Wl) {
    int i = blockIdx.x * blockDim.x + threadIdx.x;
    if (i >= NL * TW * 300 * 46) return;
    int lt = i / (300 * 46), r = i % (300 * 46);
    int c = r / 46, col = r % 46;
    float v = 0.f;
    if (col < 45) {
        int g = col / 15, f = col % 15;
        v = Wpost[(lt * 975 + 75 + g * 300 + c) * 15 + f];
    }
    int o = (lt * 300 + c) * 46 + col;
    bsplit(v, &Wh[o], &Wl[o]);
}

__global__ void prep_wlin(const float* __restrict__ Wlin, bf16* __restrict__ Wh,
                          bf16* __restrict__ Wl) {
    int i = blockIdx.x * blockDim.x + threadIdx.x;
    if (i >= NL * 75 * 76) return;
    int l = i / (75 * 76), r = i % (75 * 76);
    int k = r / 76, c = r % 76;
    float v = (c < 75) ? Wlin[l * 5625 + k * 75 + c] : 0.f;
    int o = (l * 75 + k) * 76 + c;
    bsplit(v, &Wh[o], &Wl[o]);
}

// ---------------- PNA aggregation: writes AGG hi/lo planes [N][T][304] --------------
__global__ __launch_bounds__(384) void pna_agg(const float* __restrict__ CAB,
                                               const float* __restrict__ Etab,
                                               const int* __restrict__ rowptr,
                                               const int* __restrict__ csr,
                                               bf16* __restrict__ AGGh,
                                               bf16* __restrict__ AGGl) {
    int n = blockIdx.x;
    int j = threadIdx.x;
    if (j >= 375) return;
    if (j < 20) {  // zero tower pads (cols 300..303 of each tower)
        int o = n * 1520 + (j >> 2) * 304 + 300 + (j & 3);
        AGGh[o] = __float2bfloat16(0.f);
        AGGl[o] = __float2bfloat16(0.f);
    }
    float adst = CAB[(long)n * 825 + j];
    int beg = rowptr[n], end = rowptr[n + 1];
    float s = 0.f, sq = 0.f, mn = 3.4e38f, mx = -3.4e38f;
    int e = beg;
    for (; e + 1 < end; e += 2) {
        int p0 = csr[e], p1 = csr[e + 1];
        float b0 = CAB[(long)(p0 & 0xFFFFF) * 825 + 375 + j];
        float b1 = CAB[(long)(p1 & 0xFFFFF) * 825 + 375 + j];
        float v0 = adst + b0 + Etab[(p0 >> 20) * 375 + j];
        float v1 = adst + b1 + Etab[(p1 >> 20) * 375 + j];
        s += v0 + v1;
        sq += v0 * v0 + v1 * v1;
        mn = fminf(mn, fminf(v0, v1));
        mx = fmaxf(mx, fmaxf(v0, v1));
    }
    if (e < end) {
        int p0 = csr[e];
        float v0 = adst + CAB[(long)(p0 & 0xFFFFF) * 825 + 375 + j] + Etab[(p0 >> 20) * 375 + j];
        s += v0;
        sq += v0 * v0;
        mn = fminf(mn, v0);
        mx = fmaxf(mx, v0);
    }
    int dg = end - beg;
    float denom = fmaxf((float)dg, 1.f);
    float mean = s / denom, msq = sq / denom;
    float sd = sqrtf(fmaxf(msq - mean * mean, 0.f) + 1e-5f);
    if (dg == 0) { mn = 0.f; mx = 0.f; }
    int t = j / 75, f = j % 75;
    long o = (long)n * 1520 + t * 304;
    bsplit(mean, &AGGh[o + f], &AGGl[o + f]);
    bsplit(mn, &AGGh[o + 75 + f], &AGGl[o + 75 + f]);
    bsplit(mx, &AGGh[o + 150 + f], &AGGl[o + 150 + f]);
    bsplit(sd, &AGGh[o + 225 + f], &AGGl[o + 225 + f]);
}

// ---------------- combine towers + scalers -> Z hi/lo planes ----------------
__global__ void combine_k(const float* __restrict__ G, const float* __restrict__ amp,
                          const float* __restrict__ invamp, const float* __restrict__ bpost,
                          bf16* __restrict__ Zh, bf16* __restrict__ Zl) {
    int i = blockIdx.x * blockDim.x + threadIdx.x;
    if (i >= NN * 80) return;
    int n = i / 80, j = i % 80;
    float v = 0.f;
    if (j < 75) {
        int t = j / 15, f = j % 15;
        const float* g = G + (long)n * 225 + t * 45;
        v = g[f] + amp[n] * g[15 + f] + invamp[n] * g[30 + f] + bpost[t * 15 + f];
    }
    bsplit(v, &Zh[i], &Zl[i]);
}

// ---------------- batchnorm ----------------
__global__ void bn_stats(const float* __restrict__ Y, double* __restrict__ S,
                         double* __restrict__ Q) {
    __shared__ float ss[4][75], sq[4][75];
    int f = threadIdx.x, w = threadIdx.y;
    int base = blockIdx.x * 64;
    float s = 0.f, q = 0.f;
    for (int r = w; r < 64; r += 4) {
        int n = base + r;
        if (n < NN) {
            float v = Y[(long)n * DD + f];
            s += v;
            q += v * v;
        }
    }
    ss[w][f] = s;
    sq[w][f] = q;
    __syncthreads();
    if (w == 0) {
        float st = ss[0][f] + ss[1][f] + ss[2][f] + ss[3][f];
        float qt = sq[0][f] + sq[1][f] + sq[2][f] + sq[3][f];
        atomicAdd(&S[f], (double)st);
        atomicAdd(&Q[f], (double)qt);
    }
}

// BN+ReLU -> H hi/lo planes
__global__ void bn_apply(const float* __restrict__ Y, const double* __restrict__ S,
                         const double* __restrict__ Q, const float* __restrict__ gamma,
                         const float* __restrict__ beta, bf16* __restrict__ Hh,
                         bf16* __restrict__ Hl) {
    int i = blockIdx.x * blockDim.x + threadIdx.x;
    if (i >= NN * 80) return;
    int n = i / 80, f = i % 80;
    float v = 0.f;
    if (f < 75) {
        double mu = S[f] / (double)NN;
        double var = Q[f] / (double)NN - mu * mu;
        float inv = rsqrtf((float)var + 1e-5f);
        v = gamma[f] * ((Y[(long)n * DD + f] - (float)mu) * inv) + beta[f];
        v = fmaxf(v, 0.f);
    }
    bsplit(v, &Hh[i], &Hl[i]);
}

// ---------------- pooling (reconstruct fp32 from planes) ----------------
__global__ void pool_k(const int* __restrict__ batch, const bf16* __restrict__ Hh,
                       const bf16* __restrict__ Hl, float* __restrict__ pool) {
    int i = blockIdx.x * blockDim.x + threadIdx.x;
    if (i >= NN * DD) return;
    int n = i / DD, f = i % DD;
    float v = __bfloat162float(Hh[n * 80 + f]) + __bfloat162float(Hl[n * 80 + f]);
    atomicAdd(&pool[batch[n] * DD + f], v);
}

// ---------------- launch ----------------
static inline void tgemm(const bf16* Ah, const bf16* Al, int lda, long sA, const bf16* Bh,
                         const bf16* Bl, int ldb, long sB, float* C, int ldc, long sC, int M,
                         int N, int K, const float* bias, const float* addC, int ldadd, int act,
                         int nz) {
    dim3 grid((N + 63) / 64, (M + 127) / 128, nz);
    tgemm_kernel<<<grid, 256, SMEM_BYTES>>>(Ah, Al, lda, sA, Bh, Bl, ldb, sB, C, ldc, sC, M, N,
                                            K, bias, addC, ldadd, act);
}

extern "C" void kernel_launch(void* const* d_in, const int* in_sizes, int n_in,
                              void* d_out, int out_size) {
    const int* x = (const int*)d_in[0];
    const int* ei = (const int*)d_in[1];
    const int* ea = (const int*)d_in[2];
    const int* batch = (const int*)d_in[3];
    const float* node_emb = (const float*)d_in[4];
    const float* edge_emb = (const float*)d_in[5];
    const float* We = (const float*)d_in[6];
    const float* be = (const float*)d_in[7];
    const float* Wpre = (const float*)d_in[8];
    const float* bpre = (const float*)d_in[9];
    const float* Wpost = (const float*)d_in[10];
    const float* bpost = (const float*)d_in[11];
    const float* Wlin = (const float*)d_in[12];
    const float* blin = (const float*)d_in[13];
    const float* gamma = (const float*)d_in[14];
    const float* beta = (const float*)d_in[15];
    const float* W1 = (const float*)d_in[16];
    const float* b1 = (const float*)d_in[17];
    const float* W2 = (const float*)d_in[18];
    const float* b2 = (const float*)d_in[19];
    const float* W3 = (const float*)d_in[20];
    const float* b3 = (const float*)d_in[21];
    float* out = (float*)d_out;

    cudaFuncSetAttribute(tgemm_kernel, cudaFuncAttributeMaxDynamicSharedMemorySize, SMEM_BYTES);

    bf16 *Hh, *Hl, *AGGh, *AGGl, *Zh, *Zl, *Wcath, *Wcatl, *WGh, *WGl, *Wlinh, *Wlinl;
    float *CAB, *G, *Y, *amp, *invamp, *Etab, *pool, *z1, *z2;
    int *deg, *rowptr, *csr, *bsum, *boffs;
    double *bnS, *bnQ;
    cudaGetSymbolAddress((void**)&Hh, g_Hh);
    cudaGetSymbolAddress((void**)&Hl, g_Hl);
    cudaGetSymbolAddress((void**)&CAB, g_CAB);
    cudaGetSymbolAddress((void**)&AGGh, g_AGGh);
    cudaGetSymbolAddress((void**)&AGGl, g_AGGl);
    cudaGetSymbolAddress((void**)&G, g_G);
    cudaGetSymbolAddress((void**)&Zh, g_Zh);
    cudaGetSymbolAddress((void**)&Zl, g_Zl);
    cudaGetSymbolAddress((void**)&Y, g_Y);
    cudaGetSymbolAddress((void**)&amp, g_amp);
    cudaGetSymbolAddress((void**)&invamp, g_invamp);
    cudaGetSymbolAddress((void**)&deg, g_deg);
    cudaGetSymbolAddress((void**)&rowptr, g_rowptr);
    cudaGetSymbolAddress((void**)&csr, g_csr);
    cudaGetSymbolAddress((void**)&bsum, g_bsum);
    cudaGetSymbolAddress((void**)&boffs, g_boffs);
    cudaGetSymbolAddress((void**)&Wcath, g_Wcath);
    cudaGetSymbolAddress((void**)&Wcatl, g_Wcatl);
    cudaGetSymbolAddress((void**)&Etab, g_Etab);
    cudaGetSymbolAddress((void**)&WGh, g_WGh);
    cudaGetSymbolAddress((void**)&WGl, g_WGl);
    cudaGetSymbolAddress((void**)&Wlinh, g_Wlinh);
    cudaGetSymbolAddress((void**)&Wlinl, g_Wlinl);
    cudaGetSymbolAddress((void**)&bnS, g_bnS);
    cudaGetSymbolAddress((void**)&bnQ, g_bnQ);
    cudaGetSymbolAddress((void**)&pool, g_pool);
    cudaGetSymbolAddress((void**)&z1, g_z1);
    cudaGetSymbolAddress((void**)&z2, g_z2);
    int* cursor = deg + NN;

    // ---- launch index 3 = layer-0 CAB GEMM (ncu capture slot) ----
    embed_k<<<(NN * 80 + 255) / 256, 256>>>(x, node_emb, Hh, Hl);               // 0
    prep_wcat<<<(NL * 75 * 826 + 255) / 256, 256>>>(Wpre, Wcath, Wcatl);        // 1
    prep_w0<<<(NL * 75 * 75 + 255) / 256, 256>>>(Wpost, Wlin, Wcath, Wcatl);    // 2
    tgemm(Hh, Hl, 80, 0, Wcath, Wcatl, 826, 0, CAB, 825, 0, NN, 825, 75,        // 3
          nullptr, nullptr, 0, 0, 1);
    prep_wg<<<(NL * TW * 300 * 46 + 255) / 256, 256>>>(Wpost, WGh, WGl);        // 4
    prep_wlin<<<(NL * 75 * 76 + 255) / 256, 256>>>(Wlin, Wlinh, Wlinl);         // 5

    // ---- graph structure prep ----
    zero_i<<<(2 * NN + 255) / 256, 256>>>(deg, 2 * NN);
    hist_k<<<(NE + 255) / 256, 256>>>(ei, deg);
    int nchunks = (NN + 511) / 512;
    scan_chunks<<<nchunks, 512>>>(deg, rowptr, bsum, NN);
    scan_sums<<<1, 128>>>(bsum, boffs, nchunks);
    scan_add<<<(NN + 255) / 256, 256>>>(rowptr, boffs);
    fill_csr<<<(NE + 255) / 256, 256>>>(ei, ea, rowptr, cursor, csr);
    amp_k<<<(NN + 255) / 256, 256>>>(rowptr, amp, invamp);
    prep_etab<<<dim3(4, NL), 384>>>(edge_emb, We, be, Wpre, bpre, Etab);

    // ---- layers ----
    for (int l = 0; l < NL; l++) {
        if (l > 0) {
            tgemm(Hh, Hl, 80, 0, Wcath + l * 75 * 826, Wcatl + l * 75 * 826, 826, 0, CAB, 825,
                  0, NN, 825, 75, nullptr, nullptr, 0, 0, 1);
        }
        pna_agg<<<NN, 384>>>(CAB, Etab + l * 4 * 375, rowptr, csr, AGGh, AGGl);
        // G[t] = AGG[:,t] @ WG[l][t]   (A slice stride 304 within padded row of 1520)
        tgemm(AGGh, AGGl, 1520, 304, WGh + l * TW * 300 * 46, WGl + l * TW * 300 * 46, 46,
              (long)300 * 46, G, 225, 45, NN, 45, 300, nullptr, nullptr, 0, 0, TW);
        combine_k<<<(NN * 80 + 255) / 256, 256>>>(G, amp, invamp, bpost + l * TW * FO, Zh, Zl);
        // Y = Z @ Wlin + (H@W0 from CAB[:,750:]) + blin
        tgemm(Zh, Zl, 80, 0, Wlinh + l * 75 * 76, Wlinl + l * 75 * 76, 76, 0, Y, 75, 0, NN, 75,
              75, blin + l * 75, CAB + 750, 825, 0, 1);
        zero_d75<<<1, 128>>>(bnS, bnQ);
        bn_stats<<<(NN + 63) / 64, dim3(75, 4)>>>(Y, bnS, bnQ);
        bn_apply<<<(NN * 80 + 255) / 256, 256>>>(Y, bnS, bnQ, gamma + l * DD, beta + l * DD,
                                                 Hh, Hl);
    }

    // ---- pooling + MLP (tiny, fp32 SIMT) ----
    zero_f<<<(NG * DD + 255) / 256, 256>>>(pool, NG * DD);
    pool_k<<<(NN * DD + 255) / 256, 256>>>(batch, Hh, Hl, pool);
    sgemm_s<<<(NG * 50 + 255) / 256, 256>>>(pool, 75, W1, 50, z1, 50, NG, 50, 75, b1, 1);
    sgemm_s<<<(NG * 25 + 255) / 256, 256>>>(z1, 50, W2, 25, z2, 25, NG, 25, 50, b2, 1);
    sgemm_s<<<(NG * 1 + 255) / 256, 256>>>(z2, 25, W3, 1, out, 1, NG, 1, 25, b3, 0);
}

// round 11
// speedup vs baseline: 1.9771x; 1.1300x over previous
#include <cuda_runtime.h>
#include <mma.h>
#include <math.h>
#include <cstdint>
#include <cuda_bf16.h>

using namespace nvcuda;

#define NN 50000
#define NE 150000
#define NG 2000
#define DD 75
#define TW 5
#define FO 15
#define NL 4
#define AVGLOG 1.1308269950720914f
#define CLD 828   // CAB row stride (multiple of 4 for wmma direct store)

typedef __nv_bfloat16 bf16;

// ---------------- scratch (device globals; no allocs) ----------------
__device__ __align__(256) bf16  g_Hh[NN * 80];
__device__ __align__(256) bf16  g_Hl[NN * 80];
__device__ __align__(256) float g_CAB[NN * CLD];     // fp32: [A(375) | B(375) | H@W0(75) | pad]
__device__ __align__(256) bf16  g_AGGh[NN * 1520];   // [N][T][304] padded towers
__device__ __align__(256) bf16  g_AGGl[NN * 1520];
__device__ float g_G[NN * 225];
__device__ __align__(256) bf16  g_Zh[NN * 80];
__device__ __align__(256) bf16  g_Zl[NN * 80];
__device__ float g_Y[NN * DD];
__device__ float g_amp[NN];
__device__ float g_invamp[NN];
__device__ int   g_deg[NN * 2];
__device__ int   g_rowptr[NN + 1];
__device__ int   g_csr[NE];
__device__ int   g_bsum[256];
__device__ int   g_boffs[256];
__device__ __align__(256) bf16  g_Wcath[NL * 75 * 832];
__device__ __align__(256) bf16  g_Wcatl[NL * 75 * 832];
__device__ float g_Etab[NL * 4 * 375];
__device__ __align__(256) bf16  g_WGh[NL * TW * 300 * 48];
__device__ __align__(256) bf16  g_WGl[NL * TW * 300 * 48];
__device__ __align__(256) bf16  g_Wlinh[NL * 75 * 80];
__device__ __align__(256) bf16  g_Wlinl[NL * 75 * 80];
__device__ double g_bnS[DD];
__device__ double g_bnQ[DD];
__device__ float g_pool[NG * DD];
__device__ float g_z1[NG * 50];
__device__ float g_z2[NG * 25];

__device__ __forceinline__ void bsplit(float v, bf16* h, bf16* l) {
    bf16 hi = __float2bfloat16(v);
    *h = hi;
    *l = __float2bfloat16(v - __bfloat162float(hi));
}

// ---------------- cp.async helpers ----------------
__device__ __forceinline__ void cp16(unsigned dst, const void* src, bool pred) {
    int sz = pred ? 16 : 0;
    asm volatile("cp.async.cg.shared.global [%0], [%1], 16, %2;\n" ::"r"(dst), "l"(src),
                 "r"(sz));
}
#define CP_COMMIT() asm volatile("cp.async.commit_group;\n" ::: "memory")
#define CP_WAIT1() asm volatile("cp.async.wait_group 1;\n" ::: "memory")
#define CP_WAIT0() asm volatile("cp.async.wait_group 0;\n" ::: "memory")

// ---------------- split-bf16 GEMM; pre-split hi/lo planes; 16B async loads ----------
// tile 128x64, 256 threads. smem: A hi[2]/lo[2] 128x24, B hi[2]/lo[2] 16x72; sC fp32 union.
#define SAS 24
#define SBS 72
#define SA_PLANE (128 * SAS)
#define SB_PLANE (16 * SBS)
#define SMEM_BYTES (128 * 72 * 4)   // sC (36864) > stages (33792)

__global__ __launch_bounds__(256) void tgemm_kernel(
    const bf16* __restrict__ Ah, const bf16* __restrict__ Al, int lda, long sAb,
    const bf16* __restrict__ Bh, const bf16* __restrict__ Bl, int ldb, long sBb,
    float* __restrict__ C, int ldc, long sCb,
    int M, int N, int K,
    const float* __restrict__ bias,
    const float* __restrict__ addC, int ldadd,
    int act) {
    extern __shared__ char smem_raw[];
    bf16* bb = (bf16*)smem_raw;
    float* sC = (float*)smem_raw;

    const bf16* Abh = Ah + (long)blockIdx.z * sAb;
    const bf16* Abl = Al + (long)blockIdx.z * sAb;
    const bf16* Bbh = Bh + (long)blockIdx.z * sBb;
    const bf16* Bbl = Bl + (long)blockIdx.z * sBb;
    float* Cb = C + (long)blockIdx.z * sCb;
    int m0 = blockIdx.y * 128, n0 = blockIdx.x * 64;
    int tid = threadIdx.x;
    int warp = tid >> 5;
    int wm = (warp & 3) * 32;
    int wn = (warp >> 2) * 32;
    int numK = (K + 15) / 16;

    // ---- precomputed loader state ----
    // A: 512 16B-chunks = 2 planes x 128 rows x 2 chunks; this thread does idx=tid, tid+256
    const bf16* aSrc[2];
    unsigned aDst[2];
    bool aPred[2];
#pragma unroll
    for (int u = 0; u < 2; u++) {
        int idx = tid + u * 256;
        int pl = idx >> 8, rem = idx & 255;
        int r = rem >> 1, ch = rem & 1;
        const bf16* base = pl ? Abl : Abh;
        aPred[u] = (m0 + r) < M;
        aSrc[u] = base + (long)(m0 + r) * lda + ch * 8;
        aDst[u] = (unsigned)__cvta_generic_to_shared(bb + pl * 2 * SA_PLANE + r * SAS + ch * 8);
    }
    // B: 256 chunks = 2 planes x 16 rows x 8 chunks; idx=tid
    int bPl = tid >> 7, bRem = tid & 127;
    int bR = bRem >> 3, bCh = bRem & 7;
    const bf16* bBase = bPl ? Bbl : Bbh;
    bool bPredN = (n0 + bCh * 8) < ldb;   // pad cols [N, ldb) are zeroed
    const bf16* bSrc = bBase + (long)bR * ldb + n0 + bCh * 8;
    unsigned bDst = (unsigned)__cvta_generic_to_shared(bb + 4 * SA_PLANE + bPl * 2 * SB_PLANE +
                                                       bR * SBS + bCh * 8);

    auto load_stage = [&](int st, int k0) {
#pragma unroll
        for (int u = 0; u < 2; u++)
            cp16(aDst[u] + st * SA_PLANE * 2, aPred[u] ? (aSrc[u] + k0) : Abh, aPred[u]);
        bool p = bPredN && (k0 + bR) < K;
        cp16(bDst + st * SB_PLANE * 2, p ? (bSrc + (long)k0 * ldb) : Bbh, p);
    };

    wmma::fragment<wmma::accumulator, 16, 16, 16, float> acc[2][2];
#pragma unroll
    for (int i = 0; i < 2; i++)
#pragma unroll
        for (int j = 0; j < 2; j++) wmma::fill_fragment(acc[i][j], 0.f);

    load_stage(0, 0);
    CP_COMMIT();

    for (int kt = 0; kt < numK; kt++) {
        int st = kt & 1;
        if (kt + 1 < numK) {
            load_stage(st ^ 1, (kt + 1) * 16);
            CP_COMMIT();
            CP_WAIT1();
        } else {
            CP_WAIT0();
        }
        __syncthreads();

        bf16* sAh = bb + st * SA_PLANE;
        bf16* sAl = bb + 2 * SA_PLANE + st * SA_PLANE;
        bf16* sBh = bb + 4 * SA_PLANE + st * SB_PLANE;
        bf16* sBl = bb + 4 * SA_PLANE + 2 * SB_PLANE + st * SB_PLANE;

        wmma::fragment<wmma::matrix_a, 16, 16, 16, bf16, wmma::row_major> ah[2], al[2];
        wmma::fragment<wmma::matrix_b, 16, 16, 16, bf16, wmma::row_major> bh[2], bl[2];
#pragma unroll
        for (int i = 0; i < 2; i++) {
            wmma::load_matrix_sync(ah[i], &sAh[(wm + 16 * i) * SAS], SAS);
            wmma::load_matrix_sync(al[i], &sAl[(wm + 16 * i) * SAS], SAS);
        }
#pragma unroll
        for (int j = 0; j < 2; j++) {
            wmma::load_matrix_sync(bh[j], &sBh[wn + 16 * j], SBS);
            wmma::load_matrix_sync(bl[j], &sBl[wn + 16 * j], SBS);
        }
#pragma unroll
        for (int i = 0; i < 2; i++)
#pragma unroll
            for (int j = 0; j < 2; j++) {
                wmma::mma_sync(acc[i][j], al[i], bh[j], acc[i][j]);
                wmma::mma_sync(acc[i][j], ah[i], bl[j], acc[i][j]);
                wmma::mma_sync(acc[i][j], ah[i], bh[j], acc[i][j]);
            }
        __syncthreads();
    }

    // direct store requires: no epilogue math, full tile, AND ldc multiple of 4 (fp32 wmma req)
    bool direct = (bias == nullptr) && (addC == nullptr) && (act == 0) && ((ldc & 3) == 0) &&
                  (m0 + 128 <= M) && (n0 + 64 <= N);
    if (direct) {
#pragma unroll
        for (int i = 0; i < 2; i++)
#pragma unroll
            for (int j = 0; j < 2; j++)
                wmma::store_matrix_sync(&Cb[(long)(m0 + wm + 16 * i) * ldc + n0 + wn + 16 * j],
                                        acc[i][j], ldc, wmma::mem_row_major);
        return;
    }
#pragma unroll
    for (int i = 0; i < 2; i++)
#pragma unroll
        for (int j = 0; j < 2; j++)
            wmma::store_matrix_sync(&sC[(wm + 16 * i) * 72 + wn + 16 * j], acc[i][j], 72,
                                    wmma::mem_row_major);
    __syncthreads();
    for (int i = tid; i < 128 * 64; i += 256) {
        int r = i >> 6, c = i & 63;
        int gm = m0 + r, gn = n0 + c;
        if (gm < M && gn < N) {
            float v = sC[r * 72 + c];
            if (bias) v += bias[gn];
            if (addC) v += addC[(long)gm * ldadd + gn];
            if (act) v = fmaxf(v, 0.f);
            Cb[(long)gm * ldc + gn] = v;
        }
    }
}

// ---------------- tiny fp32 GEMM for the final MLP ----------------
__global__ void sgemm_s(const float* __restrict__ A, int lda, const float* __restrict__ B,
                        int ldb, float* __restrict__ C, int ldc, int M, int N, int K,
                        const float* __restrict__ bias, int act) {
    int i = blockIdx.x * blockDim.x + threadIdx.x;
    if (i >= M * N) return;
    int m = i / N, n = i % N;
    float s = bias ? bias[n] : 0.f;
    for (int k = 0; k < K; k++) s += A[m * lda + k] * B[k * ldb + n];
    if (act) s = fmaxf(s, 0.f);
    C[m * ldc + n] = s;
}

// ---------------- small utility kernels ----------------
__global__ void zero_i(int* p, int n) {
    int i = blockIdx.x * blockDim.x + threadIdx.x;
    if (i < n) p[i] = 0;
}
__global__ void zero_f(float* p, int n) {
    int i = blockIdx.x * blockDim.x + threadIdx.x;
    if (i < n) p[i] = 0.f;
}
__global__ void zero_d75(double* a, double* b) {
    int i = threadIdx.x;
    if (i < DD) { a[i] = 0.0; b[i] = 0.0; }
}

__global__ void hist_k(const int* __restrict__ ei, int* __restrict__ deg) {
    int e = blockIdx.x * blockDim.x + threadIdx.x;
    if (e < NE) atomicAdd(&deg[ei[NE + e]], 1);
}

__global__ void scan_chunks(const int* __restrict__ in, int* __restrict__ out,
                            int* __restrict__ bsum, int n) {
    __shared__ int s[512];
    int b = blockIdx.x, t = threadIdx.x;
    int idx = b * 512 + t;
    int v = (idx < n) ? in[idx] : 0;
    s[t] = v;
    __syncthreads();
    for (int off = 1; off < 512; off <<= 1) {
        int x = (t >= off) ? s[t - off] : 0;
        __syncthreads();
        s[t] += x;
        __syncthreads();
    }
    if (idx < n) out[idx] = s[t] - v;
    if (t == 511) bsum[b] = s[511];
}
__global__ void scan_sums(const int* __restrict__ sums, int* __restrict__ offs, int nb) {
    __shared__ int s[128];
    int t = threadIdx.x;
    int v = (t < nb) ? sums[t] : 0;
    s[t] = v;
    __syncthreads();
    for (int off = 1; off < 128; off <<= 1) {
        int x = (t >= off) ? s[t - off] : 0;
        __syncthreads();
        s[t] += x;
        __syncthreads();
    }
    if (t < nb) offs[t] = s[t] - v;
}
__global__ void scan_add(int* __restrict__ rowptr, const int* __restrict__ offs) {
    int i = blockIdx.x * blockDim.x + threadIdx.x;
    if (i < NN) rowptr[i] += offs[i >> 9];
    if (i == 0) rowptr[NN] = NE;
}

__global__ void fill_csr(const int* __restrict__ ei, const int* __restrict__ ea,
                         const int* __restrict__ rowptr, int* __restrict__ cursor,
                         int* __restrict__ csr) {
    int e = blockIdx.x * blockDim.x + threadIdx.x;
    if (e >= NE) return;
    int d = ei[NE + e];
    int pos = rowptr[d] + atomicAdd(&cursor[d], 1);
    csr[pos] = ei[e] | (ea[e] << 20);
}

__global__ void amp_k(const int* __restrict__ rowptr, float* __restrict__ amp,
                      float* __restrict__ invamp) {
    int i = blockIdx.x * blockDim.x + threadIdx.x;
    if (i >= NN) return;
    int dg = rowptr[i + 1] - rowptr[i];
    float a = logf((float)max(dg, 1) + 1.f) / AVGLOG;
    amp[i] = a;
    invamp[i] = 1.f / a;
}

// writes H hi/lo planes (ld 80, cols 75..79 zero)
__global__ void embed_k(const int* __restrict__ x, const float* __restrict__ emb,
                        bf16* __restrict__ Hh, bf16* __restrict__ Hl) {
    int i = blockIdx.x * blockDim.x + threadIdx.x;
    if (i >= NN * 80) return;
    int n = i / 80, f = i % 80;
    float v = (f < 75) ? emb[x[n] * 75 + f] : 0.f;
    bsplit(v, &Hh[i], &Hl[i]);
}

// ---------------- weight prep (bf16 planes) ----------------
__global__ void prep_wcat(const float* __restrict__ Wpre, bf16* __restrict__ Wh,
                          bf16* __restrict__ Wl) {
    int i = blockIdx.x * blockDim.x + threadIdx.x;
    if (i >= NL * 75 * 832) return;
    int l = i / (75 * 832), r = i % (75 * 832);
    int k = r / 832, j = r % 832;
    if (j >= 750 && j < 825) return;  // W0 region written by prep_w0
    float v = 0.f;
    if (j < 750) {
        int part = j / 375, j2 = j % 375;
        int t = j2 / 75, f = j2 % 75;
        int c = part * 75 + k;
        v = Wpre[((l * TW + t) * 225 + c) * 75 + f];
    }
    bsplit(v, &Wh[(l * 75 + k) * 832 + j], &Wl[(l * 75 + k) * 832 + j]);
}

__global__ void prep_w0(const float* __restrict__ Wpost, const float* __restrict__ Wlin,
                        bf16* __restrict__ Wh, bf16* __restrict__ Wl) {
    int i = blockIdx.x * blockDim.x + threadIdx.x;
    if (i >= NL * 75 * 75) return;
    int l = i / 5625, r = i % 5625;
    int k = r / 75, c = r % 75;
    float s = 0.f;
    for (int d = 0; d < 75; d++) {
        int t = d / 15, f = d % 15;
        s += Wpost[((l * TW + t) * 975 + k) * 15 + f] * Wlin[l * 5625 + d * 75 + c];
    }
    int o = (l * 75 + k) * 832 + 750 + c;
    bsplit(s, &Wh[o], &Wl[o]);
}

__global__ void prep_etab(const float* __restrict__ edge_emb, const float* __restrict__ We,
                          const float* __restrict__ be, const float* __restrict__ Wpre,
                          const float* __restrict__ bpre, float* __restrict__ Etab) {
    int a = blockIdx.x, l = blockIdx.y;
    __shared__ float ev[75];
    int t0 = threadIdx.x;
    if (t0 < 75) {
        float s = be[l * 75 + t0];
        for (int c = 0; c < 50; c++) s += edge_emb[a * 50 + c] * We[(l * 50 + c) * 75 + t0];
        ev[t0] = s;
    }
    __syncthreads();
    for (int j = t0; j < 375; j += blockDim.x) {
        int t = j / 75, f = j % 75;
        float s = bpre[(l * TW + t) * 75 + f];
        for (int d = 0; d < 75; d++)
            s += ev[d] * Wpre[((l * TW + t) * 225 + 150 + d) * 75 + f];
        Etab[(l * 4 + a) * 375 + j] = s;
    }
}

__global__ void prep_wg(const float* __restrict__ Wpost, bf16* __restrict__ Wh,
                        bf16* __restrict__ Wl) {
    int i = blockIdx.x * blockDim.x + threadIdx.x;
    if (i >= NL * TW * 300 * 48) return;
    int lt = i / (300 * 48), r = i % (300 * 48);
    int c = r / 48, col = r % 48;
    float v = 0.f;
    if (col < 45) {
        int g = col / 15, f = col % 15;
        v = Wpost[(lt * 975 + 75 + g * 300 + c) * 15 + f];
    }
    int o = (lt * 300 + c) * 48 + col;
    bsplit(v, &Wh[o], &Wl[o]);
}

__global__ void prep_wlin(const float* __restrict__ Wlin, bf16* __restrict__ Wh,
                          bf16* __restrict__ Wl) {
    int i = blockIdx.x * blockDim.x + threadIdx.x;
    if (i >= NL * 75 * 80) return;
    int l = i / (75 * 80), r = i % (75 * 80);
    int k = r / 80, c = r % 80;
    float v = (c < 75) ? Wlin[l * 5625 + k * 75 + c] : 0.f;
    int o = (l * 75 + k) * 80 + c;
    bsplit(v, &Wh[o], &Wl[o]);
}

// ---------------- PNA aggregation: writes AGG hi/lo planes [N][T][304] --------------
__global__ __launch_bounds__(384) void pna_agg(const float* __restrict__ CAB,
                                               const float* __restrict__ Etab,
                                               const int* __restrict__ rowptr,
                                               const int* __restrict__ csr,
                                               bf16* __restrict__ AGGh,
                                               bf16* __restrict__ AGGl) {
    int n = blockIdx.x;
    int j = threadIdx.x;
    if (j >= 375) return;
    if (j < 20) {  // zero tower pads (cols 300..303 of each tower)
        int o = n * 1520 + (j >> 2) * 304 + 300 + (j & 3);
        AGGh[o] = __float2bfloat16(0.f);
        AGGl[o] = __float2bfloat16(0.f);
    }
    float adst = CAB[(long)n * CLD + j];
    int beg = rowptr[n], end = rowptr[n + 1];
    float s = 0.f, sq = 0.f, mn = 3.4e38f, mx = -3.4e38f;
    int e = beg;
    for (; e + 1 < end; e += 2) {
        int p0 = csr[e], p1 = csr[e + 1];
        float b0 = CAB[(long)(p0 & 0xFFFFF) * CLD + 375 + j];
        float b1 = CAB[(long)(p1 & 0xFFFFF) * CLD + 375 + j];
        float v0 = adst + b0 + Etab[(p0 >> 20) * 375 + j];
        float v1 = adst + b1 + Etab[(p1 >> 20) * 375 + j];
        s += v0 + v1;
        sq += v0 * v0 + v1 * v1;
        mn = fminf(mn, fminf(v0, v1));
        mx = fmaxf(mx, fmaxf(v0, v1));
    }
    if (e < end) {
        int p0 = csr[e];
        float v0 = adst + CAB[(long)(p0 & 0xFFFFF) * CLD + 375 + j] + Etab[(p0 >> 20) * 375 + j];
        s += v0;
        sq += v0 * v0;
        mn = fminf(mn, v0);
        mx = fmaxf(mx, v0);
    }
    int dg = end - beg;
    float denom = fmaxf((float)dg, 1.f);
    float mean = s / denom, msq = sq / denom;
    float sd = sqrtf(fmaxf(msq - mean * mean, 0.f) + 1e-5f);
    if (dg == 0) { mn = 0.f; mx = 0.f; }
    int t = j / 75, f = j % 75;
    long o = (long)n * 1520 + t * 304;
    bsplit(mean, &AGGh[o + f], &AGGl[o + f]);
    bsplit(mn, &AGGh[o + 75 + f], &AGGl[o + 75 + f]);
    bsplit(mx, &AGGh[o + 150 + f], &AGGl[o + 150 + f]);
    bsplit(sd, &AGGh[o + 225 + f], &AGGl[o + 225 + f]);
}

// ---------------- combine towers + scalers -> Z hi/lo planes ----------------
__global__ void combine_k(const float* __restrict__ G, const float* __restrict__ amp,
                          const float* __restrict__ invamp, const float* __restrict__ bpost,
                          bf16* __restrict__ Zh, bf16* __restrict__ Zl) {
    int i = blockIdx.x * blockDim.x + threadIdx.x;
    if (i >= NN * 80) return;
    int n = i / 80, j = i % 80;
    float v = 0.f;
    if (j < 75) {
        int t = j / 15, f = j % 15;
        const float* g = G + (long)n * 225 + t * 45;
        v = g[f] + amp[n] * g[15 + f] + invamp[n] * g[30 + f] + bpost[t * 15 + f];
    }
    bsplit(v, &Zh[i], &Zl[i]);
}

// ---------------- batchnorm ----------------
__global__ void bn_stats(const float* __restrict__ Y, double* __restrict__ S,
                         double* __restrict__ Q) {
    __shared__ float ss[4][75], sq[4][75];
    int f = threadIdx.x, w = threadIdx.y;
    int base = blockIdx.x * 64;
    float s = 0.f, q = 0.f;
    for (int r = w; r < 64; r += 4) {
        int n = base + r;
        if (n < NN) {
            float v = Y[(long)n * DD + f];
            s += v;
            q += v * v;
        }
    }
    ss[w][f] = s;
    sq[w][f] = q;
    __syncthreads();
    if (w == 0) {
        float st = ss[0][f] + ss[1][f] + ss[2][f] + ss[3][f];
        float qt = sq[0][f] + sq[1][f] + sq[2][f] + sq[3][f];
        atomicAdd(&S[f], (double)st);
        atomicAdd(&Q[f], (double)qt);
    }
}

// BN+ReLU -> H hi/lo planes
__global__ void bn_apply(const float* __restrict__ Y, const double* __restrict__ S,
                         const double* __restrict__ Q, const float* __restrict__ gamma,
                         const float* __restrict__ beta, bf16* __restrict__ Hh,
                         bf16* __restrict__ Hl) {
    int i = blockIdx.x * blockDim.x + threadIdx.x;
    if (i >= NN * 80) return;
    int n = i / 80, f = i % 80;
    float v = 0.f;
    if (f < 75) {
        double mu = S[f] / (double)NN;
        double var = Q[f] / (double)NN - mu * mu;
        float inv = rsqrtf((float)var + 1e-5f);
        v = gamma[f] * ((Y[(long)n * DD + f] - (float)mu) * inv) + beta[f];
        v = fmaxf(v, 0.f);
    }
    bsplit(v, &Hh[i], &Hl[i]);
}

// ---------------- pooling (reconstruct fp32 from planes) ----------------
__global__ void pool_k(const int* __restrict__ batch, const bf16* __restrict__ Hh,
                       const bf16* __restrict__ Hl, float* __restrict__ pool) {
    int i = blockIdx.x * blockDim.x + threadIdx.x;
    if (i >= NN * DD) return;
    int n = i / DD, f = i % DD;
    float v = __bfloat162float(Hh[n * 80 + f]) + __bfloat162float(Hl[n * 80 + f]);
    atomicAdd(&pool[batch[n] * DD + f], v);
}

// ---------------- launch ----------------
static inline void tgemm(const bf16* Ah, const bf16* Al, int lda, long sA, const bf16* Bh,
                         const bf16* Bl, int ldb, long sB, float* C, int ldc, long sC, int M,
                         int N, int K, const float* bias, const float* addC, int ldadd, int act,
                         int nz) {
    dim3 grid((N + 63) / 64, (M + 127) / 128, nz);
    tgemm_kernel<<<grid, 256, SMEM_BYTES>>>(Ah, Al, lda, sA, Bh, Bl, ldb, sB, C, ldc, sC, M, N,
                                            K, bias, addC, ldadd, act);
}

extern "C" void kernel_launch(void* const* d_in, const int* in_sizes, int n_in,
                              void* d_out, int out_size) {
    const int* x = (const int*)d_in[0];
    const int* ei = (const int*)d_in[1];
    const int* ea = (const int*)d_in[2];
    const int* batch = (const int*)d_in[3];
    const float* node_emb = (const float*)d_in[4];
    const float* edge_emb = (const float*)d_in[5];
    const float* We = (const float*)d_in[6];
    const float* be = (const float*)d_in[7];
    const float* Wpre = (const float*)d_in[8];
    const float* bpre = (const float*)d_in[9];
    const float* Wpost = (const float*)d_in[10];
    const float* bpost = (const float*)d_in[11];
    const float* Wlin = (const float*)d_in[12];
    const float* blin = (const float*)d_in[13];
    const float* gamma = (const float*)d_in[14];
    const float* beta = (const float*)d_in[15];
    const float* W1 = (const float*)d_in[16];
    const float* b1 = (const float*)d_in[17];
    const float* W2 = (const float*)d_in[18];
    const float* b2 = (const float*)d_in[19];
    const float* W3 = (const float*)d_in[20];
    const float* b3 = (const float*)d_in[21];
    float* out = (float*)d_out;

    cudaFuncSetAttribute(tgemm_kernel, cudaFuncAttributeMaxDynamicSharedMemorySize, SMEM_BYTES);

    bf16 *Hh, *Hl, *AGGh, *AGGl, *Zh, *Zl, *Wcath, *Wcatl, *WGh, *WGl, *Wlinh, *Wlinl;
    float *CAB, *G, *Y, *amp, *invamp, *Etab, *pool, *z1, *z2;
    int *deg, *rowptr, *csr, *bsum, *boffs;
    double *bnS, *bnQ;
    cudaGetSymbolAddress((void**)&Hh, g_Hh);
    cudaGetSymbolAddress((void**)&Hl, g_Hl);
    cudaGetSymbolAddress((void**)&CAB, g_CAB);
    cudaGetSymbolAddress((void**)&AGGh, g_AGGh);
    cudaGetSymbolAddress((void**)&AGGl, g_AGGl);
    cudaGetSymbolAddress((void**)&G, g_G);
    cudaGetSymbolAddress((void**)&Zh, g_Zh);
    cudaGetSymbolAddress((void**)&Zl, g_Zl);
    cudaGetSymbolAddress((void**)&Y, g_Y);
    cudaGetSymbolAddress((void**)&amp, g_amp);
    cudaGetSymbolAddress((void**)&invamp, g_invamp);
    cudaGetSymbolAddress((void**)&deg, g_deg);
    cudaGetSymbolAddress((void**)&rowptr, g_rowptr);
    cudaGetSymbolAddress((void**)&csr, g_csr);
    cudaGetSymbolAddress((void**)&bsum, g_bsum);
    cudaGetSymbolAddress((void**)&boffs, g_boffs);
    cudaGetSymbolAddress((void**)&Wcath, g_Wcath);
    cudaGetSymbolAddress((void**)&Wcatl, g_Wcatl);
    cudaGetSymbolAddress((void**)&Etab, g_Etab);
    cudaGetSymbolAddress((void**)&WGh, g_WGh);
    cudaGetSymbolAddress((void**)&WGl, g_WGl);
    cudaGetSymbolAddress((void**)&Wlinh, g_Wlinh);
    cudaGetSymbolAddress((void**)&Wlinl, g_Wlinl);
    cudaGetSymbolAddress((void**)&bnS, g_bnS);
    cudaGetSymbolAddress((void**)&bnQ, g_bnQ);
    cudaGetSymbolAddress((void**)&pool, g_pool);
    cudaGetSymbolAddress((void**)&z1, g_z1);
    cudaGetSymbolAddress((void**)&z2, g_z2);
    int* cursor = deg + NN;

    // ---- launch index 3 = layer-0 CAB GEMM (ncu capture slot) ----
    embed_k<<<(NN * 80 + 255) / 256, 256>>>(x, node_emb, Hh, Hl);               // 0
    prep_wcat<<<(NL * 75 * 832 + 255) / 256, 256>>>(Wpre, Wcath, Wcatl);        // 1
    prep_w0<<<(NL * 75 * 75 + 255) / 256, 256>>>(Wpost, Wlin, Wcath, Wcatl);    // 2
    tgemm(Hh, Hl, 80, 0, Wcath, Wcatl, 832, 0, CAB, CLD, 0, NN, 825, 75,        // 3
          nullptr, nullptr, 0, 0, 1);
    prep_wg<<<(NL * TW * 300 * 48 + 255) / 256, 256>>>(Wpost, WGh, WGl);        // 4
    prep_wlin<<<(NL * 75 * 80 + 255) / 256, 256>>>(Wlin, Wlinh, Wlinl);         // 5

    // ---- graph structure prep ----
    zero_i<<<(2 * NN + 255) / 256, 256>>>(deg, 2 * NN);
    hist_k<<<(NE + 255) / 256, 256>>>(ei, deg);
    int nchunks = (NN + 511) / 512;
    scan_chunks<<<nchunks, 512>>>(deg, rowptr, bsum, NN);
    scan_sums<<<1, 128>>>(bsum, boffs, nchunks);
    scan_add<<<(NN + 255) / 256, 256>>>(rowptr, boffs);
    fill_csr<<<(NE + 255) / 256, 256>>>(ei, ea, rowptr, cursor, csr);
    amp_k<<<(NN + 255) / 256, 256>>>(rowptr, amp, invamp);
    prep_etab<<<dim3(4, NL), 384>>>(edge_emb, We, be, Wpre, bpre, Etab);

    // ---- layers ----
    for (int l = 0; l < NL; l++) {
        if (l > 0) {
            tgemm(Hh, Hl, 80, 0, Wcath + l * 75 * 832, Wcatl + l * 75 * 832, 832, 0, CAB, CLD,
                  0, NN, 825, 75, nullptr, nullptr, 0, 0, 1);
        }
        pna_agg<<<NN, 384>>>(CAB, Etab + l * 4 * 375, rowptr, csr, AGGh, AGGl);
        // G[t] = AGG[:,t] @ WG[l][t]   (A slice stride 304 within padded row of 1520)
        tgemm(AGGh, AGGl, 1520, 304, WGh + l * TW * 300 * 48, WGl + l * TW * 300 * 48, 48,
              (long)300 * 48, G, 225, 45, NN, 45, 300, nullptr, nullptr, 0, 0, TW);
        combine_k<<<(NN * 80 + 255) / 256, 256>>>(G, amp, invamp, bpost + l * TW * FO, Zh, Zl);
        // Y = Z @ Wlin + (H@W0 from CAB[:,750:]) + blin
        tgemm(Zh, Zl, 80, 0, Wlinh + l * 75 * 80, Wlinl + l * 75 * 80, 80, 0, Y, 75, 0, NN, 75,
              75, blin + l * 75, CAB + 750, CLD, 0, 1);
        zero_d75<<<1, 128>>>(bnS, bnQ);
        bn_stats<<<(NN + 63) / 64, dim3(75, 4)>>>(Y, bnS, bnQ);
        bn_apply<<<(NN * 80 + 255) / 256, 256>>>(Y, bnS, bnQ, gamma + l * DD, beta + l * DD,
                                                 Hh, Hl);
    }

    // ---- pooling + MLP (tiny, fp32 SIMT) ----
    zero_f<<<(NG * DD + 255) / 256, 256>>>(pool, NG * DD);
    pool_k<<<(NN * DD + 255) / 256, 256>>>(batch, Hh, Hl, pool);
    sgemm_s<<<(NG * 50 + 255) / 256, 256>>>(pool, 75, W1, 50, z1, 50, NG, 50, 75, b1, 1);
    sgemm_s<<<(NG * 25 + 255) / 256, 256>>>(z1, 50, W2, 25, z2, 25, NG, 25, 50, b2, 1);
    sgemm_s<<<(NG * 1 + 255) / 256, 256>>>(z2, 25, W3, 1, out, 1, NG, 1, 25, b3, 0);
}

// round 12
// speedup vs baseline: 2.0938x; 1.0590x over previous
#include <cuda_runtime.h>
#include <mma.h>
#include <math.h>
#include <cstdint>
#include <cuda_bf16.h>

using namespace nvcuda;

#define NN 50000
#define NE 150000
#define NG 2000
#define DD 75
#define TW 5
#define FO 15
#define NL 4
#define AVGLOG 1.1308269950720914f
#define CLD 828   // CAB row stride (multiple of 4 for wmma direct store)

typedef __nv_bfloat16 bf16;

// ---------------- scratch (device globals; no allocs) ----------------
__device__ __align__(256) bf16  g_Hh[NN * 80];
__device__ __align__(256) bf16  g_Hl[NN * 80];
__device__ __align__(256) float g_CAB[NN * CLD];     // fp32: [A(375) | B(375) | H@W0(75) | pad]
__device__ __align__(256) bf16  g_AGGh[NN * 1520];   // [N][T][304] padded towers
__device__ __align__(256) bf16  g_AGGl[NN * 1520];
__device__ __align__(256) bf16  g_Zh[NN * 80];
__device__ __align__(256) bf16  g_Zl[NN * 80];
__device__ float g_Y[NN * DD];
__device__ float g_amp[NN];
__device__ float g_invamp[NN];
__device__ int   g_deg[NN * 2];
__device__ int   g_rowptr[NN + 1];
__device__ int   g_csr[NE];
__device__ int   g_bsum[256];
__device__ int   g_boffs[256];
__device__ __align__(256) bf16  g_Wcath[NL * 75 * 832];
__device__ __align__(256) bf16  g_Wcatl[NL * 75 * 832];
__device__ float g_Etab[NL * 4 * 375];
__device__ __align__(256) bf16  g_WGh[NL * TW * 300 * 48];
__device__ __align__(256) bf16  g_WGl[NL * TW * 300 * 48];
__device__ __align__(256) bf16  g_Wlinh[NL * 75 * 80];
__device__ __align__(256) bf16  g_Wlinl[NL * 75 * 80];
__device__ double g_bnS[NL * DD];
__device__ double g_bnQ[NL * DD];
__device__ float g_pool[NG * DD];
__device__ float g_z1[NG * 50];
__device__ float g_z2[NG * 25];

__device__ __forceinline__ void bsplit(float v, bf16* h, bf16* l) {
    bf16 hi = __float2bfloat16(v);
    *h = hi;
    *l = __float2bfloat16(v - __bfloat162float(hi));
}

// ---------------- cp.async helpers ----------------
__device__ __forceinline__ void cp16(unsigned dst, const void* src, bool pred) {
    int sz = pred ? 16 : 0;   // sz=0 -> zero-fill
    asm volatile("cp.async.cg.shared.global [%0], [%1], 16, %2;\n" ::"r"(dst), "l"(src),
                 "r"(sz));
}
#define CP_COMMIT() asm volatile("cp.async.commit_group;\n" ::: "memory")
#define CP_WAIT1() asm volatile("cp.async.wait_group 1;\n" ::: "memory")
#define CP_WAIT0() asm volatile("cp.async.wait_group 0;\n" ::: "memory")

// ---------------- split-bf16 GEMM; pre-split hi/lo planes; 16B async loads ----------
// tile 128x64, 256 threads. smem: A hi[2]/lo[2] 128x24, B hi[2]/lo[2] 16x72; sC fp32 union.
// mode 0: standard epilogue (bias/addC/act, direct store when legal)
// mode 1: PNA combine epilogue -> Z planes (bias=bpost base; blockIdx.z = tower)
// mode 2: Y epilogue + BN column stats accumulation
#define SAS 24
#define SBS 72
#define SA_PLANE (128 * SAS)
#define SB_PLANE (16 * SBS)
#define SMEM_BYTES (128 * 72 * 4)   // sC (36864) > stages (33792)

__global__ __launch_bounds__(256) void tgemm_kernel(
    const bf16* __restrict__ Ah, const bf16* __restrict__ Al, int lda, long sAb,
    const bf16* __restrict__ Bh, const bf16* __restrict__ Bl, int ldb, long sBb,
    float* __restrict__ C, int ldc, long sCb,
    int M, int N, int K,
    const float* __restrict__ bias,
    const float* __restrict__ addC, int ldadd,
    const float* __restrict__ amp, const float* __restrict__ invamp,
    bf16* __restrict__ Zph, bf16* __restrict__ Zpl,
    double* __restrict__ bnS, double* __restrict__ bnQ,
    int act, int mode) {
    extern __shared__ char smem_raw[];
    __shared__ float rs[256], rq[256];
    bf16* bb = (bf16*)smem_raw;
    float* sC = (float*)smem_raw;

    const bf16* Abh = Ah + (long)blockIdx.z * sAb;
    const bf16* Abl = Al + (long)blockIdx.z * sAb;
    const bf16* Bbh = Bh + (long)blockIdx.z * sBb;
    const bf16* Bbl = Bl + (long)blockIdx.z * sBb;
    float* Cb = C + (long)blockIdx.z * sCb;
    int m0 = blockIdx.y * 128, n0 = blockIdx.x * 64;
    int tid = threadIdx.x;
    int warp = tid >> 5;
    int wm = (warp & 3) * 32;
    int wn = (warp >> 2) * 32;
    int numK = (K + 15) / 16;

    // ---- precomputed loader state ----
    const bf16* aSrc[2];
    unsigned aDst[2];
    bool aPred[2];
#pragma unroll
    for (int u = 0; u < 2; u++) {
        int idx = tid + u * 256;
        int pl = idx >> 8, rem = idx & 255;
        int r = rem >> 1, ch = rem & 1;
        const bf16* base = pl ? Abl : Abh;
        aPred[u] = (m0 + r) < M;
        aSrc[u] = base + (long)(m0 + r) * lda + ch * 8;
        aDst[u] = (unsigned)__cvta_generic_to_shared(bb + pl * 2 * SA_PLANE + r * SAS + ch * 8);
    }
    int bPl = tid >> 7, bRem = tid & 127;
    int bR = bRem >> 3, bCh = bRem & 7;
    const bf16* bBase = bPl ? Bbl : Bbh;
    bool bPredN = (n0 + bCh * 8) < ldb;
    const bf16* bSrc = bBase + (long)bR * ldb + n0 + bCh * 8;
    unsigned bDst = (unsigned)__cvta_generic_to_shared(bb + 4 * SA_PLANE + bPl * 2 * SB_PLANE +
                                                       bR * SBS + bCh * 8);

    auto load_stage = [&](int st, int k0) {
#pragma unroll
        for (int u = 0; u < 2; u++)
            cp16(aDst[u] + st * SA_PLANE * 2, aPred[u] ? (aSrc[u] + k0) : Abh, aPred[u]);
        bool p = bPredN && (k0 + bR) < K;
        cp16(bDst + st * SB_PLANE * 2, p ? (bSrc + (long)k0 * ldb) : Bbh, p);
    };

    wmma::fragment<wmma::accumulator, 16, 16, 16, float> acc[2][2];
#pragma unroll
    for (int i = 0; i < 2; i++)
#pragma unroll
        for (int j = 0; j < 2; j++) wmma::fill_fragment(acc[i][j], 0.f);

    load_stage(0, 0);
    CP_COMMIT();

    for (int kt = 0; kt < numK; kt++) {
        int st = kt & 1;
        if (kt + 1 < numK) {
            load_stage(st ^ 1, (kt + 1) * 16);
            CP_COMMIT();
            CP_WAIT1();
        } else {
            CP_WAIT0();
        }
        __syncthreads();

        bf16* sAh = bb + st * SA_PLANE;
        bf16* sAl = bb + 2 * SA_PLANE + st * SA_PLANE;
        bf16* sBh = bb + 4 * SA_PLANE + st * SB_PLANE;
        bf16* sBl = bb + 4 * SA_PLANE + 2 * SB_PLANE + st * SB_PLANE;

        wmma::fragment<wmma::matrix_a, 16, 16, 16, bf16, wmma::row_major> ah[2], al[2];
        wmma::fragment<wmma::matrix_b, 16, 16, 16, bf16, wmma::row_major> bh[2], bl[2];
#pragma unroll
        for (int i = 0; i < 2; i++) {
            wmma::load_matrix_sync(ah[i], &sAh[(wm + 16 * i) * SAS], SAS);
            wmma::load_matrix_sync(al[i], &sAl[(wm + 16 * i) * SAS], SAS);
        }
#pragma unroll
        for (int j = 0; j < 2; j++) {
            wmma::load_matrix_sync(bh[j], &sBh[wn + 16 * j], SBS);
            wmma::load_matrix_sync(bl[j], &sBl[wn + 16 * j], SBS);
        }
#pragma unroll
        for (int i = 0; i < 2; i++)
#pragma unroll
            for (int j = 0; j < 2; j++) {
                wmma::mma_sync(acc[i][j], al[i], bh[j], acc[i][j]);
                wmma::mma_sync(acc[i][j], ah[i], bl[j], acc[i][j]);
                wmma::mma_sync(acc[i][j], ah[i], bh[j], acc[i][j]);
            }
        __syncthreads();
    }

    // direct store: mode 0, no epilogue math, full tile, ldc multiple of 4
    bool direct = (mode == 0) && (bias == nullptr) && (addC == nullptr) && (act == 0) &&
                  ((ldc & 3) == 0) && (m0 + 128 <= M) && (n0 + 64 <= N);
    if (direct) {
#pragma unroll
        for (int i = 0; i < 2; i++)
#pragma unroll
            for (int j = 0; j < 2; j++)
                wmma::store_matrix_sync(&Cb[(long)(m0 + wm + 16 * i) * ldc + n0 + wn + 16 * j],
                                        acc[i][j], ldc, wmma::mem_row_major);
        return;
    }
#pragma unroll
    for (int i = 0; i < 2; i++)
#pragma unroll
        for (int j = 0; j < 2; j++)
            wmma::store_matrix_sync(&sC[(wm + 16 * i) * 72 + wn + 16 * j], acc[i][j], 72,
                                    wmma::mem_row_major);
    __syncthreads();

    if (mode == 1) {
        // combine towers + degree scalers -> Z planes; tower = blockIdx.z; cols 0..44 valid
        int t = blockIdx.z;
        for (int i = tid; i < 128 * 15; i += 256) {
            int r = i / 15, f = i % 15;
            int gm = m0 + r;
            if (gm < M) {
                const float* row = &sC[r * 72];
                float v = row[f] + amp[gm] * row[15 + f] + invamp[gm] * row[30 + f] +
                          bias[t * 15 + f];
                long o = (long)gm * 80 + t * 15 + f;
                bsplit(v, &Zph[o], &Zpl[o]);
            }
        }
        return;
    }
    if (mode == 2) {
        // Y = acc + bias + addC; accumulate BN column stats
        float s = 0.f, q = 0.f;
        int c = tid & 63, gn = n0 + c;
        for (int i = tid; i < 128 * 64; i += 256) {
            int r = i >> 6;
            int gm = m0 + r;
            if (gm < M && gn < N) {
                float v = sC[r * 72 + c] + bias[gn] + addC[(long)gm * ldadd + gn];
                Cb[(long)gm * ldc + gn] = v;
                s += v;
                q += v * v;
            }
        }
        rs[tid] = s;
        rq[tid] = q;
        __syncthreads();
        if (tid < 64 && gn < N) {
            float ts = rs[tid] + rs[tid + 64] + rs[tid + 128] + rs[tid + 192];
            float tq = rq[tid] + rq[tid + 64] + rq[tid + 128] + rq[tid + 192];
            atomicAdd(&bnS[gn], (double)ts);
            atomicAdd(&bnQ[gn], (double)tq);
        }
        return;
    }
    // mode 0 generic
    for (int i = tid; i < 128 * 64; i += 256) {
        int r = i >> 6, c = i & 63;
        int gm = m0 + r, gn = n0 + c;
        if (gm < M && gn < N) {
            float v = sC[r * 72 + c];
            if (bias) v += bias[gn];
            if (addC) v += addC[(long)gm * ldadd + gn];
            if (act) v = fmaxf(v, 0.f);
            Cb[(long)gm * ldc + gn] = v;
        }
    }
}

// ---------------- tiny fp32 GEMM for the final MLP ----------------
__global__ void sgemm_s(const float* __restrict__ A, int lda, const float* __restrict__ B,
                        int ldb, float* __restrict__ C, int ldc, int M, int N, int K,
                        const float* __restrict__ bias, int act) {
    int i = blockIdx.x * blockDim.x + threadIdx.x;
    if (i >= M * N) return;
    int m = i / N, n = i % N;
    float s = bias ? bias[n] : 0.f;
    for (int k = 0; k < K; k++) s += A[m * lda + k] * B[k * ldb + n];
    if (act) s = fmaxf(s, 0.f);
    C[m * ldc + n] = s;
}

// ---------------- small utility kernels ----------------
__global__ void zero_i(int* p, int n) {
    int i = blockIdx.x * blockDim.x + threadIdx.x;
    if (i < n) p[i] = 0;
}
__global__ void zero_f(float* p, int n) {
    int i = blockIdx.x * blockDim.x + threadIdx.x;
    if (i < n) p[i] = 0.f;
}
__global__ void zero_bn(double* s, double* q, int n) {
    int i = blockIdx.x * blockDim.x + threadIdx.x;
    if (i < n) { s[i] = 0.0; q[i] = 0.0; }
}
__global__ void zero_zpad(bf16* Zh, bf16* Zl) {
    int i = blockIdx.x * blockDim.x + threadIdx.x;
    if (i >= NN * 5) return;
    int n = i / 5, k = i % 5;
    Zh[n * 80 + 75 + k] = __float2bfloat16(0.f);
    Zl[n * 80 + 75 + k] = __float2bfloat16(0.f);
}

__global__ void hist_k(const int* __restrict__ ei, int* __restrict__ deg) {
    int e = blockIdx.x * blockDim.x + threadIdx.x;
    if (e < NE) atomicAdd(&deg[ei[NE + e]], 1);
}

__global__ void scan_chunks(const int* __restrict__ in, int* __restrict__ out,
                            int* __restrict__ bsum, int n) {
    __shared__ int s[512];
    int b = blockIdx.x, t = threadIdx.x;
    int idx = b * 512 + t;
    int v = (idx < n) ? in[idx] : 0;
    s[t] = v;
    __syncthreads();
    for (int off = 1; off < 512; off <<= 1) {
        int x = (t >= off) ? s[t - off] : 0;
        __syncthreads();
        s[t] += x;
        __syncthreads();
    }
    if (idx < n) out[idx] = s[t] - v;
    if (t == 511) bsum[b] = s[511];
}
__global__ void scan_sums(const int* __restrict__ sums, int* __restrict__ offs, int nb) {
    __shared__ int s[128];
    int t = threadIdx.x;
    int v = (t < nb) ? sums[t] : 0;
    s[t] = v;
    __syncthreads();
    for (int off = 1; off < 128; off <<= 1) {
        int x = (t >= off) ? s[t - off] : 0;
        __syncthreads();
        s[t] += x;
        __syncthreads();
    }
    if (t < nb) offs[t] = s[t] - v;
}
__global__ void scan_add(int* __restrict__ rowptr, const int* __restrict__ offs) {
    int i = blockIdx.x * blockDim.x + threadIdx.x;
    if (i < NN) rowptr[i] += offs[i >> 9];
    if (i == 0) rowptr[NN] = NE;
}

__global__ void fill_csr(const int* __restrict__ ei, const int* __restrict__ ea,
                         const int* __restrict__ rowptr, int* __restrict__ cursor,
                         int* __restrict__ csr) {
    int e = blockIdx.x * blockDim.x + threadIdx.x;
    if (e >= NE) return;
    int d = ei[NE + e];
    int pos = rowptr[d] + atomicAdd(&cursor[d], 1);
    csr[pos] = ei[e] | (ea[e] << 20);
}

__global__ void amp_k(const int* __restrict__ rowptr, float* __restrict__ amp,
                      float* __restrict__ invamp) {
    int i = blockIdx.x * blockDim.x + threadIdx.x;
    if (i >= NN) return;
    int dg = rowptr[i + 1] - rowptr[i];
    float a = logf((float)max(dg, 1) + 1.f) / AVGLOG;
    amp[i] = a;
    invamp[i] = 1.f / a;
}

// writes H hi/lo planes (ld 80, cols 75..79 zero)
__global__ void embed_k(const int* __restrict__ x, const float* __restrict__ emb,
                        bf16* __restrict__ Hh, bf16* __restrict__ Hl) {
    int i = blockIdx.x * blockDim.x + threadIdx.x;
    if (i >= NN * 80) return;
    int n = i / 80, f = i % 80;
    float v = (f < 75) ? emb[x[n] * 75 + f] : 0.f;
    bsplit(v, &Hh[i], &Hl[i]);
}

// ---------------- weight prep (bf16 planes) ----------------
__global__ void prep_wcat(const float* __restrict__ Wpre, bf16* __restrict__ Wh,
                          bf16* __restrict__ Wl) {
    int i = blockIdx.x * blockDim.x + threadIdx.x;
    if (i >= NL * 75 * 832) return;
    int l = i / (75 * 832), r = i % (75 * 832);
    int k = r / 832, j = r % 832;
    if (j >= 750 && j < 825) return;  // W0 region written by prep_w0
    float v = 0.f;
    if (j < 750) {
        int part = j / 375, j2 = j % 375;
        int t = j2 / 75, f = j2 % 75;
        int c = part * 75 + k;
        v = Wpre[((l * TW + t) * 225 + c) * 75 + f];
    }
    bsplit(v, &Wh[(l * 75 + k) * 832 + j], &Wl[(l * 75 + k) * 832 + j]);
}

__global__ void prep_w0(const float* __restrict__ Wpost, const float* __restrict__ Wlin,
                        bf16* __restrict__ Wh, bf16* __restrict__ Wl) {
    int i = blockIdx.x * blockDim.x + threadIdx.x;
    if (i >= NL * 75 * 75) return;
    int l = i / 5625, r = i % 5625;
    int k = r / 75, c = r % 75;
    float s = 0.f;
    for (int d = 0; d < 75; d++) {
        int t = d / 15, f = d % 15;
        s += Wpost[((l * TW + t) * 975 + k) * 15 + f] * Wlin[l * 5625 + d * 75 + c];
    }
    int o = (l * 75 + k) * 832 + 750 + c;
    bsplit(s, &Wh[o], &Wl[o]);
}

__global__ void prep_etab(const float* __restrict__ edge_emb, const float* __restrict__ We,
                          const float* __restrict__ be, const float* __restrict__ Wpre,
                          const float* __restrict__ bpre, float* __restrict__ Etab) {
    int a = blockIdx.x, l = blockIdx.y;
    __shared__ float ev[75];
    int t0 = threadIdx.x;
    if (t0 < 75) {
        float s = be[l * 75 + t0];
        for (int c = 0; c < 50; c++) s += edge_emb[a * 50 + c] * We[(l * 50 + c) * 75 + t0];
        ev[t0] = s;
    }
    __syncthreads();
    for (int j = t0; j < 375; j += blockDim.x) {
        int t = j / 75, f = j % 75;
        float s = bpre[(l * TW + t) * 75 + f];
        for (int d = 0; d < 75; d++)
            s += ev[d] * Wpre[((l * TW + t) * 225 + 150 + d) * 75 + f];
        Etab[(l * 4 + a) * 375 + j] = s;
    }
}

__global__ void prep_wg(const float* __restrict__ Wpost, bf16* __restrict__ Wh,
                        bf16* __restrict__ Wl) {
    int i = blockIdx.x * blockDim.x + threadIdx.x;
    if (i >= NL * TW * 300 * 48) return;
    int lt = i / (300 * 48), r = i % (300 * 48);
    int c = r / 48, col = r % 48;
    float v = 0.f;
    if (col < 45) {
        int g = col / 15, f = col % 15;
        v = Wpost[(lt * 975 + 75 + g * 300 + c) * 15 + f];
    }
    int o = (lt * 300 + c) * 48 + col;
    bsplit(v, &Wh[o], &Wl[o]);
}

__global__ void prep_wlin(const float* __restrict__ Wlin, bf16* __restrict__ Wh,
                          bf16* __restrict__ Wl) {
    int i = blockIdx.x * blockDim.x + threadIdx.x;
    if (i >= NL * 75 * 80) return;
    int l = i / (75 * 80), r = i % (75 * 80);
    int k = r / 80, c = r % 80;
    float v = (c < 75) ? Wlin[l * 5625 + k * 75 + c] : 0.f;
    int o = (l * 75 + k) * 80 + c;
    bsplit(v, &Wh[o], &Wl[o]);
}

// ---------------- PNA aggregation: writes AGG hi/lo planes [N][T][304] --------------
__global__ __launch_bounds__(384) void pna_agg(const float* __restrict__ CAB,
                                               const float* __restrict__ Etab,
                                               const int* __restrict__ rowptr,
                                               const int* __restrict__ csr,
                                               bf16* __restrict__ AGGh,
                                               bf16* __restrict__ AGGl) {
    int n = blockIdx.x;
    int j = threadIdx.x;
    if (j >= 375) return;
    if (j < 20) {  // zero tower pads (cols 300..303 of each tower)
        int o = n * 1520 + (j >> 2) * 304 + 300 + (j & 3);
        AGGh[o] = __float2bfloat16(0.f);
        AGGl[o] = __float2bfloat16(0.f);
    }
    float adst = CAB[(long)n * CLD + j];
    int beg = rowptr[n], end = rowptr[n + 1];
    float s = 0.f, sq = 0.f, mn = 3.4e38f, mx = -3.4e38f;
    int e = beg;
    for (; e + 1 < end; e += 2) {
        int p0 = csr[e], p1 = csr[e + 1];
        float b0 = CAB[(long)(p0 & 0xFFFFF) * CLD + 375 + j];
        float b1 = CAB[(long)(p1 & 0xFFFFF) * CLD + 375 + j];
        float v0 = adst + b0 + Etab[(p0 >> 20) * 375 + j];
        float v1 = adst + b1 + Etab[(p1 >> 20) * 375 + j];
        s += v0 + v1;
        sq += v0 * v0 + v1 * v1;
        mn = fminf(mn, fminf(v0, v1));
        mx = fmaxf(mx, fmaxf(v0, v1));
    }
    if (e < end) {
        int p0 = csr[e];
        float v0 = adst + CAB[(long)(p0 & 0xFFFFF) * CLD + 375 + j] + Etab[(p0 >> 20) * 375 + j];
        s += v0;
        sq += v0 * v0;
        mn = fminf(mn, v0);
        mx = fmaxf(mx, v0);
    }
    int dg = end - beg;
    float denom = fmaxf((float)dg, 1.f);
    float mean = s / denom, msq = sq / denom;
    float sd = sqrtf(fmaxf(msq - mean * mean, 0.f) + 1e-5f);
    if (dg == 0) { mn = 0.f; mx = 0.f; }
    int t = j / 75, f = j % 75;
    long o = (long)n * 1520 + t * 304;
    bsplit(mean, &AGGh[o + f], &AGGl[o + f]);
    bsplit(mn, &AGGh[o + 75 + f], &AGGl[o + 75 + f]);
    bsplit(mx, &AGGh[o + 150 + f], &AGGl[o + 150 + f]);
    bsplit(sd, &AGGh[o + 225 + f], &AGGl[o + 225 + f]);
}

// ---------------- BN apply + ReLU -> H hi/lo planes ----------------
__global__ void bn_apply(const float* __restrict__ Y, const double* __restrict__ S,
                         const double* __restrict__ Q, const float* __restrict__ gamma,
                         const float* __restrict__ beta, bf16* __restrict__ Hh,
                         bf16* __restrict__ Hl) {
    int i = blockIdx.x * blockDim.x + threadIdx.x;
    if (i >= NN * 80) return;
    int n = i / 80, f = i % 80;
    float v = 0.f;
    if (f < 75) {
        double mu = S[f] / (double)NN;
        double var = Q[f] / (double)NN - mu * mu;
        float inv = rsqrtf((float)var + 1e-5f);
        v = gamma[f] * ((Y[(long)n * DD + f] - (float)mu) * inv) + beta[f];
        v = fmaxf(v, 0.f);
    }
    bsplit(v, &Hh[i], &Hl[i]);
}

// ---------------- pooling (reconstruct fp32 from planes) ----------------
__global__ void pool_k(const int* __restrict__ batch, const bf16* __restrict__ Hh,
                       const bf16* __restrict__ Hl, float* __restrict__ pool) {
    int i = blockIdx.x * blockDim.x + threadIdx.x;
    if (i >= NN * DD) return;
    int n = i / DD, f = i % DD;
    float v = __bfloat162float(Hh[n * 80 + f]) + __bfloat162float(Hl[n * 80 + f]);
    atomicAdd(&pool[batch[n] * DD + f], v);
}

// ---------------- launch ----------------
static inline void tgemm(const bf16* Ah, const bf16* Al, int lda, long sA, const bf16* Bh,
                         const bf16* Bl, int ldb, long sB, float* C, int ldc, long sC, int M,
                         int N, int K, const float* bias, const float* addC, int ldadd,
                         const float* amp, const float* invamp, bf16* Zh, bf16* Zl,
                         double* bnS, double* bnQ, int act, int mode, int nz) {
    dim3 grid((N + 63) / 64, (M + 127) / 128, nz);
    tgemm_kernel<<<grid, 256, SMEM_BYTES>>>(Ah, Al, lda, sA, Bh, Bl, ldb, sB, C, ldc, sC, M, N,
                                            K, bias, addC, ldadd, amp, invamp, Zh, Zl, bnS, bnQ,
                                            act, mode);
}

extern "C" void kernel_launch(void* const* d_in, const int* in_sizes, int n_in,
                              void* d_out, int out_size) {
    const int* x = (const int*)d_in[0];
    const int* ei = (const int*)d_in[1];
    const int* ea = (const int*)d_in[2];
    const int* batch = (const int*)d_in[3];
    const float* node_emb = (const float*)d_in[4];
    const float* edge_emb = (const float*)d_in[5];
    const float* We = (const float*)d_in[6];
    const float* be = (const float*)d_in[7];
    const float* Wpre = (const float*)d_in[8];
    const float* bpre = (const float*)d_in[9];
    const float* Wpost = (const float*)d_in[10];
    const float* bpost = (const float*)d_in[11];
    const float* Wlin = (const float*)d_in[12];
    const float* blin = (const float*)d_in[13];
    const float* gamma = (const float*)d_in[14];
    const float* beta = (const float*)d_in[15];
    const float* W1 = (const float*)d_in[16];
    const float* b1 = (const float*)d_in[17];
    const float* W2 = (const float*)d_in[18];
    const float* b2 = (const float*)d_in[19];
    const float* W3 = (const float*)d_in[20];
    const float* b3 = (const float*)d_in[21];
    float* out = (float*)d_out;

    cudaFuncSetAttribute(tgemm_kernel, cudaFuncAttributeMaxDynamicSharedMemorySize, SMEM_BYTES);

    bf16 *Hh, *Hl, *AGGh, *AGGl, *Zh, *Zl, *Wcath, *Wcatl, *WGh, *WGl, *Wlinh, *Wlinl;
    float *CAB, *Y, *amp, *invamp, *Etab, *pool, *z1, *z2;
    int *deg, *rowptr, *csr, *bsum, *boffs;
    double *bnS, *bnQ;
    cudaGetSymbolAddress((void**)&Hh, g_Hh);
    cudaGetSymbolAddress((void**)&Hl, g_Hl);
    cudaGetSymbolAddress((void**)&CAB, g_CAB);
    cudaGetSymbolAddress((void**)&AGGh, g_AGGh);
    cudaGetSymbolAddress((void**)&AGGl, g_AGGl);
    cudaGetSymbolAddress((void**)&Zh, g_Zh);
    cudaGetSymbolAddress((void**)&Zl, g_Zl);
    cudaGetSymbolAddress((void**)&Y, g_Y);
    cudaGetSymbolAddress((void**)&amp, g_amp);
    cudaGetSymbolAddress((void**)&invamp, g_invamp);
    cudaGetSymbolAddress((void**)&deg, g_deg);
    cudaGetSymbolAddress((void**)&rowptr, g_rowptr);
    cudaGetSymbolAddress((void**)&csr, g_csr);
    cudaGetSymbolAddress((void**)&bsum, g_bsum);
    cudaGetSymbolAddress((void**)&boffs, g_boffs);
    cudaGetSymbolAddress((void**)&Wcath, g_Wcath);
    cudaGetSymbolAddress((void**)&Wcatl, g_Wcatl);
    cudaGetSymbolAddress((void**)&Etab, g_Etab);
    cudaGetSymbolAddress((void**)&WGh, g_WGh);
    cudaGetSymbolAddress((void**)&WGl, g_WGl);
    cudaGetSymbolAddress((void**)&Wlinh, g_Wlinh);
    cudaGetSymbolAddress((void**)&Wlinl, g_Wlinl);
    cudaGetSymbolAddress((void**)&bnS, g_bnS);
    cudaGetSymbolAddress((void**)&bnQ, g_bnQ);
    cudaGetSymbolAddress((void**)&pool, g_pool);
    cudaGetSymbolAddress((void**)&z1, g_z1);
    cudaGetSymbolAddress((void**)&z2, g_z2);
    int* cursor = deg + NN;

    // ---- launch index 3 = layer-0 CAB GEMM (ncu capture slot) ----
    embed_k<<<(NN * 80 + 255) / 256, 256>>>(x, node_emb, Hh, Hl);               // 0
    prep_wcat<<<(NL * 75 * 832 + 255) / 256, 256>>>(Wpre, Wcath, Wcatl);        // 1
    prep_w0<<<(NL * 75 * 75 + 255) / 256, 256>>>(Wpost, Wlin, Wcath, Wcatl);    // 2
    tgemm(Hh, Hl, 80, 0, Wcath, Wcatl, 832, 0, CAB, CLD, 0, NN, 825, 75,        // 3
          nullptr, nullptr, 0, nullptr, nullptr, nullptr, nullptr, nullptr, nullptr, 0, 0, 1);
    prep_wg<<<(NL * TW * 300 * 48 + 255) / 256, 256>>>(Wpost, WGh, WGl);        // 4
    prep_wlin<<<(NL * 75 * 80 + 255) / 256, 256>>>(Wlin, Wlinh, Wlinl);         // 5
    zero_zpad<<<(NN * 5 + 255) / 256, 256>>>(Zh, Zl);                           // 6
    zero_bn<<<(NL * DD + 255) / 256, 256>>>(bnS, bnQ, NL * DD);                 // 7

    // ---- graph structure prep ----
    zero_i<<<(2 * NN + 255) / 256, 256>>>(deg, 2 * NN);
    hist_k<<<(NE + 255) / 256, 256>>>(ei, deg);
    int nchunks = (NN + 511) / 512;
    scan_chunks<<<nchunks, 512>>>(deg, rowptr, bsum, NN);
    scan_sums<<<1, 128>>>(bsum, boffs, nchunks);
    scan_add<<<(NN + 255) / 256, 256>>>(rowptr, boffs);
    fill_csr<<<(NE + 255) / 256, 256>>>(ei, ea, rowptr, cursor, csr);
    amp_k<<<(NN + 255) / 256, 256>>>(rowptr, amp, invamp);
    prep_etab<<<dim3(4, NL), 384>>>(edge_emb, We, be, Wpre, bpre, Etab);

    // ---- layers ----
    for (int l = 0; l < NL; l++) {
        if (l > 0) {
            tgemm(Hh, Hl, 80, 0, Wcath + l * 75 * 832, Wcatl + l * 75 * 832, 832, 0, CAB, CLD,
                  0, NN, 825, 75, nullptr, nullptr, 0, nullptr, nullptr, nullptr, nullptr,
                  nullptr, nullptr, 0, 0, 1);
        }
        pna_agg<<<NN, 384>>>(CAB, Etab + l * 4 * 375, rowptr, csr, AGGh, AGGl);
        // AGG GEMM + fused combine -> Z planes (mode 1)
        tgemm(AGGh, AGGl, 1520, 304, WGh + l * TW * 300 * 48, WGl + l * TW * 300 * 48, 48,
              (long)300 * 48, Y /*unused*/, 45, 0, NN, 45, 300, bpost + l * TW * FO, nullptr, 0,
              amp, invamp, Zh, Zl, nullptr, nullptr, 0, 1, TW);
        // Y GEMM + fused BN stats (mode 2)
        tgemm(Zh, Zl, 80, 0, Wlinh + l * 75 * 80, Wlinl + l * 75 * 80, 80, 0, Y, 75, 0, NN, 75,
              75, blin + l * 75, CAB + 750, CLD, nullptr, nullptr, nullptr, nullptr,
              bnS + l * DD, bnQ + l * DD, 0, 2, 1);
        bn_apply<<<(NN * 80 + 255) / 256, 256>>>(Y, bnS + l * DD, bnQ + l * DD, gamma + l * DD,
                                                 beta + l * DD, Hh, Hl);
    }

    // ---- pooling + MLP (tiny, fp32 SIMT) ----
    zero_f<<<(NG * DD + 255) / 256, 256>>>(pool, NG * DD);
    pool_k<<<(NN * DD + 255) / 256, 256>>>(batch, Hh, Hl, pool);
    sgemm_s<<<(NG * 50 + 255) / 256, 256>>>(pool, 75, W1, 50, z1, 50, NG, 50, 75, b1, 1);
    sgemm_s<<<(NG * 25 + 255) / 256, 256>>>(z1, 50, W2, 25, z2, 25, NG, 25, 50, b2, 1);
    sgemm_s<<<(NG * 1 + 255) / 256, 256>>>(z2, 25, W3, 1, out, 1, NG, 1, 25, b3, 0);
}

// round 13
// speedup vs baseline: 2.2295x; 1.0648x over previous
#include <cuda_runtime.h>
#include <mma.h>
#include <math.h>
#include <cstdint>
#include <cuda_bf16.h>

using namespace nvcuda;

#define NN 50000
#define NE 150000
#define NG 2000
#define DD 75
#define TW 5
#define FO 15
#define NL 4
#define AVGLOG 1.1308269950720914f
#define CLD 828   // CAB row stride (multiple of 4 for wmma direct store)

typedef __nv_bfloat16 bf16;

// ---------------- scratch (device globals; no allocs) ----------------
__device__ __align__(256) bf16  g_Hh[NN * 80];
__device__ __align__(256) bf16  g_Hl[NN * 80];
__device__ __align__(256) float g_CAB[NN * CLD];     // fp32: [A(375) | B(375) | H@W0(75) | pad]
__device__ __align__(256) bf16  g_AGGh[NN * 1520];   // [N][T][304] padded towers
__device__ __align__(256) bf16  g_AGGl[NN * 1520];
__device__ __align__(256) bf16  g_Zh[NN * 80];
__device__ __align__(256) bf16  g_Zl[NN * 80];
__device__ float g_Y[NN * DD];
__device__ float g_amp[NN];
__device__ float g_invamp[NN];
__device__ int   g_deg[NN * 2];
__device__ int   g_rowptr[NN + 1];
__device__ int   g_csr[NE];
__device__ int   g_bsum[256];
__device__ int   g_boffs[256];
__device__ __align__(256) bf16  g_Wcath[NL * 75 * 832];
__device__ __align__(256) bf16  g_Wcatl[NL * 75 * 832];
__device__ float g_Etab[NL * 4 * 375];
__device__ __align__(256) bf16  g_WGh[NL * TW * 300 * 48];
__device__ __align__(256) bf16  g_WGl[NL * TW * 300 * 48];
__device__ __align__(256) bf16  g_Wlinh[NL * 75 * 80];
__device__ __align__(256) bf16  g_Wlinl[NL * 75 * 80];
__device__ double g_bnS[NL * DD];
__device__ double g_bnQ[NL * DD];
__device__ float g_pool[NG * DD];
__device__ float g_z1[NG * 50];
__device__ float g_z2[NG * 25];

__device__ __forceinline__ void bsplit(float v, bf16* h, bf16* l) {
    bf16 hi = __float2bfloat16(v);
    *h = hi;
    *l = __float2bfloat16(v - __bfloat162float(hi));
}

// ---------------- cp.async helpers ----------------
__device__ __forceinline__ void cp16(unsigned dst, const void* src, bool pred) {
    int sz = pred ? 16 : 0;   // sz=0 -> zero-fill
    asm volatile("cp.async.cg.shared.global [%0], [%1], 16, %2;\n" ::"r"(dst), "l"(src),
                 "r"(sz));
}
#define CP_COMMIT() asm volatile("cp.async.commit_group;\n" ::: "memory")
#define CP_WAIT1() asm volatile("cp.async.wait_group 1;\n" ::: "memory")
#define CP_WAIT0() asm volatile("cp.async.wait_group 0;\n" ::: "memory")

// ---------------- split-bf16 GEMM; pre-split hi/lo planes; 16B async loads ----------
// tile 128x64, 256 threads, 3 CTAs/SM target. smem: A hi[2]/lo[2] 128x24, B hi[2]/lo[2] 16x72.
// mode 0: standard epilogue; mode 1: PNA combine -> Z planes; mode 2: Y + BN stats.
#define SAS 24
#define SBS 72
#define SA_PLANE (128 * SAS)
#define SB_PLANE (16 * SBS)
#define SMEM_BYTES (128 * 72 * 4)   // sC (36864) > stages (33792)

__global__ __launch_bounds__(256, 3) void tgemm_kernel(
    const bf16* __restrict__ Ah, const bf16* __restrict__ Al, int lda, long sAb,
    const bf16* __restrict__ Bh, const bf16* __restrict__ Bl, int ldb, long sBb,
    float* __restrict__ C, int ldc, long sCb,
    int M, int N, int K,
    const float* __restrict__ bias,
    const float* __restrict__ addC, int ldadd,
    const float* __restrict__ amp, const float* __restrict__ invamp,
    bf16* __restrict__ Zph, bf16* __restrict__ Zpl,
    double* __restrict__ bnS, double* __restrict__ bnQ,
    int act, int mode) {
    extern __shared__ char smem_raw[];
    __shared__ float rs[256], rq[256];
    bf16* bb = (bf16*)smem_raw;
    float* sC = (float*)smem_raw;

    const bf16* Abh = Ah + (long)blockIdx.z * sAb;
    const bf16* Abl = Al + (long)blockIdx.z * sAb;
    const bf16* Bbh = Bh + (long)blockIdx.z * sBb;
    const bf16* Bbl = Bl + (long)blockIdx.z * sBb;
    float* Cb = C + (long)blockIdx.z * sCb;
    int m0 = blockIdx.y * 128, n0 = blockIdx.x * 64;
    int tid = threadIdx.x;
    int warp = tid >> 5;
    int wm = (warp & 3) * 32;
    int wn = (warp >> 2) * 32;
    int numK = (K + 15) / 16;

    // ---- precomputed loader state ----
    const bf16* aSrc[2];
    unsigned aDst[2];
    bool aPred[2];
#pragma unroll
    for (int u = 0; u < 2; u++) {
        int idx = tid + u * 256;
        int pl = idx >> 8, rem = idx & 255;
        int r = rem >> 1, ch = rem & 1;
        const bf16* base = pl ? Abl : Abh;
        aPred[u] = (m0 + r) < M;
        aSrc[u] = base + (long)(m0 + r) * lda + ch * 8;
        aDst[u] = (unsigned)__cvta_generic_to_shared(bb + pl * 2 * SA_PLANE + r * SAS + ch * 8);
    }
    int bPl = tid >> 7, bRem = tid & 127;
    int bR = bRem >> 3, bCh = bRem & 7;
    const bf16* bBase = bPl ? Bbl : Bbh;
    bool bPredN = (n0 + bCh * 8) < ldb;
    const bf16* bSrc = bBase + (long)bR * ldb + n0 + bCh * 8;
    unsigned bDst = (unsigned)__cvta_generic_to_shared(bb + 4 * SA_PLANE + bPl * 2 * SB_PLANE +
                                                       bR * SBS + bCh * 8);

    auto load_stage = [&](int st, int k0) {
#pragma unroll
        for (int u = 0; u < 2; u++)
            cp16(aDst[u] + st * SA_PLANE * 2, aPred[u] ? (aSrc[u] + k0) : Abh, aPred[u]);
        bool p = bPredN && (k0 + bR) < K;
        cp16(bDst + st * SB_PLANE * 2, p ? (bSrc + (long)k0 * ldb) : Bbh, p);
    };

    wmma::fragment<wmma::accumulator, 16, 16, 16, float> acc[2][2];
#pragma unroll
    for (int i = 0; i < 2; i++)
#pragma unroll
        for (int j = 0; j < 2; j++) wmma::fill_fragment(acc[i][j], 0.f);

    load_stage(0, 0);
    CP_COMMIT();

    for (int kt = 0; kt < numK; kt++) {
        int st = kt & 1;
        if (kt + 1 < numK) {
            load_stage(st ^ 1, (kt + 1) * 16);
            CP_COMMIT();
            CP_WAIT1();
        } else {
            CP_WAIT0();
        }
        __syncthreads();

        bf16* sAh = bb + st * SA_PLANE;
        bf16* sAl = bb + 2 * SA_PLANE + st * SA_PLANE;
        bf16* sBh = bb + 4 * SA_PLANE + st * SB_PLANE;
        bf16* sBl = bb + 4 * SA_PLANE + 2 * SB_PLANE + st * SB_PLANE;

        wmma::fragment<wmma::matrix_a, 16, 16, 16, bf16, wmma::row_major> ah[2], al[2];
        wmma::fragment<wmma::matrix_b, 16, 16, 16, bf16, wmma::row_major> bh[2], bl[2];
#pragma unroll
        for (int i = 0; i < 2; i++) {
            wmma::load_matrix_sync(ah[i], &sAh[(wm + 16 * i) * SAS], SAS);
            wmma::load_matrix_sync(al[i], &sAl[(wm + 16 * i) * SAS], SAS);
        }
#pragma unroll
        for (int j = 0; j < 2; j++) {
            wmma::load_matrix_sync(bh[j], &sBh[wn + 16 * j], SBS);
            wmma::load_matrix_sync(bl[j], &sBl[wn + 16 * j], SBS);
        }
#pragma unroll
        for (int i = 0; i < 2; i++)
#pragma unroll
            for (int j = 0; j < 2; j++) {
                wmma::mma_sync(acc[i][j], al[i], bh[j], acc[i][j]);
                wmma::mma_sync(acc[i][j], ah[i], bl[j], acc[i][j]);
                wmma::mma_sync(acc[i][j], ah[i], bh[j], acc[i][j]);
            }
        __syncthreads();
    }

    // direct store: mode 0, no epilogue math, full tile, ldc multiple of 4
    bool direct = (mode == 0) && (bias == nullptr) && (addC == nullptr) && (act == 0) &&
                  ((ldc & 3) == 0) && (m0 + 128 <= M) && (n0 + 64 <= N);
    if (direct) {
#pragma unroll
        for (int i = 0; i < 2; i++)
#pragma unroll
            for (int j = 0; j < 2; j++)
                wmma::store_matrix_sync(&Cb[(long)(m0 + wm + 16 * i) * ldc + n0 + wn + 16 * j],
                                        acc[i][j], ldc, wmma::mem_row_major);
        return;
    }
#pragma unroll
    for (int i = 0; i < 2; i++)
#pragma unroll
        for (int j = 0; j < 2; j++)
            wmma::store_matrix_sync(&sC[(wm + 16 * i) * 72 + wn + 16 * j], acc[i][j], 72,
                                    wmma::mem_row_major);
    __syncthreads();

    if (mode == 1) {
        // combine towers + degree scalers -> Z planes; tower = blockIdx.z
        int t = blockIdx.z;
        for (int i = tid; i < 128 * 15; i += 256) {
            int r = i / 15, f = i % 15;
            int gm = m0 + r;
            if (gm < M) {
                const float* row = &sC[r * 72];
                float v = row[f] + amp[gm] * row[15 + f] + invamp[gm] * row[30 + f] +
                          bias[t * 15 + f];
                long o = (long)gm * 80 + t * 15 + f;
                bsplit(v, &Zph[o], &Zpl[o]);
            }
        }
        return;
    }
    if (mode == 2) {
        // Y = acc + bias + addC; accumulate BN column stats
        float s = 0.f, q = 0.f;
        int c = tid & 63, gn = n0 + c;
        for (int i = tid; i < 128 * 64; i += 256) {
            int r = i >> 6;
            int gm = m0 + r;
            if (gm < M && gn < N) {
                float v = sC[r * 72 + c] + bias[gn] + addC[(long)gm * ldadd + gn];
                Cb[(long)gm * ldc + gn] = v;
                s += v;
                q += v * v;
            }
        }
        rs[tid] = s;
        rq[tid] = q;
        __syncthreads();
        if (tid < 64 && gn < N) {
            float ts = rs[tid] + rs[tid + 64] + rs[tid + 128] + rs[tid + 192];
            float tq = rq[tid] + rq[tid + 64] + rq[tid + 128] + rq[tid + 192];
            atomicAdd(&bnS[gn], (double)ts);
            atomicAdd(&bnQ[gn], (double)tq);
        }
        return;
    }
    // mode 0 generic
    for (int i = tid; i < 128 * 64; i += 256) {
        int r = i >> 6, c = i & 63;
        int gm = m0 + r, gn = n0 + c;
        if (gm < M && gn < N) {
            float v = sC[r * 72 + c];
            if (bias) v += bias[gn];
            if (addC) v += addC[(long)gm * ldadd + gn];
            if (act) v = fmaxf(v, 0.f);
            Cb[(long)gm * ldc + gn] = v;
        }
    }
}

// ---------------- tiny fp32 GEMM for the final MLP ----------------
__global__ void sgemm_s(const float* __restrict__ A, int lda, const float* __restrict__ B,
                        int ldb, float* __restrict__ C, int ldc, int M, int N, int K,
                        const float* __restrict__ bias, int act) {
    int i = blockIdx.x * blockDim.x + threadIdx.x;
    if (i >= M * N) return;
    int m = i / N, n = i % N;
    float s = bias ? bias[n] : 0.f;
    for (int k = 0; k < K; k++) s += A[m * lda + k] * B[k * ldb + n];
    if (act) s = fmaxf(s, 0.f);
    C[m * ldc + n] = s;
}

// ---------------- small utility kernels ----------------
__global__ void zero_i(int* p, int n) {
    int i = blockIdx.x * blockDim.x + threadIdx.x;
    if (i < n) p[i] = 0;
}
__global__ void zero_f(float* p, int n) {
    int i = blockIdx.x * blockDim.x + threadIdx.x;
    if (i < n) p[i] = 0.f;
}
__global__ void zero_bn(double* s, double* q, int n) {
    int i = blockIdx.x * blockDim.x + threadIdx.x;
    if (i < n) { s[i] = 0.0; q[i] = 0.0; }
}
__global__ void zero_zpad(bf16* Zh, bf16* Zl, bf16* Ah, bf16* Al) {
    int i = blockIdx.x * blockDim.x + threadIdx.x;
    if (i < NN * 5) {  // Z pad cols 75..79
        int n = i / 5, k = i % 5;
        Zh[n * 80 + 75 + k] = __float2bfloat16(0.f);
        Zl[n * 80 + 75 + k] = __float2bfloat16(0.f);
    }
    if (i < NN * 20) {  // AGG tower pad cols 300..303 (constant zero across layers)
        int n = i / 20, r = i % 20;
        int o = n * 1520 + (r >> 2) * 304 + 300 + (r & 3);
        Ah[o] = __float2bfloat16(0.f);
        Al[o] = __float2bfloat16(0.f);
    }
}

__global__ void hist_k(const int* __restrict__ ei, int* __restrict__ deg) {
    int e = blockIdx.x * blockDim.x + threadIdx.x;
    if (e < NE) atomicAdd(&deg[ei[NE + e]], 1);
}

__global__ void scan_chunks(const int* __restrict__ in, int* __restrict__ out,
                            int* __restrict__ bsum, int n) {
    __shared__ int s[512];
    int b = blockIdx.x, t = threadIdx.x;
    int idx = b * 512 + t;
    int v = (idx < n) ? in[idx] : 0;
    s[t] = v;
    __syncthreads();
    for (int off = 1; off < 512; off <<= 1) {
        int x = (t >= off) ? s[t - off] : 0;
        __syncthreads();
        s[t] += x;
        __syncthreads();
    }
    if (idx < n) out[idx] = s[t] - v;
    if (t == 511) bsum[b] = s[511];
}
__global__ void scan_sums(const int* __restrict__ sums, int* __restrict__ offs, int nb) {
    __shared__ int s[128];
    int t = threadIdx.x;
    int v = (t < nb) ? sums[t] : 0;
    s[t] = v;
    __syncthreads();
    for (int off = 1; off < 128; off <<= 1) {
        int x = (t >= off) ? s[t - off] : 0;
        __syncthreads();
        s[t] += x;
        __syncthreads();
    }
    if (t < nb) offs[t] = s[t] - v;
}
__global__ void scan_add(int* __restrict__ rowptr, const int* __restrict__ offs) {
    int i = blockIdx.x * blockDim.x + threadIdx.x;
    if (i < NN) rowptr[i] += offs[i >> 9];
    if (i == 0) rowptr[NN] = NE;
}

__global__ void fill_csr(const int* __restrict__ ei, const int* __restrict__ ea,
                         const int* __restrict__ rowptr, int* __restrict__ cursor,
                         int* __restrict__ csr) {
    int e = blockIdx.x * blockDim.x + threadIdx.x;
    if (e >= NE) return;
    int d = ei[NE + e];
    int pos = rowptr[d] + atomicAdd(&cursor[d], 1);
    csr[pos] = ei[e] | (ea[e] << 20);
}

__global__ void amp_k(const int* __restrict__ rowptr, float* __restrict__ amp,
                      float* __restrict__ invamp) {
    int i = blockIdx.x * blockDim.x + threadIdx.x;
    if (i >= NN) return;
    int dg = rowptr[i + 1] - rowptr[i];
    float a = logf((float)max(dg, 1) + 1.f) / AVGLOG;
    amp[i] = a;
    invamp[i] = 1.f / a;
}

// writes H hi/lo planes (ld 80, cols 75..79 zero)
__global__ void embed_k(const int* __restrict__ x, const float* __restrict__ emb,
                        bf16* __restrict__ Hh, bf16* __restrict__ Hl) {
    int i = blockIdx.x * blockDim.x + threadIdx.x;
    if (i >= NN * 80) return;
    int n = i / 80, f = i % 80;
    float v = (f < 75) ? emb[x[n] * 75 + f] : 0.f;
    bsplit(v, &Hh[i], &Hl[i]);
}

// ---------------- weight prep (bf16 planes) ----------------
__global__ void prep_wcat(const float* __restrict__ Wpre, bf16* __restrict__ Wh,
                          bf16* __restrict__ Wl) {
    int i = blockIdx.x * blockDim.x + threadIdx.x;
    if (i >= NL * 75 * 832) return;
    int l = i / (75 * 832), r = i % (75 * 832);
    int k = r / 832, j = r % 832;
    if (j >= 750 && j < 825) return;  // W0 region written by prep_w0
    float v = 0.f;
    if (j < 750) {
        int part = j / 375, j2 = j % 375;
        int t = j2 / 75, f = j2 % 75;
        int c = part * 75 + k;
        v = Wpre[((l * TW + t) * 225 + c) * 75 + f];
    }
    bsplit(v, &Wh[(l * 75 + k) * 832 + j], &Wl[(l * 75 + k) * 832 + j]);
}

__global__ void prep_w0(const float* __restrict__ Wpost, const float* __restrict__ Wlin,
                        bf16* __restrict__ Wh, bf16* __restrict__ Wl) {
    int i = blockIdx.x * blockDim.x + threadIdx.x;
    if (i >= NL * 75 * 75) return;
    int l = i / 5625, r = i % 5625;
    int k = r / 75, c = r % 75;
    float s = 0.f;
    for (int d = 0; d < 75; d++) {
        int t = d / 15, f = d % 15;
        s += Wpost[((l * TW + t) * 975 + k) * 15 + f] * Wlin[l * 5625 + d * 75 + c];
    }
    int o = (l * 75 + k) * 832 + 750 + c;
    bsplit(s, &Wh[o], &Wl[o]);
}

__global__ void prep_etab(const float* __restrict__ edge_emb, const float* __restrict__ We,
                          const float* __restrict__ be, const float* __restrict__ Wpre,
                          const float* __restrict__ bpre, float* __restrict__ Etab) {
    int a = blockIdx.x, l = blockIdx.y;
    __shared__ float ev[75];
    int t0 = threadIdx.x;
    if (t0 < 75) {
        float s = be[l * 75 + t0];
        for (int c = 0; c < 50; c++) s += edge_emb[a * 50 + c] * We[(l * 50 + c) * 75 + t0];
        ev[t0] = s;
    }
    __syncthreads();
    for (int j = t0; j < 375; j += blockDim.x) {
        int t = j / 75, f = j % 75;
        float s = bpre[(l * TW + t) * 75 + f];
        for (int d = 0; d < 75; d++)
            s += ev[d] * Wpre[((l * TW + t) * 225 + 150 + d) * 75 + f];
        Etab[(l * 4 + a) * 375 + j] = s;
    }
}

__global__ void prep_wg(const float* __restrict__ Wpost, bf16* __restrict__ Wh,
                        bf16* __restrict__ Wl) {
    int i = blockIdx.x * blockDim.x + threadIdx.x;
    if (i >= NL * TW * 300 * 48) return;
    int lt = i / (300 * 48), r = i % (300 * 48);
    int c = r / 48, col = r % 48;
    float v = 0.f;
    if (col < 45) {
        int g = col / 15, f = col % 15;
        v = Wpost[(lt * 975 + 75 + g * 300 + c) * 15 + f];
    }
    int o = (lt * 300 + c) * 48 + col;
    bsplit(v, &Wh[o], &Wl[o]);
}

__global__ void prep_wlin(const float* __restrict__ Wlin, bf16* __restrict__ Wh,
                          bf16* __restrict__ Wl) {
    int i = blockIdx.x * blockDim.x + threadIdx.x;
    if (i >= NL * 75 * 80) return;
    int l = i / (75 * 80), r = i % (75 * 80);
    int k = r / 80, c = r % 80;
    float v = (c < 75) ? Wlin[l * 5625 + k * 75 + c] : 0.f;
    int o = (l * 75 + k) * 80 + c;
    bsplit(v, &Wh[o], &Wl[o]);
}

// ---------------- PNA aggregation: writes AGG hi/lo planes [N][T][304] --------------
__global__ __launch_bounds__(384) void pna_agg(const float* __restrict__ CAB,
                                               const float* __restrict__ Etab,
                                               const int* __restrict__ rowptr,
                                               const int* __restrict__ csr,
                                               bf16* __restrict__ AGGh,
                                               bf16* __restrict__ AGGl) {
    int n = blockIdx.x;
    int j = threadIdx.x;
    if (j >= 375) return;
    float adst = CAB[(long)n * CLD + j];
    int beg = rowptr[n], end = rowptr[n + 1];
    float s = 0.f, sq = 0.f, mn = 3.4e38f, mx = -3.4e38f;
    int e = beg;
    for (; e + 1 < end; e += 2) {
        int p0 = csr[e], p1 = csr[e + 1];
        float b0 = CAB[(long)(p0 & 0xFFFFF) * CLD + 375 + j];
        float b1 = CAB[(long)(p1 & 0xFFFFF) * CLD + 375 + j];
        float v0 = adst + b0 + Etab[(p0 >> 20) * 375 + j];
        float v1 = adst + b1 + Etab[(p1 >> 20) * 375 + j];
        s += v0 + v1;
        sq += v0 * v0 + v1 * v1;
        mn = fminf(mn, fminf(v0, v1));
        mx = fmaxf(mx, fmaxf(v0, v1));
    }
    if (e < end) {
        int p0 = csr[e];
        float v0 = adst + CAB[(long)(p0 & 0xFFFFF) * CLD + 375 + j] + Etab[(p0 >> 20) * 375 + j];
        s += v0;
        sq += v0 * v0;
        mn = fminf(mn, v0);
        mx = fmaxf(mx, v0);
    }
    int dg = end - beg;
    float denom = fmaxf((float)dg, 1.f);
    float mean = s / denom, msq = sq / denom;
    float sd = sqrtf(fmaxf(msq - mean * mean, 0.f) + 1e-5f);
    if (dg == 0) { mn = 0.f; mx = 0.f; }
    int t = j / 75, f = j % 75;
    long o = (long)n * 1520 + t * 304;
    bsplit(mean, &AGGh[o + f], &AGGl[o + f]);
    bsplit(mn, &AGGh[o + 75 + f], &AGGl[o + 75 + f]);
    bsplit(mx, &AGGh[o + 150 + f], &AGGl[o + 150 + f]);
    bsplit(sd, &AGGh[o + 225 + f], &AGGl[o + 225 + f]);
}

// ---------------- BN apply + ReLU -> H hi/lo planes ----------------
__global__ void bn_apply(const float* __restrict__ Y, const double* __restrict__ S,
                         const double* __restrict__ Q, const float* __restrict__ gamma,
                         const float* __restrict__ beta, bf16* __restrict__ Hh,
                         bf16* __restrict__ Hl) {
    int i = blockIdx.x * blockDim.x + threadIdx.x;
    if (i >= NN * 80) return;
    int n = i / 80, f = i % 80;
    float v = 0.f;
    if (f < 75) {
        double mu = S[f] / (double)NN;
        double var = Q[f] / (double)NN - mu * mu;
        float inv = rsqrtf((float)var + 1e-5f);
        v = gamma[f] * ((Y[(long)n * DD + f] - (float)mu) * inv) + beta[f];
        v = fmaxf(v, 0.f);
    }
    bsplit(v, &Hh[i], &Hl[i]);
}

// ---------------- pooling (reconstruct fp32 from planes) ----------------
__global__ void pool_k(const int* __restrict__ batch, const bf16* __restrict__ Hh,
                       const bf16* __restrict__ Hl, float* __restrict__ pool) {
    int i = blockIdx.x * blockDim.x + threadIdx.x;
    if (i >= NN * DD) return;
    int n = i / DD, f = i % DD;
    float v = __bfloat162float(Hh[n * 80 + f]) + __bfloat162float(Hl[n * 80 + f]);
    atomicAdd(&pool[batch[n] * DD + f], v);
}

// ---------------- launch ----------------
static inline void tgemm(const bf16* Ah, const bf16* Al, int lda, long sA, const bf16* Bh,
                         const bf16* Bl, int ldb, long sB, float* C, int ldc, long sC, int M,
                         int N, int K, const float* bias, const float* addC, int ldadd,
                         const float* amp, const float* invamp, bf16* Zh, bf16* Zl,
                         double* bnS, double* bnQ, int act, int mode, int nz) {
    dim3 grid((N + 63) / 64, (M + 127) / 128, nz);
    tgemm_kernel<<<grid, 256, SMEM_BYTES>>>(Ah, Al, lda, sA, Bh, Bl, ldb, sB, C, ldc, sC, M, N,
                                            K, bias, addC, ldadd, amp, invamp, Zh, Zl, bnS, bnQ,
                                            act, mode);
}

extern "C" void kernel_launch(void* const* d_in, const int* in_sizes, int n_in,
                              void* d_out, int out_size) {
    const int* x = (const int*)d_in[0];
    const int* ei = (const int*)d_in[1];
    const int* ea = (const int*)d_in[2];
    const int* batch = (const int*)d_in[3];
    const float* node_emb = (const float*)d_in[4];
    const float* edge_emb = (const float*)d_in[5];
    const float* We = (const float*)d_in[6];
    const float* be = (const float*)d_in[7];
    const float* Wpre = (const float*)d_in[8];
    const float* bpre = (const float*)d_in[9];
    const float* Wpost = (const float*)d_in[10];
    const float* bpost = (const float*)d_in[11];
    const float* Wlin = (const float*)d_in[12];
    const float* blin = (const float*)d_in[13];
    const float* gamma = (const float*)d_in[14];
    const float* beta = (const float*)d_in[15];
    const float* W1 = (const float*)d_in[16];
    const float* b1 = (const float*)d_in[17];
    const float* W2 = (const float*)d_in[18];
    const float* b2 = (const float*)d_in[19];
    const float* W3 = (const float*)d_in[20];
    const float* b3 = (const float*)d_in[21];
    float* out = (float*)d_out;

    cudaFuncSetAttribute(tgemm_kernel, cudaFuncAttributeMaxDynamicSharedMemorySize, SMEM_BYTES);

    bf16 *Hh, *Hl, *AGGh, *AGGl, *Zh, *Zl, *Wcath, *Wcatl, *WGh, *WGl, *Wlinh, *Wlinl;
    float *CAB, *Y, *amp, *invamp, *Etab, *pool, *z1, *z2;
    int *deg, *rowptr, *csr, *bsum, *boffs;
    double *bnS, *bnQ;
    cudaGetSymbolAddress((void**)&Hh, g_Hh);
    cudaGetSymbolAddress((void**)&Hl, g_Hl);
    cudaGetSymbolAddress((void**)&CAB, g_CAB);
    cudaGetSymbolAddress((void**)&AGGh, g_AGGh);
    cudaGetSymbolAddress((void**)&AGGl, g_AGGl);
    cudaGetSymbolAddress((void**)&Zh, g_Zh);
    cudaGetSymbolAddress((void**)&Zl, g_Zl);
    cudaGetSymbolAddress((void**)&Y, g_Y);
    cudaGetSymbolAddress((void**)&amp, g_amp);
    cudaGetSymbolAddress((void**)&invamp, g_invamp);
    cudaGetSymbolAddress((void**)&deg, g_deg);
    cudaGetSymbolAddress((void**)&rowptr, g_rowptr);
    cudaGetSymbolAddress((void**)&csr, g_csr);
    cudaGetSymbolAddress((void**)&bsum, g_bsum);
    cudaGetSymbolAddress((void**)&boffs, g_boffs);
    cudaGetSymbolAddress((void**)&Wcath, g_Wcath);
    cudaGetSymbolAddress((void**)&Wcatl, g_Wcatl);
    cudaGetSymbolAddress((void**)&Etab, g_Etab);
    cudaGetSymbolAddress((void**)&WGh, g_WGh);
    cudaGetSymbolAddress((void**)&WGl, g_WGl);
    cudaGetSymbolAddress((void**)&Wlinh, g_Wlinh);
    cudaGetSymbolAddress((void**)&Wlinl, g_Wlinl);
    cudaGetSymbolAddress((void**)&bnS, g_bnS);
    cudaGetSymbolAddress((void**)&bnQ, g_bnQ);
    cudaGetSymbolAddress((void**)&pool, g_pool);
    cudaGetSymbolAddress((void**)&z1, g_z1);
    cudaGetSymbolAddress((void**)&z2, g_z2);
    int* cursor = deg + NN;

    // ---- launch index 3 = layer-0 CAB GEMM (ncu capture slot) ----
    embed_k<<<(NN * 80 + 255) / 256, 256>>>(x, node_emb, Hh, Hl);               // 0
    prep_wcat<<<(NL * 75 * 832 + 255) / 256, 256>>>(Wpre, Wcath, Wcatl);        // 1
    prep_w0<<<(NL * 75 * 75 + 255) / 256, 256>>>(Wpost, Wlin, Wcath, Wcatl);    // 2
    tgemm(Hh, Hl, 80, 0, Wcath, Wcatl, 832, 0, CAB, CLD, 0, NN, 825, 75,        // 3
          nullptr, nullptr, 0, nullptr, nullptr, nullptr, nullptr, nullptr, nullptr, 0, 0, 1);
    prep_wg<<<(NL * TW * 300 * 48 + 255) / 256, 256>>>(Wpost, WGh, WGl);        // 4
    prep_wlin<<<(NL * 75 * 80 + 255) / 256, 256>>>(Wlin, Wlinh, Wlinl);         // 5
    zero_zpad<<<(NN * 20 + 255) / 256, 256>>>(Zh, Zl, AGGh, AGGl);              // 6
    zero_bn<<<(NL * DD + 255) / 256, 256>>>(bnS, bnQ, NL * DD);                 // 7

    // ---- graph structure prep ----
    zero_i<<<(2 * NN + 255) / 256, 256>>>(deg, 2 * NN);
    hist_k<<<(NE + 255) / 256, 256>>>(ei, deg);
    int nchunks = (NN + 511) / 512;
    scan_chunks<<<nchunks, 512>>>(deg, rowptr, bsum, NN);
    scan_sums<<<1, 128>>>(bsum, boffs, nchunks);
    scan_add<<<(NN + 255) / 256, 256>>>(rowptr, boffs);
    fill_csr<<<(NE + 255) / 256, 256>>>(ei, ea, rowptr, cursor, csr);
    amp_k<<<(NN + 255) / 256, 256>>>(rowptr, amp, invamp);
    prep_etab<<<dim3(4, NL), 384>>>(edge_emb, We, be, Wpre, bpre, Etab);

    // ---- layers ----
    for (int l = 0; l < NL; l++) {
        if (l > 0) {
            tgemm(Hh, Hl, 80, 0, Wcath + l * 75 * 832, Wcatl + l * 75 * 832, 832, 0, CAB, CLD,
                  0, NN, 825, 75, nullptr, nullptr, 0, nullptr, nullptr, nullptr, nullptr,
                  nullptr, nullptr, 0, 0, 1);
        }
        pna_agg<<<NN, 384>>>(CAB, Etab + l * 4 * 375, rowptr, csr, AGGh, AGGl);
        // AGG GEMM + fused combine -> Z planes (mode 1)
        tgemm(AGGh, AGGl, 1520, 304, WGh + l * TW * 300 * 48, WGl + l * TW * 300 * 48, 48,
              (long)300 * 48, Y /*unused*/, 45, 0, NN, 45, 300, bpost + l * TW * FO, nullptr, 0,
              amp, invamp, Zh, Zl, nullptr, nullptr, 0, 1, TW);
        // Y GEMM + fused BN stats (mode 2)
        tgemm(Zh, Zl, 80, 0, Wlinh + l * 75 * 80, Wlinl + l * 75 * 80, 80, 0, Y, 75, 0, NN, 75,
              75, blin + l * 75, CAB + 750, CLD, nullptr, nullptr, nullptr, nullptr,
              bnS + l * DD, bnQ + l * DD, 0, 2, 1);
        bn_apply<<<(NN * 80 + 255) / 256, 256>>>(Y, bnS + l * DD, bnQ + l * DD, gamma + l * DD,
                                                 beta + l * DD, Hh, Hl);
    }

    // ---- pooling + MLP (tiny, fp32 SIMT) ----
    zero_f<<<(NG * DD + 255) / 256, 256>>>(pool, NG * DD);
    pool_k<<<(NN * DD + 255) / 256, 256>>>(batch, Hh, Hl, pool);
    sgemm_s<<<(NG * 50 + 255) / 256, 256>>>(pool, 75, W1, 50, z1, 50, NG, 50, 75, b1, 1);
    sgemm_s<<<(NG * 25 + 255) / 256, 256>>>(z1, 50, W2, 25, z2, 25, NG, 25, 50, b2, 1);
    sgemm_s<<<(NG * 1 + 255) / 256, 256>>>(z2, 25, W3, 1, out, 1, NG, 1, 25, b3, 0);
}